// round 3
// baseline (speedup 1.0000x reference)
#include <cuda_runtime.h>
#include <math.h>

#define BB 2
#define NN 768
#define CT 768
#define CS 384
#define CP 128
#define NH 16
#define HD 48
#define ROWS (BB*NN)   /* 1536 */

// ---------------- scratch (device globals; no allocation allowed) ----------------
__device__ float g_aln  [ROWS*CT];
__device__ float g_sln  [ROWS*CS];
__device__ float g_tmpb [ROWS*CT];
__device__ float g_anorm[ROWS*CT];
__device__ float g_q    [ROWS*CT];
__device__ float g_k    [ROWS*CT];
__device__ float g_v    [ROWS*CT];
__device__ float g_gate [ROWS*CT];
__device__ float g_og   [ROWS*CT];
__device__ float g_o    [ROWS*CT];
__device__ float g_pb   [BB*NH*NN*NN];   // 75.5 MB pair bias [b,h,i,j]

// ---------------- LayerNorm (no affine) ----------------
__device__ __forceinline__ float2 blockReduce2(float a, float b) {
    #pragma unroll
    for (int o = 16; o; o >>= 1) {
        a += __shfl_xor_sync(0xffffffffu, a, o);
        b += __shfl_xor_sync(0xffffffffu, b, o);
    }
    __shared__ float sa[8], sb[8];
    int w = threadIdx.x >> 5, l = threadIdx.x & 31;
    if (l == 0) { sa[w] = a; sb[w] = b; }
    __syncthreads();
    if (w == 0) {
        a = (l < 8) ? sa[l] : 0.f;
        b = (l < 8) ? sb[l] : 0.f;
        #pragma unroll
        for (int o = 4; o; o >>= 1) {
            a += __shfl_xor_sync(0xffffffffu, a, o);
            b += __shfl_xor_sync(0xffffffffu, b, o);
        }
        if (l == 0) { sa[0] = a; sb[0] = b; }
    }
    __syncthreads();
    return make_float2(sa[0], sb[0]);
}

__global__ void __launch_bounds__(256) ln_kernel(const float* __restrict__ in,
                                                 float* __restrict__ out, int C) {
    int r = blockIdx.x;
    const float* x = in + (size_t)r * C;
    float s = 0.f, sq = 0.f;
    for (int c = threadIdx.x; c < C; c += 256) { float v = x[c]; s += v; sq += v * v; }
    float2 red = blockReduce2(s, sq);
    float mean = red.x / C;
    float inv = rsqrtf(red.y / C - mean * mean + 1e-5f);
    float* y = out + (size_t)r * C;
    for (int c = threadIdx.x; c < C; c += 256) y[c] = (x[c] - mean) * inv;
}

// ---------------- SGEMM: C = epi(A[M,K] @ B[K,N]) ----------------
// epi: v = acc + bias[n] (opt); if sig: v = sigmoid(v); if mul: v *= mul[m,n]; if add: v += add[m,n]
// BM=128 BN=64 BK=16, 256 threads, 8x4 microtile. All dims divide evenly here.
__global__ void __launch_bounds__(256) sgemm_kernel(
    const float* __restrict__ A, const float* __restrict__ B, float* __restrict__ C,
    int M, int N, int K,
    const float* __restrict__ bias, int do_sig,
    const float* __restrict__ mul, const float* __restrict__ add)
{
    __shared__ float As[16][128];
    __shared__ float Bs[16][64];
    int t = threadIdx.x;
    int tx = t & 15, ty = t >> 4;
    int m0 = blockIdx.y * 128, n0 = blockIdx.x * 64;

    float acc[8][4];
    #pragma unroll
    for (int i = 0; i < 8; i++)
        #pragma unroll
        for (int j = 0; j < 4; j++) acc[i][j] = 0.f;

    for (int k0 = 0; k0 < K; k0 += 16) {
        #pragma unroll
        for (int sIt = 0; sIt < 2; sIt++) {
            int slot = t + sIt * 256;
            int row = slot >> 2, kq = slot & 3;
            float4 av = *(const float4*)(A + (size_t)(m0 + row) * K + k0 + kq * 4);
            As[kq * 4 + 0][row] = av.x;
            As[kq * 4 + 1][row] = av.y;
            As[kq * 4 + 2][row] = av.z;
            As[kq * 4 + 3][row] = av.w;
        }
        {
            int row = t >> 4, c4 = t & 15;
            float4 bv = *(const float4*)(B + (size_t)(k0 + row) * N + n0 + c4 * 4);
            *(float4*)(&Bs[row][c4 * 4]) = bv;
        }
        __syncthreads();
        #pragma unroll
        for (int kk = 0; kk < 16; kk++) {
            float a[8], bb[4];
            *(float4*)(a)     = *(const float4*)(&As[kk][ty * 8]);
            *(float4*)(a + 4) = *(const float4*)(&As[kk][ty * 8 + 4]);
            *(float4*)(bb)    = *(const float4*)(&Bs[kk][tx * 4]);
            #pragma unroll
            for (int i = 0; i < 8; i++)
                #pragma unroll
                for (int j = 0; j < 4; j++)
                    acc[i][j] += a[i] * bb[j];
        }
        __syncthreads();
    }

    int coln = n0 + tx * 4;
    #pragma unroll
    for (int i = 0; i < 8; i++) {
        int row = m0 + ty * 8 + i;
        size_t idx = (size_t)row * N + coln;
        float vals[4];
        #pragma unroll
        for (int j = 0; j < 4; j++) {
            float v = acc[i][j];
            if (bias) v += bias[coln + j];
            if (do_sig) v = 1.f / (1.f + expf(-v));
            vals[j] = v;
        }
        if (mul) {
            #pragma unroll
            for (int j = 0; j < 4; j++) vals[j] *= mul[idx + j];
        }
        if (add) {
            #pragma unroll
            for (int j = 0; j < 4; j++) vals[j] += add[idx + j];
        }
        float4 o4 = make_float4(vals[0], vals[1], vals[2], vals[3]);
        *(float4*)(C + idx) = o4;
    }
}

// ---------------- pair bias: LN(z)*gamma+beta @ Wpb + bias_mask -> g_pb[b,h,i,j] ----------------
// grid (NN/8, ROWS), 256 threads = 8 warps; warp w handles j = blockIdx.x*8 + w for (b,i)=blockIdx.y
__global__ void __launch_bounds__(256) pair_kernel(
    const float* __restrict__ z, const float* __restrict__ bmask,
    const float* __restrict__ Wpb, const float* __restrict__ gma,
    const float* __restrict__ bta, float* __restrict__ pb)
{
    __shared__ float WpbS[CP * 17];
    __shared__ float gS[CP], bS[CP];
    __shared__ float trans[8][17];
    int t = threadIdx.x;
    for (int idx = t; idx < CP * NH; idx += 256) {
        int c = idx / NH, h = idx % NH;
        WpbS[c * 17 + h] = Wpb[idx];
    }
    if (t < CP) { gS[t] = gma[t]; bS[t] = bta[t]; }
    __syncthreads();

    int bi = blockIdx.y;               // b*768 + i
    int b = bi / NN, i = bi % NN;
    int w = t >> 5, lane = t & 31;
    int j = blockIdx.x * 8 + w;

    const float* zp = z + ((size_t)bi * NN + j) * CP;
    float zv[4];
    float sum = 0.f, sq = 0.f;
    #pragma unroll
    for (int cc = 0; cc < 4; cc++) {
        float v = zp[lane + 32 * cc];
        zv[cc] = v; sum += v; sq += v * v;
    }
    #pragma unroll
    for (int o = 16; o; o >>= 1) {
        sum += __shfl_xor_sync(0xffffffffu, sum, o);
        sq  += __shfl_xor_sync(0xffffffffu, sq, o);
    }
    float mean = sum * (1.f / CP);
    float inv = rsqrtf(sq * (1.f / CP) - mean * mean + 1e-5f);

    float part[NH];
    #pragma unroll
    for (int h = 0; h < NH; h++) part[h] = 0.f;
    #pragma unroll
    for (int cc = 0; cc < 4; cc++) {
        int c = lane + 32 * cc;
        float zn = (zv[cc] - mean) * inv * gS[c] + bS[c];
        const float* wr = &WpbS[c * 17];
        #pragma unroll
        for (int h = 0; h < NH; h++) part[h] += zn * wr[h];
    }
    #pragma unroll
    for (int o = 16; o; o >>= 1) {
        #pragma unroll
        for (int h = 0; h < NH; h++)
            part[h] += __shfl_xor_sync(0xffffffffu, part[h], o);
    }
    float bm = bmask[(size_t)bi * NN + j];
    if (lane < NH) trans[w][lane] = part[lane] + bm;
    __syncthreads();

    if (t < 128) {
        int h = t >> 3, wj = t & 7;
        pb[(((size_t)(b * NH + h) * NN + i) * NN) + blockIdx.x * 8 + wj] = trans[wj][h];
    }
}

// ---------------- attention: flash-style, 64-query tiles ----------------
// grid (12, 16, 2) = (qtile, head, batch); 256 threads; dyn smem 54784 B
#define QS 49
#define ATTN_SMEM ((3 * 64 * QS + 64 * 64 + 3 * 64) * 4)

__global__ void __launch_bounds__(256) attn_kernel(
    const float* __restrict__ q, const float* __restrict__ k,
    const float* __restrict__ v, const float* __restrict__ gate,
    const float* __restrict__ pb, float* __restrict__ o)
{
    extern __shared__ float sm[];
    float* Qs = sm;                    // 64*49
    float* Ks = Qs + 64 * QS;
    float* Vs = Ks + 64 * QS;
    float* Ps = Vs + 64 * QS;          // 64*64
    float* Ms = Ps + 64 * 64;          // 64
    float* Ls = Ms + 64;
    float* Ss = Ls + 64;

    int qt = blockIdx.x, h = blockIdx.y, b = blockIdx.z;
    int t = threadIdx.x;
    int q0 = qt * 64;
    const float SC = 0.14433756729740643f;  // 1/sqrt(48)

    for (int idx = t; idx < 64 * HD; idx += 256) {
        int r = idx / HD, d = idx % HD;
        Qs[r * QS + d] = q[((size_t)(b * NN + q0 + r)) * CT + h * HD + d] * SC;
    }
    if (t < 64) { Ms[t] = -1e30f; Ls[t] = 0.f; }

    float acc[4][3];
    #pragma unroll
    for (int i = 0; i < 4; i++)
        #pragma unroll
        for (int c = 0; c < 3; c++) acc[i][c] = 0.f;
    int aq = (t >> 4) * 4;             // 4 queries per thread (AV phase)
    int ad = (t & 15) * 3;             // 3 dims per thread
    int tx = t & 15, ty = t >> 4;      // S microtile mapping

    const float* bp0 = pb + ((size_t)(b * NH + h) * NN + q0) * NN;

    for (int kt = 0; kt < 12; kt++) {
        int k0 = kt * 64;
        __syncthreads();
        for (int idx = t; idx < 64 * HD; idx += 256) {
            int r = idx / HD, d = idx % HD;
            size_t gi = ((size_t)(b * NN + k0 + r)) * CT + h * HD + d;
            Ks[r * QS + d] = k[gi];
            Vs[r * QS + d] = v[gi];
        }
        for (int idx = t; idx < 64 * 16; idx += 256) {   // bias tile -> Ps (float4)
            int r = idx >> 4, c4 = idx & 15;
            float4 bv = *(const float4*)(bp0 + (size_t)r * NN + k0 + c4 * 4);
            *(float4*)(Ps + r * 64 + c4 * 4) = bv;
        }
        __syncthreads();

        // S = Qs @ Ks^T (4x4 per thread), add into bias tile
        float sacc[4][4];
        #pragma unroll
        for (int i = 0; i < 4; i++)
            #pragma unroll
            for (int j = 0; j < 4; j++) sacc[i][j] = 0.f;
        #pragma unroll 8
        for (int d = 0; d < HD; d++) {
            float a0 = Qs[(ty * 4 + 0) * QS + d];
            float a1 = Qs[(ty * 4 + 1) * QS + d];
            float a2 = Qs[(ty * 4 + 2) * QS + d];
            float a3 = Qs[(ty * 4 + 3) * QS + d];
            float b0 = Ks[(tx * 4 + 0) * QS + d];
            float b1 = Ks[(tx * 4 + 1) * QS + d];
            float b2 = Ks[(tx * 4 + 2) * QS + d];
            float b3 = Ks[(tx * 4 + 3) * QS + d];
            sacc[0][0] += a0 * b0; sacc[0][1] += a0 * b1; sacc[0][2] += a0 * b2; sacc[0][3] += a0 * b3;
            sacc[1][0] += a1 * b0; sacc[1][1] += a1 * b1; sacc[1][2] += a1 * b2; sacc[1][3] += a1 * b3;
            sacc[2][0] += a2 * b0; sacc[2][1] += a2 * b1; sacc[2][2] += a2 * b2; sacc[2][3] += a2 * b3;
            sacc[3][0] += a3 * b0; sacc[3][1] += a3 * b1; sacc[3][2] += a3 * b2; sacc[3][3] += a3 * b3;
        }
        #pragma unroll
        for (int i = 0; i < 4; i++) {
            float4* pp = (float4*)(Ps + (ty * 4 + i) * 64 + tx * 4);
            float4 pv = *pp;
            pv.x += sacc[i][0]; pv.y += sacc[i][1];
            pv.z += sacc[i][2]; pv.w += sacc[i][3];
            *pp = pv;
        }
        __syncthreads();

        // online softmax: 4 lanes per query, 16 entries each
        {
            int qq = t >> 2, pp = t & 3;
            float* prow = Ps + qq * 64 + pp * 16;
            float tmax = -1e30f;
            #pragma unroll
            for (int jj = 0; jj < 16; jj++) tmax = fmaxf(tmax, prow[jj]);
            tmax = fmaxf(tmax, __shfl_xor_sync(0xffffffffu, tmax, 1));
            tmax = fmaxf(tmax, __shfl_xor_sync(0xffffffffu, tmax, 2));
            float mold = Ms[qq];
            float mnew = fmaxf(mold, tmax);
            float tsum = 0.f;
            #pragma unroll
            for (int jj = 0; jj < 16; jj++) {
                float p = __expf(prow[jj] - mnew);
                prow[jj] = p; tsum += p;
            }
            tsum += __shfl_xor_sync(0xffffffffu, tsum, 1);
            tsum += __shfl_xor_sync(0xffffffffu, tsum, 2);
            if (pp == 0) {
                float scl = __expf(mold - mnew);
                Ss[qq] = scl;
                Ls[qq] = Ls[qq] * scl + tsum;
                Ms[qq] = mnew;
            }
        }
        __syncthreads();

        // rescale + accumulate P @ V
        {
            float scl[4];
            #pragma unroll
            for (int i = 0; i < 4; i++) {
                scl[i] = Ss[aq + i];
                #pragma unroll
                for (int c = 0; c < 3; c++) acc[i][c] *= scl[i];
            }
            #pragma unroll 4
            for (int j = 0; j < 64; j++) {
                float v0 = Vs[j * QS + ad + 0];
                float v1 = Vs[j * QS + ad + 1];
                float v2 = Vs[j * QS + ad + 2];
                #pragma unroll
                for (int i = 0; i < 4; i++) {
                    float p = Ps[(aq + i) * 64 + j];
                    acc[i][0] += p * v0;
                    acc[i][1] += p * v1;
                    acc[i][2] += p * v2;
                }
            }
        }
    }

    // epilogue: normalize, gate, write [B*N, H*D]
    #pragma unroll
    for (int i = 0; i < 4; i++) {
        float inv = 1.f / Ls[aq + i];
        size_t row = (size_t)(b * NN + q0 + aq + i);
        #pragma unroll
        for (int c = 0; c < 3; c++) {
            size_t idx = row * CT + h * HD + ad + c;
            float gv = 1.f / (1.f + expf(-gate[idx]));
            o[idx] = gv * acc[i][c] * inv;
        }
    }
}

// ---------------- launch ----------------
static float* symaddr(const void* sym) {
    void* p = nullptr;
    cudaGetSymbolAddress(&p, sym);
    return (float*)p;
}

extern "C" void kernel_launch(void* const* d_in, const int* in_sizes, int n_in,
                              void* d_out, int out_size) {
    const float* a    = (const float*)d_in[0];
    const float* s    = (const float*)d_in[1];
    const float* z    = (const float*)d_in[2];
    const float* bm   = (const float*)d_in[3];
    const float* Wg   = (const float*)d_in[4];
    const float* bg   = (const float*)d_in[5];
    const float* Wb   = (const float*)d_in[6];
    const float* Wq   = (const float*)d_in[7];
    const float* bq   = (const float*)d_in[8];
    const float* Wk   = (const float*)d_in[9];
    const float* Wv   = (const float*)d_in[10];
    const float* Wpb  = (const float*)d_in[11];
    const float* png  = (const float*)d_in[12];
    const float* pnb  = (const float*)d_in[13];
    const float* Wgt  = (const float*)d_in[14];
    const float* Wout = (const float*)d_in[15];
    const float* Wog  = (const float*)d_in[16];
    const float* bog  = (const float*)d_in[17];
    float* out = (float*)d_out;

    float* aln   = symaddr(g_aln);
    float* sln   = symaddr(g_sln);
    float* tmpb  = symaddr(g_tmpb);
    float* anorm = symaddr(g_anorm);
    float* qb    = symaddr(g_q);
    float* kb    = symaddr(g_k);
    float* vb    = symaddr(g_v);
    float* gateb = symaddr(g_gate);
    float* ogb   = symaddr(g_og);
    float* ob    = symaddr(g_o);
    float* pbb   = symaddr(g_pb);

    // LayerNorms
    ln_kernel<<<ROWS, 256>>>(a, aln, CT);
    ln_kernel<<<ROWS, 256>>>(s, sln, CS);

    dim3 gg(CT / 64, ROWS / 128);   // (12, 12)
    // AdaLN: tmpb = s_ln @ Wb_ada ; a_norm = sigmoid(s_ln@Wg_ada + bg)*a_ln + tmpb
    sgemm_kernel<<<gg, 256>>>(sln, Wb, tmpb, ROWS, CT, CS, nullptr, 0, nullptr, nullptr);
    sgemm_kernel<<<gg, 256>>>(sln, Wg, anorm, ROWS, CT, CS, bg, 1, aln, tmpb);
    // QKV + gate
    sgemm_kernel<<<gg, 256>>>(anorm, Wq, qb, ROWS, CT, CT, bq, 0, nullptr, nullptr);
    sgemm_kernel<<<gg, 256>>>(anorm, Wk, kb, ROWS, CT, CT, nullptr, 0, nullptr, nullptr);
    sgemm_kernel<<<gg, 256>>>(anorm, Wv, vb, ROWS, CT, CT, nullptr, 0, nullptr, nullptr);
    sgemm_kernel<<<gg, 256>>>(anorm, Wgt, gateb, ROWS, CT, CT, nullptr, 0, nullptr, nullptr);
    // pair bias (incl. bias_mask)
    pair_kernel<<<dim3(NN / 8, ROWS), 256>>>(z, bm, Wpb, png, pnb, pbb);
    // attention + gating
    cudaFuncSetAttribute(attn_kernel, cudaFuncAttributeMaxDynamicSharedMemorySize, ATTN_SMEM);
    attn_kernel<<<dim3(NN / 64, NH, BB), 256, ATTN_SMEM>>>(qb, kb, vb, gateb, pbb, ob);
    // output gating + projection
    sgemm_kernel<<<gg, 256>>>(s, Wog, ogb, ROWS, CT, CS, bog, 1, nullptr, nullptr);
    sgemm_kernel<<<gg, 256>>>(ob, Wout, out, ROWS, CT, CT, nullptr, 0, ogb, nullptr);
}

// round 4
// speedup vs baseline: 2.1861x; 2.1861x over previous
#include <cuda_runtime.h>
#include <math.h>

#define BB 2
#define NN 768
#define CT 768
#define CS 384
#define CP 128
#define NH 16
#define HD 48
#define ROWS (BB*NN)   /* 1536 */

// ---------------- scratch (device globals; no allocation allowed) ----------------
__device__ float g_aln  [ROWS*CT];
__device__ float g_sln  [ROWS*CS];
__device__ float g_tmpb [ROWS*CT];
__device__ float g_anorm[ROWS*CT];
__device__ float g_q    [ROWS*CT];
__device__ float g_k    [ROWS*CT];
__device__ float g_v    [ROWS*CT];
__device__ float g_gate [ROWS*CT];
__device__ float g_og   [ROWS*CT];
__device__ float g_o    [ROWS*CT];
__device__ float g_pb   [BB*NH*NN*NN];   // 75.5 MB pair bias [b,h,i,j]

// ---------------- tf32 helpers ----------------
__device__ __forceinline__ unsigned f2tf(float f) {
    unsigned u;
    asm("cvt.rna.tf32.f32 %0, %1;" : "=r"(u) : "f"(f));
    return u;
}
__device__ __forceinline__ void mma_tf32(float* c, const unsigned* a, unsigned b0, unsigned b1) {
    asm volatile(
        "mma.sync.aligned.m16n8k8.row.col.f32.tf32.tf32.f32 "
        "{%0,%1,%2,%3}, {%4,%5,%6,%7}, {%8,%9}, {%0,%1,%2,%3};\n"
        : "+f"(c[0]), "+f"(c[1]), "+f"(c[2]), "+f"(c[3])
        : "r"(a[0]), "r"(a[1]), "r"(a[2]), "r"(a[3]), "r"(b0), "r"(b1));
}

// ---------------- LayerNorm (no affine) ----------------
__device__ __forceinline__ float2 blockReduce2(float a, float b) {
    #pragma unroll
    for (int o = 16; o; o >>= 1) {
        a += __shfl_xor_sync(0xffffffffu, a, o);
        b += __shfl_xor_sync(0xffffffffu, b, o);
    }
    __shared__ float sa[8], sb[8];
    int w = threadIdx.x >> 5, l = threadIdx.x & 31;
    if (l == 0) { sa[w] = a; sb[w] = b; }
    __syncthreads();
    if (w == 0) {
        a = (l < 8) ? sa[l] : 0.f;
        b = (l < 8) ? sb[l] : 0.f;
        #pragma unroll
        for (int o = 4; o; o >>= 1) {
            a += __shfl_xor_sync(0xffffffffu, a, o);
            b += __shfl_xor_sync(0xffffffffu, b, o);
        }
        if (l == 0) { sa[0] = a; sb[0] = b; }
    }
    __syncthreads();
    return make_float2(sa[0], sb[0]);
}

__global__ void __launch_bounds__(256) ln_kernel(const float* __restrict__ in,
                                                 float* __restrict__ out, int C) {
    int r = blockIdx.x;
    const float* x = in + (size_t)r * C;
    float s = 0.f, sq = 0.f;
    for (int c = threadIdx.x; c < C; c += 256) { float v = x[c]; s += v; sq += v * v; }
    float2 red = blockReduce2(s, sq);
    float mean = red.x / C;
    float inv = rsqrtf(red.y / C - mean * mean + 1e-5f);
    float* y = out + (size_t)r * C;
    for (int c = threadIdx.x; c < C; c += 256) y[c] = (x[c] - mean) * inv;
}

// ---------------- tf32 GEMM: C = epi(A[M,K] @ B[K,N]) ----------------
// BM=128 BN=64 BK=32, 256 threads = 8 warps in 4(m)x2(n), warp tile 32x32 (2 mtiles x 4 ntiles)
#define GBM 128
#define GBN 64
#define GBK 32
#define GAS 136   /* As stride (m cols) */
#define GBS 72    /* Bs stride (n cols) */

__global__ void __launch_bounds__(256) gemm_tf32_kernel(
    const float* __restrict__ A, const float* __restrict__ B, float* __restrict__ C,
    int M, int N, int K,
    const float* __restrict__ bias, int do_sig,
    const float* __restrict__ mul, const float* __restrict__ add)
{
    __shared__ unsigned As[GBK][GAS];   // [k][m]
    __shared__ unsigned Bs[GBK][GBS];   // [k][n]
    int t = threadIdx.x;
    int w = t >> 5, lane = t & 31;
    int gid = lane >> 2, tig = lane & 3;
    int wm = w >> 1, wn = w & 1;
    int m0 = blockIdx.y * GBM, n0 = blockIdx.x * GBN;
    int mw = wm * 32, nw = wn * 32;

    float acc[2][4][4];
    #pragma unroll
    for (int mt = 0; mt < 2; mt++)
        #pragma unroll
        for (int nt = 0; nt < 4; nt++)
            #pragma unroll
            for (int r = 0; r < 4; r++) acc[mt][nt][r] = 0.f;

    int arow[4], akb[4], brow[2], bc4[2];
    #pragma unroll
    for (int i = 0; i < 4; i++) { int idx = t + i * 256; arow[i] = idx & 127; akb[i] = idx >> 7; }
    #pragma unroll
    for (int i = 0; i < 2; i++) { int idx = t + i * 256; brow[i] = idx >> 4; bc4[i] = idx & 15; }

    float4 ar[4], br[2];
    #pragma unroll
    for (int i = 0; i < 4; i++)
        ar[i] = *(const float4*)(A + (size_t)(m0 + arow[i]) * K + akb[i] * 4);
    #pragma unroll
    for (int i = 0; i < 2; i++)
        br[i] = *(const float4*)(B + (size_t)brow[i] * N + n0 + bc4[i] * 4);

    int nchunk = K / GBK;
    for (int ch = 0; ch < nchunk; ch++) {
        #pragma unroll
        for (int i = 0; i < 4; i++) {
            As[akb[i] * 4 + 0][arow[i]] = f2tf(ar[i].x);
            As[akb[i] * 4 + 1][arow[i]] = f2tf(ar[i].y);
            As[akb[i] * 4 + 2][arow[i]] = f2tf(ar[i].z);
            As[akb[i] * 4 + 3][arow[i]] = f2tf(ar[i].w);
        }
        #pragma unroll
        for (int i = 0; i < 2; i++) {
            Bs[brow[i]][bc4[i] * 4 + 0] = f2tf(br[i].x);
            Bs[brow[i]][bc4[i] * 4 + 1] = f2tf(br[i].y);
            Bs[brow[i]][bc4[i] * 4 + 2] = f2tf(br[i].z);
            Bs[brow[i]][bc4[i] * 4 + 3] = f2tf(br[i].w);
        }
        __syncthreads();
        if (ch + 1 < nchunk) {
            int k0 = (ch + 1) * GBK;
            #pragma unroll
            for (int i = 0; i < 4; i++)
                ar[i] = *(const float4*)(A + (size_t)(m0 + arow[i]) * K + k0 + akb[i] * 4);
            #pragma unroll
            for (int i = 0; i < 2; i++)
                br[i] = *(const float4*)(B + (size_t)(k0 + brow[i]) * N + n0 + bc4[i] * 4);
        }
        #pragma unroll
        for (int ks = 0; ks < 4; ks++) {
            int kb = ks * 8;
            unsigned af[2][4];
            #pragma unroll
            for (int mt = 0; mt < 2; mt++) {
                int mb = mw + mt * 16 + gid;
                af[mt][0] = As[kb + tig][mb];
                af[mt][1] = As[kb + tig][mb + 8];
                af[mt][2] = As[kb + tig + 4][mb];
                af[mt][3] = As[kb + tig + 4][mb + 8];
            }
            unsigned bf[4][2];
            #pragma unroll
            for (int nt = 0; nt < 4; nt++) {
                int nb = nw + nt * 8 + gid;
                bf[nt][0] = Bs[kb + tig][nb];
                bf[nt][1] = Bs[kb + tig + 4][nb];
            }
            #pragma unroll
            for (int mt = 0; mt < 2; mt++)
                #pragma unroll
                for (int nt = 0; nt < 4; nt++)
                    mma_tf32(acc[mt][nt], af[mt], bf[nt][0], bf[nt][1]);
        }
        __syncthreads();
    }

    // epilogue
    #pragma unroll
    for (int mt = 0; mt < 2; mt++) {
        #pragma unroll
        for (int nt = 0; nt < 4; nt++) {
            int r0 = m0 + mw + mt * 16 + gid;
            int c0 = n0 + nw + nt * 8 + 2 * tig;
            #pragma unroll
            for (int rr = 0; rr < 2; rr++) {
                int r = r0 + rr * 8;
                #pragma unroll
                for (int cc = 0; cc < 2; cc++) {
                    float v = acc[mt][nt][rr * 2 + cc];
                    int c = c0 + cc;
                    if (bias) v += bias[c];
                    if (do_sig) v = 1.f / (1.f + __expf(-v));
                    size_t ix = (size_t)r * N + c;
                    if (mul) v *= mul[ix];
                    if (add) v += add[ix];
                    C[ix] = v;
                }
            }
        }
    }
}

// ---------------- pair bias: LN(z)*gamma+beta @ Wpb + bias_mask -> g_pb[b,h,i,j] ----------------
// block: 256 thr, 128 j's for one (b,i); z tile staged in smem; tf32 mma for the 128x16 matvec
#define PJT 128
#define ZST 132
#define WST 24
#define PAIR_SMEM ((PJT*ZST + CP*WST + PJT + CP + CP) * 4)

__global__ void __launch_bounds__(256, 2) pair_kernel(
    const float* __restrict__ z, const float* __restrict__ bmask,
    const float* __restrict__ Wpb, const float* __restrict__ gma,
    const float* __restrict__ bta, float* __restrict__ pb)
{
    extern __shared__ float smp[];
    float* zn = smp;                                  // [128][132] (tf32 after LN)
    unsigned* Wb = (unsigned*)(smp + PJT * ZST);      // [128][24]
    float* bm_s = smp + PJT * ZST + CP * WST;         // [128]
    float* g_s = bm_s + PJT;
    float* b_s = g_s + CP;

    int t = threadIdx.x;
    int w = t >> 5, lane = t & 31;
    int gid = lane >> 2, tig = lane & 3;
    int bi = blockIdx.y;
    int b = bi / NN, i = bi % NN;
    int j0 = blockIdx.x * PJT;

    const float* zrow = z + ((size_t)bi * NN + j0) * CP;
    #pragma unroll
    for (int it = 0; it < 16; it++) {
        int idx = t + it * 256;
        int r = idx >> 5, c4 = idx & 31;
        float4 v = *(const float4*)(zrow + (size_t)r * CP + c4 * 4);
        *(float4*)(zn + r * ZST + c4 * 4) = v;
    }
    for (int idx = t; idx < CP * NH; idx += 256) {
        int c = idx >> 4, hh = idx & 15;
        Wb[c * WST + hh] = f2tf(Wpb[idx]);
    }
    if (t < PJT) bm_s[t] = bmask[(size_t)bi * NN + j0 + t];
    if (t < CP) { g_s[t] = gma[t]; b_s[t] = bta[t]; }
    __syncthreads();

    // LN per row (warp w handles rows w*16..w*16+15), rewrite as tf32
    #pragma unroll 2
    for (int rr = 0; rr < 16; rr++) {
        int r = w * 16 + rr;
        float v0 = zn[r * ZST + lane];
        float v1 = zn[r * ZST + lane + 32];
        float v2 = zn[r * ZST + lane + 64];
        float v3 = zn[r * ZST + lane + 96];
        float s = v0 + v1 + v2 + v3;
        float sq = v0 * v0 + v1 * v1 + v2 * v2 + v3 * v3;
        #pragma unroll
        for (int o = 16; o; o >>= 1) {
            s  += __shfl_xor_sync(0xffffffffu, s, o);
            sq += __shfl_xor_sync(0xffffffffu, sq, o);
        }
        float mean = s * (1.f / CP);
        float inv = rsqrtf(sq * (1.f / CP) - mean * mean + 1e-5f);
        zn[r * ZST + lane]      = __uint_as_float(f2tf((v0 - mean) * inv * g_s[lane]      + b_s[lane]));
        zn[r * ZST + lane + 32] = __uint_as_float(f2tf((v1 - mean) * inv * g_s[lane + 32] + b_s[lane + 32]));
        zn[r * ZST + lane + 64] = __uint_as_float(f2tf((v2 - mean) * inv * g_s[lane + 64] + b_s[lane + 64]));
        zn[r * ZST + lane + 96] = __uint_as_float(f2tf((v3 - mean) * inv * g_s[lane + 96] + b_s[lane + 96]));
    }
    __syncthreads();

    // mma: warp w -> rows mb..mb+15, heads 0..15 (2 ntiles)
    int mb = w * 16;
    float c2[2][4];
    #pragma unroll
    for (int nt = 0; nt < 2; nt++)
        #pragma unroll
        for (int r = 0; r < 4; r++) c2[nt][r] = 0.f;
    #pragma unroll
    for (int ks = 0; ks < 16; ks++) {
        int kb = ks * 8;
        unsigned af[4];
        af[0] = __float_as_uint(zn[(mb + gid) * ZST + kb + tig]);
        af[1] = __float_as_uint(zn[(mb + gid + 8) * ZST + kb + tig]);
        af[2] = __float_as_uint(zn[(mb + gid) * ZST + kb + tig + 4]);
        af[3] = __float_as_uint(zn[(mb + gid + 8) * ZST + kb + tig + 4]);
        #pragma unroll
        for (int nt = 0; nt < 2; nt++) {
            unsigned b0 = Wb[(kb + tig) * WST + nt * 8 + gid];
            unsigned b1 = Wb[(kb + tig + 4) * WST + nt * 8 + gid];
            mma_tf32(c2[nt], af, b0, b1);
        }
    }
    float bm0 = bm_s[mb + gid], bm1 = bm_s[mb + gid + 8];
    int jg0 = j0 + mb + gid;
    #pragma unroll
    for (int nt = 0; nt < 2; nt++) {
        int h0 = nt * 8 + 2 * tig;
        size_t base0 = ((size_t)(b * NH + h0) * NN + i) * NN;
        size_t base1 = ((size_t)(b * NH + h0 + 1) * NN + i) * NN;
        pb[base0 + jg0]     = c2[nt][0] + bm0;
        pb[base1 + jg0]     = c2[nt][1] + bm0;
        pb[base0 + jg0 + 8] = c2[nt][2] + bm1;
        pb[base1 + jg0 + 8] = c2[nt][3] + bm1;
    }
}

// ---------------- attention: flash-style with tf32 mma ----------------
#define ATQ 52    /* Qs/Ks stride (row varies with gid in frag) */
#define AVQ 56    /* Vs stride (row varies with tig in frag) */
#define ATP 68    /* Ps stride */
#define ATTN_SMEM ((2*64*ATQ + 64*AVQ + 64*ATP + 3*64) * 4)

__global__ void __launch_bounds__(256, 3) attn_kernel(
    const float* __restrict__ q, const float* __restrict__ k,
    const float* __restrict__ v, const float* __restrict__ gate,
    const float* __restrict__ pb, float* __restrict__ o)
{
    extern __shared__ float sm[];
    unsigned* Qs = (unsigned*)sm;           // [64][52]
    unsigned* Ks = Qs + 64 * ATQ;           // [64][52]
    unsigned* Vs = Ks + 64 * ATQ;           // [64][56]
    float* Ps = (float*)(Vs + 64 * AVQ);    // [64][68]
    float* Ms = Ps + 64 * ATP;
    float* Ls = Ms + 64;
    float* Ss = Ls + 64;

    int qt = blockIdx.x, hh = blockIdx.y, b = blockIdx.z;
    int t = threadIdx.x;
    int w = t >> 5, lane = t & 31;
    int gid = lane >> 2, tig = lane & 3;
    int q0 = qt * 64;
    const float SC = 0.14433756729740643f;  // 1/sqrt(48)

    for (int idx = t; idx < 64 * HD; idx += 256) {
        int r = idx / HD, d = idx % HD;
        Qs[r * ATQ + d] = f2tf(q[((size_t)(b * NN + q0 + r)) * CT + hh * HD + d] * SC);
    }
    if (t < 64) { Ms[t] = -1e30f; Ls[t] = 0.f; }

    // S warps: 2(m) x 4(n): warp tile 32m x 16n
    int wmS = w >> 2, wnS = w & 3;
    int mbS = wmS * 32, nbS = wnS * 16;
    // PV warps: 4(m) x 2(n): warp tile 16m x 24n
    int wmP = w >> 1, wnP = w & 1;
    int mbP = wmP * 16, nbP = wnP * 24;

    float oacc[3][4];
    #pragma unroll
    for (int nt = 0; nt < 3; nt++)
        #pragma unroll
        for (int r = 0; r < 4; r++) oacc[nt][r] = 0.f;

    const float* bp0 = pb + ((size_t)(b * NH + hh) * NN + q0) * NN;

    for (int kt = 0; kt < 12; kt++) {
        int k0 = kt * 64;
        __syncthreads();
        for (int idx = t; idx < 64 * HD; idx += 256) {
            int r = idx / HD, d = idx % HD;
            size_t gi = ((size_t)(b * NN + k0 + r)) * CT + hh * HD + d;
            Ks[r * ATQ + d] = f2tf(k[gi]);
            Vs[r * AVQ + d] = f2tf(v[gi]);
        }
        for (int idx = t; idx < 64 * 16; idx += 256) {
            int r = idx >> 4, c4 = idx & 15;
            float4 bv = *(const float4*)(bp0 + (size_t)r * NN + k0 + c4 * 4);
            *(float4*)(Ps + r * ATP + c4 * 4) = bv;
        }
        __syncthreads();

        // S = Q @ K^T via mma, accumulate into bias tile in Ps
        float sacc[2][2][4];
        #pragma unroll
        for (int mt = 0; mt < 2; mt++)
            #pragma unroll
            for (int nt = 0; nt < 2; nt++)
                #pragma unroll
                for (int r = 0; r < 4; r++) sacc[mt][nt][r] = 0.f;
        #pragma unroll
        for (int ks = 0; ks < 6; ks++) {
            int kb = ks * 8;
            unsigned af[2][4];
            #pragma unroll
            for (int mt = 0; mt < 2; mt++) {
                int mr = mbS + mt * 16 + gid;
                af[mt][0] = Qs[mr * ATQ + kb + tig];
                af[mt][1] = Qs[(mr + 8) * ATQ + kb + tig];
                af[mt][2] = Qs[mr * ATQ + kb + tig + 4];
                af[mt][3] = Qs[(mr + 8) * ATQ + kb + tig + 4];
            }
            #pragma unroll
            for (int nt = 0; nt < 2; nt++) {
                int nr = nbS + nt * 8 + gid;
                unsigned b0 = Ks[nr * ATQ + kb + tig];
                unsigned b1 = Ks[nr * ATQ + kb + tig + 4];
                #pragma unroll
                for (int mt = 0; mt < 2; mt++)
                    mma_tf32(sacc[mt][nt], af[mt], b0, b1);
            }
        }
        #pragma unroll
        for (int mt = 0; mt < 2; mt++) {
            #pragma unroll
            for (int nt = 0; nt < 2; nt++) {
                int r = mbS + mt * 16 + gid;
                int c = nbS + nt * 8 + 2 * tig;
                float* p0 = Ps + r * ATP + c;
                float* p1 = Ps + (r + 8) * ATP + c;
                p0[0] += sacc[mt][nt][0];
                p0[1] += sacc[mt][nt][1];
                p1[0] += sacc[mt][nt][2];
                p1[1] += sacc[mt][nt][3];
            }
        }
        __syncthreads();

        // online softmax: 4 lanes per query row
        {
            int qq = t >> 2, pp = t & 3;
            float* prow = Ps + qq * ATP + pp * 16;
            float tmax = -1e30f;
            #pragma unroll
            for (int jj = 0; jj < 16; jj++) tmax = fmaxf(tmax, prow[jj]);
            tmax = fmaxf(tmax, __shfl_xor_sync(0xffffffffu, tmax, 1));
            tmax = fmaxf(tmax, __shfl_xor_sync(0xffffffffu, tmax, 2));
            float mold = Ms[qq];
            float mnew = fmaxf(mold, tmax);
            float tsum = 0.f;
            #pragma unroll
            for (int jj = 0; jj < 16; jj++) {
                float p = __expf(prow[jj] - mnew);
                prow[jj] = p; tsum += p;
            }
            tsum += __shfl_xor_sync(0xffffffffu, tsum, 1);
            tsum += __shfl_xor_sync(0xffffffffu, tsum, 2);
            if (pp == 0) {
                float scl = __expf(mold - mnew);
                Ss[qq] = scl;
                Ls[qq] = Ls[qq] * scl + tsum;
                Ms[qq] = mnew;
            }
        }
        __syncthreads();

        // rescale + O += P @ V via mma
        {
            float s0 = Ss[mbP + gid], s1 = Ss[mbP + gid + 8];
            #pragma unroll
            for (int nt = 0; nt < 3; nt++) {
                oacc[nt][0] *= s0; oacc[nt][1] *= s0;
                oacc[nt][2] *= s1; oacc[nt][3] *= s1;
            }
            #pragma unroll
            for (int ks = 0; ks < 8; ks++) {
                int kb = ks * 8;
                unsigned af[4];
                af[0] = f2tf(Ps[(mbP + gid) * ATP + kb + tig]);
                af[1] = f2tf(Ps[(mbP + gid + 8) * ATP + kb + tig]);
                af[2] = f2tf(Ps[(mbP + gid) * ATP + kb + tig + 4]);
                af[3] = f2tf(Ps[(mbP + gid + 8) * ATP + kb + tig + 4]);
                #pragma unroll
                for (int nt = 0; nt < 3; nt++) {
                    unsigned b0 = Vs[(kb + tig) * AVQ + nbP + nt * 8 + gid];
                    unsigned b1 = Vs[(kb + tig + 4) * AVQ + nbP + nt * 8 + gid];
                    mma_tf32(oacc[nt], af, b0, b1);
                }
            }
        }
    }

    // epilogue: normalize, gate, write
    __syncthreads();
    float inv0 = 1.f / Ls[mbP + gid];
    float inv1 = 1.f / Ls[mbP + gid + 8];
    size_t row0 = (size_t)(b * NN + q0 + mbP + gid);
    size_t row1 = row0 + 8;
    #pragma unroll
    for (int nt = 0; nt < 3; nt++) {
        int c = hh * HD + nbP + nt * 8 + 2 * tig;
        size_t i00 = row0 * CT + c;
        size_t i10 = row1 * CT + c;
        float g00 = 1.f / (1.f + __expf(-gate[i00]));
        float g01 = 1.f / (1.f + __expf(-gate[i00 + 1]));
        float g10 = 1.f / (1.f + __expf(-gate[i10]));
        float g11 = 1.f / (1.f + __expf(-gate[i10 + 1]));
        o[i00]     = g00 * oacc[nt][0] * inv0;
        o[i00 + 1] = g01 * oacc[nt][1] * inv0;
        o[i10]     = g10 * oacc[nt][2] * inv1;
        o[i10 + 1] = g11 * oacc[nt][3] * inv1;
    }
}

// ---------------- launch ----------------
static float* symaddr(const void* sym) {
    void* p = nullptr;
    cudaGetSymbolAddress(&p, sym);
    return (float*)p;
}

extern "C" void kernel_launch(void* const* d_in, const int* in_sizes, int n_in,
                              void* d_out, int out_size) {
    const float* a    = (const float*)d_in[0];
    const float* s    = (const float*)d_in[1];
    const float* z    = (const float*)d_in[2];
    const float* bm   = (const float*)d_in[3];
    const float* Wg   = (const float*)d_in[4];
    const float* bg   = (const float*)d_in[5];
    const float* Wb   = (const float*)d_in[6];
    const float* Wq   = (const float*)d_in[7];
    const float* bq   = (const float*)d_in[8];
    const float* Wk   = (const float*)d_in[9];
    const float* Wv   = (const float*)d_in[10];
    const float* Wpb  = (const float*)d_in[11];
    const float* png  = (const float*)d_in[12];
    const float* pnb  = (const float*)d_in[13];
    const float* Wgt  = (const float*)d_in[14];
    const float* Wout = (const float*)d_in[15];
    const float* Wog  = (const float*)d_in[16];
    const float* bog  = (const float*)d_in[17];
    float* out = (float*)d_out;

    float* aln   = symaddr(g_aln);
    float* sln   = symaddr(g_sln);
    float* tmpb  = symaddr(g_tmpb);
    float* anorm = symaddr(g_anorm);
    float* qb    = symaddr(g_q);
    float* kb    = symaddr(g_k);
    float* vb    = symaddr(g_v);
    float* gateb = symaddr(g_gate);
    float* ogb   = symaddr(g_og);
    float* ob    = symaddr(g_o);
    float* pbb   = symaddr(g_pb);

    cudaFuncSetAttribute(pair_kernel, cudaFuncAttributeMaxDynamicSharedMemorySize, PAIR_SMEM);
    cudaFuncSetAttribute(attn_kernel, cudaFuncAttributeMaxDynamicSharedMemorySize, ATTN_SMEM);

    // LayerNorms
    ln_kernel<<<ROWS, 256>>>(a, aln, CT);
    ln_kernel<<<ROWS, 256>>>(s, sln, CS);

    dim3 gg(CT / GBN, ROWS / GBM);   // (12, 12)
    // AdaLN: tmpb = s_ln @ Wb_ada ; a_norm = sigmoid(s_ln@Wg_ada + bg)*a_ln + tmpb
    gemm_tf32_kernel<<<gg, 256>>>(sln, Wb, tmpb, ROWS, CT, CS, nullptr, 0, nullptr, nullptr);
    gemm_tf32_kernel<<<gg, 256>>>(sln, Wg, anorm, ROWS, CT, CS, bg, 1, aln, tmpb);
    // QKV + gate
    gemm_tf32_kernel<<<gg, 256>>>(anorm, Wq, qb, ROWS, CT, CT, bq, 0, nullptr, nullptr);
    gemm_tf32_kernel<<<gg, 256>>>(anorm, Wk, kb, ROWS, CT, CT, nullptr, 0, nullptr, nullptr);
    gemm_tf32_kernel<<<gg, 256>>>(anorm, Wv, vb, ROWS, CT, CT, nullptr, 0, nullptr, nullptr);
    gemm_tf32_kernel<<<gg, 256>>>(anorm, Wgt, gateb, ROWS, CT, CT, nullptr, 0, nullptr, nullptr);
    // pair bias (incl. bias_mask)
    pair_kernel<<<dim3(NN / PJT, ROWS), 256, PAIR_SMEM>>>(z, bm, Wpb, png, pnb, pbb);
    // attention + gating
    attn_kernel<<<dim3(NN / 64, NH, BB), 256, ATTN_SMEM>>>(qb, kb, vb, gateb, pbb, ob);
    // output gating + projection
    gemm_tf32_kernel<<<gg, 256>>>(s, Wog, ogb, ROWS, CT, CS, bog, 1, nullptr, nullptr);
    gemm_tf32_kernel<<<gg, 256>>>(ob, Wout, out, ROWS, CT, CT, nullptr, 0, ogb, nullptr);
}

// round 8
// speedup vs baseline: 2.3731x; 1.0855x over previous
#include <cuda_runtime.h>
#include <math.h>

#define BB 2
#define NN 768
#define CT 768
#define CS 384
#define CP 128
#define NH 16
#define HD 48
#define ROWS (BB*NN)   /* 1536 */

// ---------------- scratch (device globals; no allocation allowed) ----------------
__device__ float g_aln  [ROWS*CT];
__device__ float g_sln  [ROWS*CS];
__device__ float g_tmpb [ROWS*CT];
__device__ float g_anorm[ROWS*CT];
__device__ float g_q    [ROWS*CT];
__device__ float g_k    [ROWS*CT];
__device__ float g_v    [ROWS*CT];
__device__ float g_gate [ROWS*CT];
__device__ float g_og   [ROWS*CT];
__device__ float g_o    [ROWS*CT];
__device__ float g_pb   [BB*NH*NN*NN];   // 75.5 MB pair bias [b,h,i,j]

// ---------------- tf32 helpers ----------------
__device__ __forceinline__ unsigned f2tf(float f) {
    unsigned u;
    asm("cvt.rna.tf32.f32 %0, %1;" : "=r"(u) : "f"(f));
    return u;
}
__device__ __forceinline__ void mma_tf32(float* c, const unsigned* a, unsigned b0, unsigned b1) {
    asm volatile(
        "mma.sync.aligned.m16n8k8.row.col.f32.tf32.tf32.f32 "
        "{%0,%1,%2,%3}, {%4,%5,%6,%7}, {%8,%9}, {%0,%1,%2,%3};\n"
        : "+f"(c[0]), "+f"(c[1]), "+f"(c[2]), "+f"(c[3])
        : "r"(a[0]), "r"(a[1]), "r"(a[2]), "r"(a[3]), "r"(b0), "r"(b1));
}

// ---------------- fused LayerNorms (no affine) ----------------
__device__ __forceinline__ float2 blockReduce2(float a, float b) {
    #pragma unroll
    for (int o = 16; o; o >>= 1) {
        a += __shfl_xor_sync(0xffffffffu, a, o);
        b += __shfl_xor_sync(0xffffffffu, b, o);
    }
    __shared__ float sa[8], sb[8];
    int w = threadIdx.x >> 5, l = threadIdx.x & 31;
    if (l == 0) { sa[w] = a; sb[w] = b; }
    __syncthreads();
    if (w == 0) {
        a = (l < 8) ? sa[l] : 0.f;
        b = (l < 8) ? sb[l] : 0.f;
        #pragma unroll
        for (int o = 4; o; o >>= 1) {
            a += __shfl_xor_sync(0xffffffffu, a, o);
            b += __shfl_xor_sync(0xffffffffu, b, o);
        }
        if (l == 0) { sa[0] = a; sb[0] = b; }
    }
    __syncthreads();
    return make_float2(sa[0], sb[0]);
}

__global__ void __launch_bounds__(256) ln2_kernel(
    const float* __restrict__ a, const float* __restrict__ s,
    float* __restrict__ aout, float* __restrict__ sout)
{
    int C = (blockIdx.y == 0) ? CT : CS;
    const float* in = (blockIdx.y == 0) ? a : s;
    float* out = (blockIdx.y == 0) ? aout : sout;
    int r = blockIdx.x;
    const float* x = in + (size_t)r * C;
    float sm = 0.f, sq = 0.f;
    for (int c = threadIdx.x; c < C; c += 256) { float v = x[c]; sm += v; sq += v * v; }
    float2 red = blockReduce2(sm, sq);
    float mean = red.x / C;
    float inv = rsqrtf(red.y / C - mean * mean + 1e-5f);
    float* y = out + (size_t)r * C;
    for (int c = threadIdx.x; c < C; c += 256) y[c] = (x[c] - mean) * inv;
}

// ---------------- batched tf32 GEMM: C[z] = epi(A[z][M,K] @ B[z][K,N]) ----------------
struct GemmJob {
    const float* A; const float* B; float* C;
    const float* bias; const float* mul; const float* add;
    int K; int sig;
};
struct GemmBatchArgs { GemmJob j[4]; };

// BM x 64 x 32 tiles, 256 threads = 8 warps (4m x 2n); warp tile (BM/4) x 32
template <int BM>
__global__ void __launch_bounds__(256, 2) gemm_batch_kernel(GemmBatchArgs p, int M, int N) {
    const GemmJob jb = p.j[blockIdx.z];
    const float* __restrict__ A = jb.A;
    const float* __restrict__ B = jb.B;
    const int K = jb.K;
    constexpr int MT = BM / 64;           // mtiles per warp
    constexpr int NLD = BM / 32;          // A staging iters

    __shared__ unsigned As[32][BM + 8];
    __shared__ unsigned Bs[32][72];
    int t = threadIdx.x;
    int w = t >> 5, lane = t & 31;
    int gid = lane >> 2, tig = lane & 3;
    int wm = w >> 1, wn = w & 1;
    int m0 = blockIdx.y * BM, n0 = blockIdx.x * 64;
    int mw = wm * (BM / 4), nw = wn * 32;

    float acc[MT][4][4];
    #pragma unroll
    for (int mt = 0; mt < MT; mt++)
        #pragma unroll
        for (int nt = 0; nt < 4; nt++)
            #pragma unroll
            for (int r = 0; r < 4; r++) acc[mt][nt][r] = 0.f;

    int arow[NLD], akb[NLD], brow[2], bc4[2];
    #pragma unroll
    for (int i = 0; i < NLD; i++) { int idx = t + i * 256; arow[i] = idx & (BM - 1); akb[i] = idx / BM; }
    #pragma unroll
    for (int i = 0; i < 2; i++) { int idx = t + i * 256; brow[i] = idx >> 4; bc4[i] = idx & 15; }

    float4 ar[NLD], br[2];
    #pragma unroll
    for (int i = 0; i < NLD; i++)
        ar[i] = *(const float4*)(A + (size_t)(m0 + arow[i]) * K + akb[i] * 4);
    #pragma unroll
    for (int i = 0; i < 2; i++)
        br[i] = *(const float4*)(B + (size_t)brow[i] * N + n0 + bc4[i] * 4);

    int nchunk = K / 32;
    for (int ch = 0; ch < nchunk; ch++) {
        #pragma unroll
        for (int i = 0; i < NLD; i++) {
            As[akb[i] * 4 + 0][arow[i]] = f2tf(ar[i].x);
            As[akb[i] * 4 + 1][arow[i]] = f2tf(ar[i].y);
            As[akb[i] * 4 + 2][arow[i]] = f2tf(ar[i].z);
            As[akb[i] * 4 + 3][arow[i]] = f2tf(ar[i].w);
        }
        #pragma unroll
        for (int i = 0; i < 2; i++) {
            Bs[brow[i]][bc4[i] * 4 + 0] = f2tf(br[i].x);
            Bs[brow[i]][bc4[i] * 4 + 1] = f2tf(br[i].y);
            Bs[brow[i]][bc4[i] * 4 + 2] = f2tf(br[i].z);
            Bs[brow[i]][bc4[i] * 4 + 3] = f2tf(br[i].w);
        }
        __syncthreads();
        if (ch + 1 < nchunk) {
            int k0 = (ch + 1) * 32;
            #pragma unroll
            for (int i = 0; i < NLD; i++)
                ar[i] = *(const float4*)(A + (size_t)(m0 + arow[i]) * K + k0 + akb[i] * 4);
            #pragma unroll
            for (int i = 0; i < 2; i++)
                br[i] = *(const float4*)(B + (size_t)(k0 + brow[i]) * N + n0 + bc4[i] * 4);
        }
        #pragma unroll
        for (int ks = 0; ks < 4; ks++) {
            int kb = ks * 8;
            unsigned af[MT][4];
            #pragma unroll
            for (int mt = 0; mt < MT; mt++) {
                int mb = mw + mt * 16 + gid;
                af[mt][0] = As[kb + tig][mb];
                af[mt][1] = As[kb + tig][mb + 8];
                af[mt][2] = As[kb + tig + 4][mb];
                af[mt][3] = As[kb + tig + 4][mb + 8];
            }
            unsigned bf[4][2];
            #pragma unroll
            for (int nt = 0; nt < 4; nt++) {
                int nb = nw + nt * 8 + gid;
                bf[nt][0] = Bs[kb + tig][nb];
                bf[nt][1] = Bs[kb + tig + 4][nb];
            }
            #pragma unroll
            for (int mt = 0; mt < MT; mt++)
                #pragma unroll
                for (int nt = 0; nt < 4; nt++)
                    mma_tf32(acc[mt][nt], af[mt], bf[nt][0], bf[nt][1]);
        }
        __syncthreads();
    }

    // epilogue
    const float* bias = jb.bias;
    const float* mul = jb.mul;
    const float* add = jb.add;
    int do_sig = jb.sig;
    float* C = jb.C;
    #pragma unroll
    for (int mt = 0; mt < MT; mt++) {
        #pragma unroll
        for (int nt = 0; nt < 4; nt++) {
            int r0 = m0 + mw + mt * 16 + gid;
            int c0 = n0 + nw + nt * 8 + 2 * tig;
            #pragma unroll
            for (int rr = 0; rr < 2; rr++) {
                int r = r0 + rr * 8;
                #pragma unroll
                for (int cc = 0; cc < 2; cc++) {
                    float v = acc[mt][nt][rr * 2 + cc];
                    int c = c0 + cc;
                    if (bias) v += bias[c];
                    if (do_sig) v = 1.f / (1.f + __expf(-v));
                    size_t ix = (size_t)r * N + c;
                    if (mul) v *= mul[ix];
                    if (add) v += add[ix];
                    C[ix] = v;
                }
            }
        }
    }
}

// ---------------- elementwise adaLN combine: anorm = gsig*aln + tmpb ----------------
__global__ void __launch_bounds__(256) combine_kernel(
    float* __restrict__ anorm, const float* __restrict__ aln, const float* __restrict__ tmpb)
{
    int i = blockIdx.x * 256 + threadIdx.x;
    float4 g = ((const float4*)anorm)[i];
    float4 a = ((const float4*)aln)[i];
    float4 tb = ((const float4*)tmpb)[i];
    g.x = g.x * a.x + tb.x;
    g.y = g.y * a.y + tb.y;
    g.z = g.z * a.z + tb.z;
    g.w = g.w * a.w + tb.w;
    ((float4*)anorm)[i] = g;
}

// ---------------- pair bias: LN(z)*gamma+beta @ Wpb + bias_mask -> g_pb[b,h,i,j] ----------------
#define PJT 128
#define ZST 132
#define WST 24
#define PAIR_SMEM ((PJT*ZST + CP*WST + PJT + CP + CP) * 4)

__global__ void __launch_bounds__(256, 2) pair_kernel(
    const float* __restrict__ z, const float* __restrict__ bmask,
    const float* __restrict__ Wpb, const float* __restrict__ gma,
    const float* __restrict__ bta, float* __restrict__ pb)
{
    extern __shared__ float smp[];
    float* zn = smp;                                  // [128][132]
    unsigned* Wb = (unsigned*)(smp + PJT * ZST);      // [128][24]
    float* bm_s = smp + PJT * ZST + CP * WST;         // [128]
    float* g_s = bm_s + PJT;
    float* b_s = g_s + CP;

    int t = threadIdx.x;
    int w = t >> 5, lane = t & 31;
    int gid = lane >> 2, tig = lane & 3;
    int bi = blockIdx.y;
    int b = bi / NN, i = bi % NN;
    int j0 = blockIdx.x * PJT;

    const float* zrow = z + ((size_t)bi * NN + j0) * CP;
    #pragma unroll
    for (int it = 0; it < 16; it++) {
        int idx = t + it * 256;
        int r = idx >> 5, c4 = idx & 31;
        float4 v = *(const float4*)(zrow + (size_t)r * CP + c4 * 4);
        *(float4*)(zn + r * ZST + c4 * 4) = v;
    }
    for (int idx = t; idx < CP * NH; idx += 256) {
        int c = idx >> 4, hh = idx & 15;
        Wb[c * WST + hh] = f2tf(Wpb[idx]);
    }
    if (t < PJT) bm_s[t] = bmask[(size_t)bi * NN + j0 + t];
    if (t < CP) { g_s[t] = gma[t]; b_s[t] = bta[t]; }
    __syncthreads();

    #pragma unroll 2
    for (int rr = 0; rr < 16; rr++) {
        int r = w * 16 + rr;
        float v0 = zn[r * ZST + lane];
        float v1 = zn[r * ZST + lane + 32];
        float v2 = zn[r * ZST + lane + 64];
        float v3 = zn[r * ZST + lane + 96];
        float s = v0 + v1 + v2 + v3;
        float sq = v0 * v0 + v1 * v1 + v2 * v2 + v3 * v3;
        #pragma unroll
        for (int o = 16; o; o >>= 1) {
            s  += __shfl_xor_sync(0xffffffffu, s, o);
            sq += __shfl_xor_sync(0xffffffffu, sq, o);
        }
        float mean = s * (1.f / CP);
        float inv = rsqrtf(sq * (1.f / CP) - mean * mean + 1e-5f);
        zn[r * ZST + lane]      = __uint_as_float(f2tf((v0 - mean) * inv * g_s[lane]      + b_s[lane]));
        zn[r * ZST + lane + 32] = __uint_as_float(f2tf((v1 - mean) * inv * g_s[lane + 32] + b_s[lane + 32]));
        zn[r * ZST + lane + 64] = __uint_as_float(f2tf((v2 - mean) * inv * g_s[lane + 64] + b_s[lane + 64]));
        zn[r * ZST + lane + 96] = __uint_as_float(f2tf((v3 - mean) * inv * g_s[lane + 96] + b_s[lane + 96]));
    }
    __syncthreads();

    int mb = w * 16;
    float c2[2][4];
    #pragma unroll
    for (int nt = 0; nt < 2; nt++)
        #pragma unroll
        for (int r = 0; r < 4; r++) c2[nt][r] = 0.f;
    #pragma unroll
    for (int ks = 0; ks < 16; ks++) {
        int kb = ks * 8;
        unsigned af[4];
        af[0] = __float_as_uint(zn[(mb + gid) * ZST + kb + tig]);
        af[1] = __float_as_uint(zn[(mb + gid + 8) * ZST + kb + tig]);
        af[2] = __float_as_uint(zn[(mb + gid) * ZST + kb + tig + 4]);
        af[3] = __float_as_uint(zn[(mb + gid + 8) * ZST + kb + tig + 4]);
        #pragma unroll
        for (int nt = 0; nt < 2; nt++) {
            unsigned b0 = Wb[(kb + tig) * WST + nt * 8 + gid];
            unsigned b1 = Wb[(kb + tig + 4) * WST + nt * 8 + gid];
            mma_tf32(c2[nt], af, b0, b1);
        }
    }
    float bm0 = bm_s[mb + gid], bm1 = bm_s[mb + gid + 8];
    int jg0 = j0 + mb + gid;
    #pragma unroll
    for (int nt = 0; nt < 2; nt++) {
        int h0 = nt * 8 + 2 * tig;
        size_t base0 = ((size_t)(b * NH + h0) * NN + i) * NN;
        size_t base1 = ((size_t)(b * NH + h0 + 1) * NN + i) * NN;
        pb[base0 + jg0]     = c2[nt][0] + bm0;
        pb[base1 + jg0]     = c2[nt][1] + bm0;
        pb[base0 + jg0 + 8] = c2[nt][2] + bm1;
        pb[base1 + jg0 + 8] = c2[nt][3] + bm1;
    }
}

// ---------------- attention: flash-style with tf32 mma ----------------
#define ATQ 52
#define AVQ 56
#define ATP 68
#define ATTN_SMEM ((2*64*ATQ + 64*AVQ + 64*ATP + 3*64) * 4)

__global__ void __launch_bounds__(256, 3) attn_kernel(
    const float* __restrict__ q, const float* __restrict__ k,
    const float* __restrict__ v, const float* __restrict__ gate,
    const float* __restrict__ pb, float* __restrict__ o)
{
    extern __shared__ float sm[];
    unsigned* Qs = (unsigned*)sm;           // [64][52]
    unsigned* Ks = Qs + 64 * ATQ;           // [64][52]
    unsigned* Vs = Ks + 64 * ATQ;           // [64][56]
    float* Ps = (float*)(Vs + 64 * AVQ);    // [64][68]
    float* Ms = Ps + 64 * ATP;
    float* Ls = Ms + 64;
    float* Ss = Ls + 64;

    int qt = blockIdx.x, hh = blockIdx.y, b = blockIdx.z;
    int t = threadIdx.x;
    int w = t >> 5, lane = t & 31;
    int gid = lane >> 2, tig = lane & 3;
    int q0 = qt * 64;
    const float SC = 0.14433756729740643f;  // 1/sqrt(48)

    for (int idx = t; idx < 64 * HD; idx += 256) {
        int r = idx / HD, d = idx % HD;
        Qs[r * ATQ + d] = f2tf(q[((size_t)(b * NN + q0 + r)) * CT + hh * HD + d] * SC);
    }
    if (t < 64) { Ms[t] = -1e30f; Ls[t] = 0.f; }

    int wmS = w >> 2, wnS = w & 3;
    int mbS = wmS * 32, nbS = wnS * 16;
    int wmP = w >> 1, wnP = w & 1;
    int mbP = wmP * 16, nbP = wnP * 24;

    float oacc[3][4];
    #pragma unroll
    for (int nt = 0; nt < 3; nt++)
        #pragma unroll
        for (int r = 0; r < 4; r++) oacc[nt][r] = 0.f;

    const float* bp0 = pb + ((size_t)(b * NH + hh) * NN + q0) * NN;

    for (int kt = 0; kt < 12; kt++) {
        int k0 = kt * 64;
        __syncthreads();
        for (int idx = t; idx < 64 * HD; idx += 256) {
            int r = idx / HD, d = idx % HD;
            size_t gi = ((size_t)(b * NN + k0 + r)) * CT + hh * HD + d;
            Ks[r * ATQ + d] = f2tf(k[gi]);
            Vs[r * AVQ + d] = f2tf(v[gi]);
        }
        for (int idx = t; idx < 64 * 16; idx += 256) {
            int r = idx >> 4, c4 = idx & 15;
            float4 bv = *(const float4*)(bp0 + (size_t)r * NN + k0 + c4 * 4);
            *(float4*)(Ps + r * ATP + c4 * 4) = bv;
        }
        __syncthreads();

        float sacc[2][2][4];
        #pragma unroll
        for (int mt = 0; mt < 2; mt++)
            #pragma unroll
            for (int nt = 0; nt < 2; nt++)
                #pragma unroll
                for (int r = 0; r < 4; r++) sacc[mt][nt][r] = 0.f;
        #pragma unroll
        for (int ks = 0; ks < 6; ks++) {
            int kb = ks * 8;
            unsigned af[2][4];
            #pragma unroll
            for (int mt = 0; mt < 2; mt++) {
                int mr = mbS + mt * 16 + gid;
                af[mt][0] = Qs[mr * ATQ + kb + tig];
                af[mt][1] = Qs[(mr + 8) * ATQ + kb + tig];
                af[mt][2] = Qs[mr * ATQ + kb + tig + 4];
                af[mt][3] = Qs[(mr + 8) * ATQ + kb + tig + 4];
            }
            #pragma unroll
            for (int nt = 0; nt < 2; nt++) {
                int nr = nbS + nt * 8 + gid;
                unsigned b0 = Ks[nr * ATQ + kb + tig];
                unsigned b1 = Ks[nr * ATQ + kb + tig + 4];
                #pragma unroll
                for (int mt = 0; mt < 2; mt++)
                    mma_tf32(sacc[mt][nt], af[mt], b0, b1);
            }
        }
        #pragma unroll
        for (int mt = 0; mt < 2; mt++) {
            #pragma unroll
            for (int nt = 0; nt < 2; nt++) {
                int r = mbS + mt * 16 + gid;
                int c = nbS + nt * 8 + 2 * tig;
                float* p0 = Ps + r * ATP + c;
                float* p1 = Ps + (r + 8) * ATP + c;
                p0[0] += sacc[mt][nt][0];
                p0[1] += sacc[mt][nt][1];
                p1[0] += sacc[mt][nt][2];
                p1[1] += sacc[mt][nt][3];
            }
        }
        __syncthreads();

        // online softmax: 4 lanes per query row, stride-4 interleave (conflict-free)
        {
            int qq = t >> 2, pp = t & 3;
            float* prow = Ps + qq * ATP + pp;
            float tmax = -1e30f;
            #pragma unroll
            for (int jj = 0; jj < 16; jj++) tmax = fmaxf(tmax, prow[jj * 4]);
            tmax = fmaxf(tmax, __shfl_xor_sync(0xffffffffu, tmax, 1));
            tmax = fmaxf(tmax, __shfl_xor_sync(0xffffffffu, tmax, 2));
            float mold = Ms[qq];
            float mnew = fmaxf(mold, tmax);
            float tsum = 0.f;
            #pragma unroll
            for (int jj = 0; jj < 16; jj++) {
                float p = __expf(prow[jj * 4] - mnew);
                prow[jj * 4] = p; tsum += p;
            }
            tsum += __shfl_xor_sync(0xffffffffu, tsum, 1);
            tsum += __shfl_xor_sync(0xffffffffu, tsum, 2);
            if (pp == 0) {
                float scl = __expf(mold - mnew);
                Ss[qq] = scl;
                Ls[qq] = Ls[qq] * scl + tsum;
                Ms[qq] = mnew;
            }
        }
        __syncthreads();

        // rescale + O += P @ V via mma
        {
            float s0 = Ss[mbP + gid], s1 = Ss[mbP + gid + 8];
            #pragma unroll
            for (int nt = 0; nt < 3; nt++) {
                oacc[nt][0] *= s0; oacc[nt][1] *= s0;
                oacc[nt][2] *= s1; oacc[nt][3] *= s1;
            }
            #pragma unroll
            for (int ks = 0; ks < 8; ks++) {
                int kb = ks * 8;
                unsigned af[4];
                af[0] = f2tf(Ps[(mbP + gid) * ATP + kb + tig]);
                af[1] = f2tf(Ps[(mbP + gid + 8) * ATP + kb + tig]);
                af[2] = f2tf(Ps[(mbP + gid) * ATP + kb + tig + 4]);
                af[3] = f2tf(Ps[(mbP + gid + 8) * ATP + kb + tig + 4]);
                #pragma unroll
                for (int nt = 0; nt < 3; nt++) {
                    unsigned b0 = Vs[(kb + tig) * AVQ + nbP + nt * 8 + gid];
                    unsigned b1 = Vs[(kb + tig + 4) * AVQ + nbP + nt * 8 + gid];
                    mma_tf32(oacc[nt], af, b0, b1);
                }
            }
        }
    }

    // epilogue: normalize, gate, write
    __syncthreads();
    float inv0 = 1.f / Ls[mbP + gid];
    float inv1 = 1.f / Ls[mbP + gid + 8];
    size_t row0 = (size_t)(b * NN + q0 + mbP + gid);
    size_t row1 = row0 + 8;
    #pragma unroll
    for (int nt = 0; nt < 3; nt++) {
        int c = hh * HD + nbP + nt * 8 + 2 * tig;
        size_t i00 = row0 * CT + c;
        size_t i10 = row1 * CT + c;
        float g00 = 1.f / (1.f + __expf(-gate[i00]));
        float g01 = 1.f / (1.f + __expf(-gate[i00 + 1]));
        float g10 = 1.f / (1.f + __expf(-gate[i10]));
        float g11 = 1.f / (1.f + __expf(-gate[i10 + 1]));
        o[i00]     = g00 * oacc[nt][0] * inv0;
        o[i00 + 1] = g01 * oacc[nt][1] * inv0;
        o[i10]     = g10 * oacc[nt][2] * inv1;
        o[i10 + 1] = g11 * oacc[nt][3] * inv1;
    }
}

// ---------------- launch ----------------
static float* symaddr(const void* sym) {
    void* p = nullptr;
    cudaGetSymbolAddress(&p, sym);
    return (float*)p;
}

extern "C" void kernel_launch(void* const* d_in, const int* in_sizes, int n_in,
                              void* d_out, int out_size) {
    const float* a    = (const float*)d_in[0];
    const float* s    = (const float*)d_in[1];
    const float* z    = (const float*)d_in[2];
    const float* bm   = (const float*)d_in[3];
    const float* Wg   = (const float*)d_in[4];
    const float* bg   = (const float*)d_in[5];
    const float* Wb   = (const float*)d_in[6];
    const float* Wq   = (const float*)d_in[7];
    const float* bq   = (const float*)d_in[8];
    const float* Wk   = (const float*)d_in[9];
    const float* Wv   = (const float*)d_in[10];
    const float* Wpb  = (const float*)d_in[11];
    const float* png  = (const float*)d_in[12];
    const float* pnb  = (const float*)d_in[13];
    const float* Wgt  = (const float*)d_in[14];
    const float* Wout = (const float*)d_in[15];
    const float* Wog  = (const float*)d_in[16];
    const float* bog  = (const float*)d_in[17];
    float* out = (float*)d_out;

    float* aln   = symaddr(g_aln);
    float* sln   = symaddr(g_sln);
    float* tmpb  = symaddr(g_tmpb);
    float* anorm = symaddr(g_anorm);
    float* qb    = symaddr(g_q);
    float* kb    = symaddr(g_k);
    float* vb    = symaddr(g_v);
    float* gateb = symaddr(g_gate);
    float* ogb   = symaddr(g_og);
    float* ob    = symaddr(g_o);
    float* pbb   = symaddr(g_pb);

    cudaFuncSetAttribute(pair_kernel, cudaFuncAttributeMaxDynamicSharedMemorySize, PAIR_SMEM);
    cudaFuncSetAttribute(attn_kernel, cudaFuncAttributeMaxDynamicSharedMemorySize, ATTN_SMEM);

    // fused LayerNorms
    ln2_kernel<<<dim3(ROWS, 2), 256>>>(a, s, aln, sln);

    // batch 1: adaLN gate (sigmoid), adaLN bias-proj, output-gate (sigmoid) — all K=384, independent
    {
        GemmBatchArgs p = {};
        p.j[0] = { sln, Wb,  tmpb,  nullptr, nullptr, nullptr, CS, 0 };
        p.j[1] = { sln, Wg,  anorm, bg,      nullptr, nullptr, CS, 1 };   // gsig
        p.j[2] = { s,   Wog, ogb,   bog,     nullptr, nullptr, CS, 1 };
        gemm_batch_kernel<128><<<dim3(CT / 64, ROWS / 128, 3), 256>>>(p, ROWS, CT);
    }
    // anorm = gsig * aln + tmpb
    combine_kernel<<<ROWS * CT / 4 / 256, 256>>>(anorm, aln, tmpb);

    // batch 2: Q/K/V/gate — shared A, K=768
    {
        GemmBatchArgs p = {};
        p.j[0] = { anorm, Wq,  qb,    bq,      nullptr, nullptr, CT, 0 };
        p.j[1] = { anorm, Wk,  kb,    nullptr, nullptr, nullptr, CT, 0 };
        p.j[2] = { anorm, Wv,  vb,    nullptr, nullptr, nullptr, CT, 0 };
        p.j[3] = { anorm, Wgt, gateb, nullptr, nullptr, nullptr, CT, 0 };
        gemm_batch_kernel<128><<<dim3(CT / 64, ROWS / 128, 4), 256>>>(p, ROWS, CT);
    }

    // pair bias (incl. bias_mask)
    pair_kernel<<<dim3(NN / PJT, ROWS), 256, PAIR_SMEM>>>(z, bm, Wpb, png, pnb, pbb);
    // attention + gating
    attn_kernel<<<dim3(NN / 64, NH, BB), 256, ATTN_SMEM>>>(qb, kb, vb, gateb, pbb, ob);

    // output projection with output-gate multiply — BM=64 for 288 CTAs
    {
        GemmBatchArgs p = {};
        p.j[0] = { ob, Wout, out, nullptr, ogb, nullptr, CT, 0 };
        gemm_batch_kernel<64><<<dim3(CT / 64, ROWS / 64, 1), 256>>>(p, ROWS, CT);
    }
}

// round 10
// speedup vs baseline: 2.7748x; 1.1693x over previous
#include <cuda_runtime.h>
#include <math.h>

#define BB 2
#define NN 768
#define CT 768
#define CS 384
#define CP 128
#define NH 16
#define HD 48
#define ROWS (BB*NN)   /* 1536 */

// ---------------- scratch (device globals; no allocation allowed) ----------------
__device__ float g_aln  [ROWS*CT];
__device__ float g_sln  [ROWS*CS];
__device__ float g_tmpb [ROWS*CT];
__device__ float g_anorm[ROWS*CT];
__device__ float g_q    [ROWS*CT];
__device__ float g_k    [ROWS*CT];
__device__ float g_v    [ROWS*CT];
__device__ float g_gate [ROWS*CT];
__device__ float g_og   [ROWS*CT];
__device__ float g_o    [ROWS*CT];
__device__ float g_pb   [BB*NH*NN*NN];   // 75.5 MB pair bias [b,h,i,j]

// ---------------- tf32 / mma / ldmatrix helpers ----------------
__device__ __forceinline__ unsigned f2tf(float f) {
    unsigned u;
    asm("cvt.rna.tf32.f32 %0, %1;" : "=r"(u) : "f"(f));
    return u;
}
__device__ __forceinline__ void mma_tf32(float* c, const unsigned* a, unsigned b0, unsigned b1) {
    asm volatile(
        "mma.sync.aligned.m16n8k8.row.col.f32.tf32.tf32.f32 "
        "{%0,%1,%2,%3}, {%4,%5,%6,%7}, {%8,%9}, {%0,%1,%2,%3};\n"
        : "+f"(c[0]), "+f"(c[1]), "+f"(c[2]), "+f"(c[3])
        : "r"(a[0]), "r"(a[1]), "r"(a[2]), "r"(a[3]), "r"(b0), "r"(b1));
}
__device__ __forceinline__ unsigned smem_u32(const void* p) {
    return (unsigned)__cvta_generic_to_shared(p);
}
__device__ __forceinline__ void ldsm_x4(unsigned* r, unsigned a) {
    asm volatile("ldmatrix.sync.aligned.m8n8.x4.shared.b16 {%0,%1,%2,%3}, [%4];"
        : "=r"(r[0]), "=r"(r[1]), "=r"(r[2]), "=r"(r[3]) : "r"(a));
}
__device__ __forceinline__ void ldsm_x2(unsigned& r0, unsigned& r1, unsigned a) {
    asm volatile("ldmatrix.sync.aligned.m8n8.x2.shared.b16 {%0,%1}, [%2];"
        : "=r"(r0), "=r"(r1) : "r"(a));
}

// ---------------- fused LayerNorms (no affine) ----------------
__device__ __forceinline__ float2 blockReduce2(float a, float b) {
    #pragma unroll
    for (int o = 16; o; o >>= 1) {
        a += __shfl_xor_sync(0xffffffffu, a, o);
        b += __shfl_xor_sync(0xffffffffu, b, o);
    }
    __shared__ float sa[8], sb[8];
    int w = threadIdx.x >> 5, l = threadIdx.x & 31;
    if (l == 0) { sa[w] = a; sb[w] = b; }
    __syncthreads();
    if (w == 0) {
        a = (l < 8) ? sa[l] : 0.f;
        b = (l < 8) ? sb[l] : 0.f;
        #pragma unroll
        for (int o = 4; o; o >>= 1) {
            a += __shfl_xor_sync(0xffffffffu, a, o);
            b += __shfl_xor_sync(0xffffffffu, b, o);
        }
        if (l == 0) { sa[0] = a; sb[0] = b; }
    }
    __syncthreads();
    return make_float2(sa[0], sb[0]);
}

__global__ void __launch_bounds__(256) ln2_kernel(
    const float* __restrict__ a, const float* __restrict__ s,
    float* __restrict__ aout, float* __restrict__ sout)
{
    int C = (blockIdx.y == 0) ? CT : CS;
    const float* in = (blockIdx.y == 0) ? a : s;
    float* out = (blockIdx.y == 0) ? aout : sout;
    int r = blockIdx.x;
    const float* x = in + (size_t)r * C;
    float sm = 0.f, sq = 0.f;
    for (int c = threadIdx.x; c < C; c += 256) { float v = x[c]; sm += v; sq += v * v; }
    float2 red = blockReduce2(sm, sq);
    float mean = red.x / C;
    float inv = rsqrtf(red.y / C - mean * mean + 1e-5f);
    float* y = out + (size_t)r * C;
    for (int c = threadIdx.x; c < C; c += 256) y[c] = (x[c] - mean) * inv;
}

// ---------------- GEMM jobs ----------------
struct GemmJob {
    const float* A; const float* B; float* C;
    const float* bias; const float* mul; const float* add;
    int K; int sig;
};
struct GemmBatchArgs { GemmJob j[4]; };

// ============ NEW: 128x128x16 tf32 GEMM with ldmatrix A-frags ============
// 256 threads = 8 warps in 2(m) x 4(n); warp tile 64m x 32n (MT=4, NT=4)
#define AST 20    /* As row stride (words); 5 16B-groups -> conflict-free ldsm */
#define BST 136   /* Bs row stride (words) */

__global__ void __launch_bounds__(256, 2) gemm128_kernel(GemmBatchArgs p, int M, int N) {
    const GemmJob jb = p.j[blockIdx.z];
    const float* __restrict__ A = jb.A;
    const float* __restrict__ B = jb.B;
    const int K = jb.K;

    __shared__ unsigned As[128 * AST];   // [m][k] tf32
    __shared__ unsigned Bs[16 * BST];    // [k][n] tf32

    int t = threadIdx.x, w = t >> 5, lane = t & 31;
    int gid = lane >> 2, tig = lane & 3;
    int wm = w >> 2, wn = w & 3;
    int m0 = blockIdx.y * 128, n0 = blockIdx.x * 128;
    int mw = wm * 64, nw = wn * 32;

    float acc[4][4][4];
    #pragma unroll
    for (int mt = 0; mt < 4; mt++)
        #pragma unroll
        for (int nt = 0; nt < 4; nt++)
            #pragma unroll
            for (int r = 0; r < 4; r++) acc[mt][nt][r] = 0.f;

    int arow[2], akq[2], brow[2], bc4[2];
    #pragma unroll
    for (int i = 0; i < 2; i++) {
        int idx = t + i * 256;
        arow[i] = idx >> 2; akq[i] = idx & 3;     // A: 128 rows x 4 float4 (16 k)
        brow[i] = idx >> 5; bc4[i] = idx & 31;    // B: 16 k-rows x 32 float4 (128 n)
    }

    float4 ar[2], br[2];
    #pragma unroll
    for (int i = 0; i < 2; i++) {
        ar[i] = *(const float4*)(A + (size_t)(m0 + arow[i]) * K + akq[i] * 4);
        br[i] = *(const float4*)(B + (size_t)brow[i] * N + n0 + bc4[i] * 4);
    }

    unsigned aBase = smem_u32(As);
    int lrow = lane & 15, lkq = lane >> 4;
    unsigned a_addr[4];
    #pragma unroll
    for (int mt = 0; mt < 4; mt++)
        a_addr[mt] = aBase + (unsigned)(((mw + mt * 16 + lrow) * AST + lkq * 4) * 4);

    int nchunk = K / 16;
    for (int ch = 0; ch < nchunk; ch++) {
        #pragma unroll
        for (int i = 0; i < 2; i++) {
            uint4 av = make_uint4(f2tf(ar[i].x), f2tf(ar[i].y), f2tf(ar[i].z), f2tf(ar[i].w));
            *(uint4*)&As[arow[i] * AST + akq[i] * 4] = av;
            uint4 bv = make_uint4(f2tf(br[i].x), f2tf(br[i].y), f2tf(br[i].z), f2tf(br[i].w));
            *(uint4*)&Bs[brow[i] * BST + bc4[i] * 4] = bv;
        }
        __syncthreads();
        if (ch + 1 < nchunk) {
            int k0 = (ch + 1) * 16;
            #pragma unroll
            for (int i = 0; i < 2; i++) {
                ar[i] = *(const float4*)(A + (size_t)(m0 + arow[i]) * K + k0 + akq[i] * 4);
                br[i] = *(const float4*)(B + (size_t)(k0 + brow[i]) * N + n0 + bc4[i] * 4);
            }
        }
        #pragma unroll
        for (int ks = 0; ks < 2; ks++) {
            int kb = ks * 8;
            unsigned af[4][4];
            #pragma unroll
            for (int mt = 0; mt < 4; mt++) ldsm_x4(af[mt], a_addr[mt] + kb * 4);
            unsigned bf[4][2];
            #pragma unroll
            for (int nt = 0; nt < 4; nt++) {
                bf[nt][0] = Bs[(kb + tig) * BST + nw + nt * 8 + gid];
                bf[nt][1] = Bs[(kb + tig + 4) * BST + nw + nt * 8 + gid];
            }
            #pragma unroll
            for (int mt = 0; mt < 4; mt++)
                #pragma unroll
                for (int nt = 0; nt < 4; nt++)
                    mma_tf32(acc[mt][nt], af[mt], bf[nt][0], bf[nt][1]);
        }
        __syncthreads();
    }

    // epilogue
    const float* bias = jb.bias;
    const float* mul = jb.mul;
    const float* add = jb.add;
    int do_sig = jb.sig;
    float* C = jb.C;
    #pragma unroll
    for (int mt = 0; mt < 4; mt++) {
        #pragma unroll
        for (int nt = 0; nt < 4; nt++) {
            int r0 = m0 + mw + mt * 16 + gid;
            int c0 = n0 + nw + nt * 8 + 2 * tig;
            #pragma unroll
            for (int rr = 0; rr < 2; rr++) {
                int r = r0 + rr * 8;
                #pragma unroll
                for (int cc = 0; cc < 2; cc++) {
                    float v = acc[mt][nt][rr * 2 + cc];
                    int c = c0 + cc;
                    if (bias) v += bias[c];
                    if (do_sig) v = 1.f / (1.f + __expf(-v));
                    size_t ix = (size_t)r * N + c;
                    if (mul) v *= mul[ix];
                    if (add) v += add[ix];
                    C[ix] = v;
                }
            }
        }
    }
}

// ============ OLD 64x64 kernel kept for Wout (needs 288 CTAs) ============
template <int BM>
__global__ void __launch_bounds__(256, 2) gemm_batch_kernel(GemmBatchArgs p, int M, int N) {
    const GemmJob jb = p.j[blockIdx.z];
    const float* __restrict__ A = jb.A;
    const float* __restrict__ B = jb.B;
    const int K = jb.K;
    constexpr int MT = BM / 64;
    constexpr int NLD = BM / 32;

    __shared__ unsigned As[32][BM + 8];
    __shared__ unsigned Bs[32][72];
    int t = threadIdx.x;
    int w = t >> 5, lane = t & 31;
    int gid = lane >> 2, tig = lane & 3;
    int wm = w >> 1, wn = w & 1;
    int m0 = blockIdx.y * BM, n0 = blockIdx.x * 64;
    int mw = wm * (BM / 4), nw = wn * 32;

    float acc[MT][4][4];
    #pragma unroll
    for (int mt = 0; mt < MT; mt++)
        #pragma unroll
        for (int nt = 0; nt < 4; nt++)
            #pragma unroll
            for (int r = 0; r < 4; r++) acc[mt][nt][r] = 0.f;

    int arow[NLD], akb[NLD], brow[2], bc4[2];
    #pragma unroll
    for (int i = 0; i < NLD; i++) { int idx = t + i * 256; arow[i] = idx & (BM - 1); akb[i] = idx / BM; }
    #pragma unroll
    for (int i = 0; i < 2; i++) { int idx = t + i * 256; brow[i] = idx >> 4; bc4[i] = idx & 15; }

    float4 ar[NLD], br[2];
    #pragma unroll
    for (int i = 0; i < NLD; i++)
        ar[i] = *(const float4*)(A + (size_t)(m0 + arow[i]) * K + akb[i] * 4);
    #pragma unroll
    for (int i = 0; i < 2; i++)
        br[i] = *(const float4*)(B + (size_t)brow[i] * N + n0 + bc4[i] * 4);

    int nchunk = K / 32;
    for (int ch = 0; ch < nchunk; ch++) {
        #pragma unroll
        for (int i = 0; i < NLD; i++) {
            As[akb[i] * 4 + 0][arow[i]] = f2tf(ar[i].x);
            As[akb[i] * 4 + 1][arow[i]] = f2tf(ar[i].y);
            As[akb[i] * 4 + 2][arow[i]] = f2tf(ar[i].z);
            As[akb[i] * 4 + 3][arow[i]] = f2tf(ar[i].w);
        }
        #pragma unroll
        for (int i = 0; i < 2; i++) {
            Bs[brow[i]][bc4[i] * 4 + 0] = f2tf(br[i].x);
            Bs[brow[i]][bc4[i] * 4 + 1] = f2tf(br[i].y);
            Bs[brow[i]][bc4[i] * 4 + 2] = f2tf(br[i].z);
            Bs[brow[i]][bc4[i] * 4 + 3] = f2tf(br[i].w);
        }
        __syncthreads();
        if (ch + 1 < nchunk) {
            int k0 = (ch + 1) * 32;
            #pragma unroll
            for (int i = 0; i < NLD; i++)
                ar[i] = *(const float4*)(A + (size_t)(m0 + arow[i]) * K + k0 + akb[i] * 4);
            #pragma unroll
            for (int i = 0; i < 2; i++)
                br[i] = *(const float4*)(B + (size_t)(k0 + brow[i]) * N + n0 + bc4[i] * 4);
        }
        #pragma unroll
        for (int ks = 0; ks < 4; ks++) {
            int kb = ks * 8;
            unsigned af[MT][4];
            #pragma unroll
            for (int mt = 0; mt < MT; mt++) {
                int mb = mw + mt * 16 + gid;
                af[mt][0] = As[kb + tig][mb];
                af[mt][1] = As[kb + tig][mb + 8];
                af[mt][2] = As[kb + tig + 4][mb];
                af[mt][3] = As[kb + tig + 4][mb + 8];
            }
            unsigned bf[4][2];
            #pragma unroll
            for (int nt = 0; nt < 4; nt++) {
                int nb = nw + nt * 8 + gid;
                bf[nt][0] = Bs[kb + tig][nb];
                bf[nt][1] = Bs[kb + tig + 4][nb];
            }
            #pragma unroll
            for (int mt = 0; mt < MT; mt++)
                #pragma unroll
                for (int nt = 0; nt < 4; nt++)
                    mma_tf32(acc[mt][nt], af[mt], bf[nt][0], bf[nt][1]);
        }
        __syncthreads();
    }

    const float* bias = jb.bias;
    const float* mul = jb.mul;
    const float* add = jb.add;
    int do_sig = jb.sig;
    float* C = jb.C;
    #pragma unroll
    for (int mt = 0; mt < MT; mt++) {
        #pragma unroll
        for (int nt = 0; nt < 4; nt++) {
            int r0 = m0 + mw + mt * 16 + gid;
            int c0 = n0 + nw + nt * 8 + 2 * tig;
            #pragma unroll
            for (int rr = 0; rr < 2; rr++) {
                int r = r0 + rr * 8;
                #pragma unroll
                for (int cc = 0; cc < 2; cc++) {
                    float v = acc[mt][nt][rr * 2 + cc];
                    int c = c0 + cc;
                    if (bias) v += bias[c];
                    if (do_sig) v = 1.f / (1.f + __expf(-v));
                    size_t ix = (size_t)r * N + c;
                    if (mul) v *= mul[ix];
                    if (add) v += add[ix];
                    C[ix] = v;
                }
            }
        }
    }
}

// ---------------- elementwise adaLN combine: anorm = gsig*aln + tmpb ----------------
__global__ void __launch_bounds__(256) combine_kernel(
    float* __restrict__ anorm, const float* __restrict__ aln, const float* __restrict__ tmpb)
{
    int i = blockIdx.x * 256 + threadIdx.x;
    float4 g = ((const float4*)anorm)[i];
    float4 a = ((const float4*)aln)[i];
    float4 tb = ((const float4*)tmpb)[i];
    g.x = g.x * a.x + tb.x;
    g.y = g.y * a.y + tb.y;
    g.z = g.z * a.z + tb.z;
    g.w = g.w * a.w + tb.w;
    ((float4*)anorm)[i] = g;
}

// ---------------- pair bias: LN(z)*gamma+beta @ Wpb + bias_mask -> g_pb[b,h,i,j] ----------------
#define PJT 128
#define ZST 132
#define WST 24
#define PAIR_SMEM ((PJT*ZST + CP*WST + PJT + CP + CP) * 4)

__global__ void __launch_bounds__(256, 2) pair_kernel(
    const float* __restrict__ z, const float* __restrict__ bmask,
    const float* __restrict__ Wpb, const float* __restrict__ gma,
    const float* __restrict__ bta, float* __restrict__ pb)
{
    extern __shared__ float smp[];
    float* zn = smp;                                  // [128][132]
    unsigned* Wb = (unsigned*)(smp + PJT * ZST);      // [128][24]
    float* bm_s = smp + PJT * ZST + CP * WST;         // [128]
    float* g_s = bm_s + PJT;
    float* b_s = g_s + CP;

    int t = threadIdx.x;
    int w = t >> 5, lane = t & 31;
    int gid = lane >> 2, tig = lane & 3;
    int bi = blockIdx.y;
    int b = bi / NN, i = bi % NN;
    int j0 = blockIdx.x * PJT;

    const float* zrow = z + ((size_t)bi * NN + j0) * CP;
    #pragma unroll
    for (int it = 0; it < 16; it++) {
        int idx = t + it * 256;
        int r = idx >> 5, c4 = idx & 31;
        float4 v = *(const float4*)(zrow + (size_t)r * CP + c4 * 4);
        *(float4*)(zn + r * ZST + c4 * 4) = v;
    }
    for (int idx = t; idx < CP * NH; idx += 256) {
        int c = idx >> 4, hh = idx & 15;
        Wb[c * WST + hh] = f2tf(Wpb[idx]);
    }
    if (t < PJT) bm_s[t] = bmask[(size_t)bi * NN + j0 + t];
    if (t < CP) { g_s[t] = gma[t]; b_s[t] = bta[t]; }
    __syncthreads();

    #pragma unroll 2
    for (int rr = 0; rr < 16; rr++) {
        int r = w * 16 + rr;
        float v0 = zn[r * ZST + lane];
        float v1 = zn[r * ZST + lane + 32];
        float v2 = zn[r * ZST + lane + 64];
        float v3 = zn[r * ZST + lane + 96];
        float s = v0 + v1 + v2 + v3;
        float sq = v0 * v0 + v1 * v1 + v2 * v2 + v3 * v3;
        #pragma unroll
        for (int o = 16; o; o >>= 1) {
            s  += __shfl_xor_sync(0xffffffffu, s, o);
            sq += __shfl_xor_sync(0xffffffffu, sq, o);
        }
        float mean = s * (1.f / CP);
        float inv = rsqrtf(sq * (1.f / CP) - mean * mean + 1e-5f);
        zn[r * ZST + lane]      = __uint_as_float(f2tf((v0 - mean) * inv * g_s[lane]      + b_s[lane]));
        zn[r * ZST + lane + 32] = __uint_as_float(f2tf((v1 - mean) * inv * g_s[lane + 32] + b_s[lane + 32]));
        zn[r * ZST + lane + 64] = __uint_as_float(f2tf((v2 - mean) * inv * g_s[lane + 64] + b_s[lane + 64]));
        zn[r * ZST + lane + 96] = __uint_as_float(f2tf((v3 - mean) * inv * g_s[lane + 96] + b_s[lane + 96]));
    }
    __syncthreads();

    int mb = w * 16;
    unsigned zBase = smem_u32(zn);
    int lrow = lane & 15, lkq = lane >> 4;
    unsigned z_addr = zBase + (unsigned)(((mb + lrow) * ZST + lkq * 4) * 4);
    float c2[2][4];
    #pragma unroll
    for (int nt = 0; nt < 2; nt++)
        #pragma unroll
        for (int r = 0; r < 4; r++) c2[nt][r] = 0.f;
    #pragma unroll
    for (int ks = 0; ks < 16; ks++) {
        int kb = ks * 8;
        unsigned af[4];
        ldsm_x4(af, z_addr + kb * 4);
        #pragma unroll
        for (int nt = 0; nt < 2; nt++) {
            unsigned b0 = Wb[(kb + tig) * WST + nt * 8 + gid];
            unsigned b1 = Wb[(kb + tig + 4) * WST + nt * 8 + gid];
            mma_tf32(c2[nt], af, b0, b1);
        }
    }
    float bm0 = bm_s[mb + gid], bm1 = bm_s[mb + gid + 8];
    int jg0 = j0 + mb + gid;
    #pragma unroll
    for (int nt = 0; nt < 2; nt++) {
        int h0 = nt * 8 + 2 * tig;
        size_t base0 = ((size_t)(b * NH + h0) * NN + i) * NN;
        size_t base1 = ((size_t)(b * NH + h0 + 1) * NN + i) * NN;
        pb[base0 + jg0]     = c2[nt][0] + bm0;
        pb[base1 + jg0]     = c2[nt][1] + bm0;
        pb[base0 + jg0 + 8] = c2[nt][2] + bm1;
        pb[base1 + jg0 + 8] = c2[nt][3] + bm1;
    }
}

// ---------------- attention: flash-style with tf32 mma + ldmatrix ----------------
#define ATQ 52
#define AVQ 56
#define ATP 68
#define ATTN_SMEM ((2*64*ATQ + 64*AVQ + 64*ATP + 3*64) * 4)

__global__ void __launch_bounds__(256, 3) attn_kernel(
    const float* __restrict__ q, const float* __restrict__ k,
    const float* __restrict__ v, const float* __restrict__ gate,
    const float* __restrict__ pb, float* __restrict__ o)
{
    extern __shared__ float sm[];
    unsigned* Qs = (unsigned*)sm;           // [64][52] tf32
    unsigned* Ks = Qs + 64 * ATQ;           // [64][52] tf32
    unsigned* Vs = Ks + 64 * ATQ;           // [64][56] tf32
    float* Ps = (float*)(Vs + 64 * AVQ);    // [64][68]
    float* Ms = Ps + 64 * ATP;
    float* Ls = Ms + 64;
    float* Ss = Ls + 64;

    int qt = blockIdx.x, hh = blockIdx.y, b = blockIdx.z;
    int t = threadIdx.x;
    int w = t >> 5, lane = t & 31;
    int gid = lane >> 2, tig = lane & 3;
    int q0 = qt * 64;
    const float SC = 0.14433756729740643f;  // 1/sqrt(48)

    for (int idx = t; idx < 64 * HD; idx += 256) {
        int r = idx / HD, d = idx % HD;
        Qs[r * ATQ + d] = f2tf(q[((size_t)(b * NN + q0 + r)) * CT + hh * HD + d] * SC);
    }
    if (t < 64) { Ms[t] = -1e30f; Ls[t] = 0.f; }

    int wmS = w >> 2, wnS = w & 3;
    int mbS = wmS * 32, nbS = wnS * 16;
    int wmP = w >> 1, wnP = w & 1;
    int mbP = wmP * 16, nbP = wnP * 24;

    // ldmatrix addresses
    int lrow = lane & 15, lkq = lane >> 4;
    unsigned qaddr[2];
    #pragma unroll
    for (int mt = 0; mt < 2; mt++)
        qaddr[mt] = smem_u32(Qs) + (unsigned)(((mbS + mt * 16 + lrow) * ATQ + lkq * 4) * 4);
    unsigned kaddr[2];
    #pragma unroll
    for (int nt = 0; nt < 2; nt++)
        kaddr[nt] = smem_u32(Ks) + (unsigned)(((nbS + nt * 8 + (lane & 7)) * ATQ + ((lane >> 3) & 1) * 4) * 4);
    unsigned paddr = smem_u32(Ps) + (unsigned)(((mbP + lrow) * ATP + lkq * 4) * 4);

    float oacc[3][4];
    #pragma unroll
    for (int nt = 0; nt < 3; nt++)
        #pragma unroll
        for (int r = 0; r < 4; r++) oacc[nt][r] = 0.f;

    const float* bp0 = pb + ((size_t)(b * NH + hh) * NN + q0) * NN;

    for (int kt = 0; kt < 12; kt++) {
        int k0 = kt * 64;
        __syncthreads();
        for (int idx = t; idx < 64 * HD; idx += 256) {
            int r = idx / HD, d = idx % HD;
            size_t gi = ((size_t)(b * NN + k0 + r)) * CT + hh * HD + d;
            Ks[r * ATQ + d] = f2tf(k[gi]);
            Vs[r * AVQ + d] = f2tf(v[gi]);
        }
        for (int idx = t; idx < 64 * 16; idx += 256) {
            int r = idx >> 4, c4 = idx & 15;
            float4 bv = *(const float4*)(bp0 + (size_t)r * NN + k0 + c4 * 4);
            *(float4*)(Ps + r * ATP + c4 * 4) = bv;
        }
        __syncthreads();

        // S = Q @ K^T via mma (ldmatrix frags), accumulate into bias tile in Ps
        float sacc[2][2][4];
        #pragma unroll
        for (int mt = 0; mt < 2; mt++)
            #pragma unroll
            for (int nt = 0; nt < 2; nt++)
                #pragma unroll
                for (int r = 0; r < 4; r++) sacc[mt][nt][r] = 0.f;
        #pragma unroll
        for (int ks = 0; ks < 6; ks++) {
            int kb = ks * 8;
            unsigned af[2][4];
            #pragma unroll
            for (int mt = 0; mt < 2; mt++) ldsm_x4(af[mt], qaddr[mt] + kb * 4);
            #pragma unroll
            for (int nt = 0; nt < 2; nt++) {
                unsigned b0, b1;
                ldsm_x2(b0, b1, kaddr[nt] + kb * 4);
                #pragma unroll
                for (int mt = 0; mt < 2; mt++)
                    mma_tf32(sacc[mt][nt], af[mt], b0, b1);
            }
        }
        #pragma unroll
        for (int mt = 0; mt < 2; mt++) {
            #pragma unroll
            for (int nt = 0; nt < 2; nt++) {
                int r = mbS + mt * 16 + gid;
                int c = nbS + nt * 8 + 2 * tig;
                float* p0 = Ps + r * ATP + c;
                float* p1 = Ps + (r + 8) * ATP + c;
                p0[0] += sacc[mt][nt][0];
                p0[1] += sacc[mt][nt][1];
                p1[0] += sacc[mt][nt][2];
                p1[1] += sacc[mt][nt][3];
            }
        }
        __syncthreads();

        // online softmax: 4 lanes per query row, stride-4 interleave; store P as tf32 bits
        {
            int qq = t >> 2, pp = t & 3;
            float* prow = Ps + qq * ATP + pp;
            float tmax = -1e30f;
            #pragma unroll
            for (int jj = 0; jj < 16; jj++) tmax = fmaxf(tmax, prow[jj * 4]);
            tmax = fmaxf(tmax, __shfl_xor_sync(0xffffffffu, tmax, 1));
            tmax = fmaxf(tmax, __shfl_xor_sync(0xffffffffu, tmax, 2));
            float mold = Ms[qq];
            float mnew = fmaxf(mold, tmax);
            float tsum = 0.f;
            #pragma unroll
            for (int jj = 0; jj < 16; jj++) {
                float p = __expf(prow[jj * 4] - mnew);
                tsum += p;
                prow[jj * 4] = __uint_as_float(f2tf(p));
            }
            tsum += __shfl_xor_sync(0xffffffffu, tsum, 1);
            tsum += __shfl_xor_sync(0xffffffffu, tsum, 2);
            if (pp == 0) {
                float scl = __expf(mold - mnew);
                Ss[qq] = scl;
                Ls[qq] = Ls[qq] * scl + tsum;
                Ms[qq] = mnew;
            }
        }
        __syncthreads();

        // rescale + O += P @ V via mma (P frag via ldmatrix)
        {
            float s0 = Ss[mbP + gid], s1 = Ss[mbP + gid + 8];
            #pragma unroll
            for (int nt = 0; nt < 3; nt++) {
                oacc[nt][0] *= s0; oacc[nt][1] *= s0;
                oacc[nt][2] *= s1; oacc[nt][3] *= s1;
            }
            #pragma unroll
            for (int ks = 0; ks < 8; ks++) {
                int kb = ks * 8;
                unsigned af[4];
                ldsm_x4(af, paddr + kb * 4);
                #pragma unroll
                for (int nt = 0; nt < 3; nt++) {
                    unsigned b0 = Vs[(kb + tig) * AVQ + nbP + nt * 8 + gid];
                    unsigned b1 = Vs[(kb + tig + 4) * AVQ + nbP + nt * 8 + gid];
                    mma_tf32(oacc[nt], af, b0, b1);
                }
            }
        }
    }

    // epilogue: normalize, gate, write
    __syncthreads();
    float inv0 = 1.f / Ls[mbP + gid];
    float inv1 = 1.f / Ls[mbP + gid + 8];
    size_t row0 = (size_t)(b * NN + q0 + mbP + gid);
    size_t row1 = row0 + 8;
    #pragma unroll
    for (int nt = 0; nt < 3; nt++) {
        int c = hh * HD + nbP + nt * 8 + 2 * tig;
        size_t i00 = row0 * CT + c;
        size_t i10 = row1 * CT + c;
        float g00 = 1.f / (1.f + __expf(-gate[i00]));
        float g01 = 1.f / (1.f + __expf(-gate[i00 + 1]));
        float g10 = 1.f / (1.f + __expf(-gate[i10]));
        float g11 = 1.f / (1.f + __expf(-gate[i10 + 1]));
        o[i00]     = g00 * oacc[nt][0] * inv0;
        o[i00 + 1] = g01 * oacc[nt][1] * inv0;
        o[i10]     = g10 * oacc[nt][2] * inv1;
        o[i10 + 1] = g11 * oacc[nt][3] * inv1;
    }
}

// ---------------- launch ----------------
static float* symaddr(const void* sym) {
    void* p = nullptr;
    cudaGetSymbolAddress(&p, sym);
    return (float*)p;
}

extern "C" void kernel_launch(void* const* d_in, const int* in_sizes, int n_in,
                              void* d_out, int out_size) {
    const float* a    = (const float*)d_in[0];
    const float* s    = (const float*)d_in[1];
    const float* z    = (const float*)d_in[2];
    const float* bm   = (const float*)d_in[3];
    const float* Wg   = (const float*)d_in[4];
    const float* bg   = (const float*)d_in[5];
    const float* Wb   = (const float*)d_in[6];
    const float* Wq   = (const float*)d_in[7];
    const float* bq   = (const float*)d_in[8];
    const float* Wk   = (const float*)d_in[9];
    const float* Wv   = (const float*)d_in[10];
    const float* Wpb  = (const float*)d_in[11];
    const float* png  = (const float*)d_in[12];
    const float* pnb  = (const float*)d_in[13];
    const float* Wgt  = (const float*)d_in[14];
    const float* Wout = (const float*)d_in[15];
    const float* Wog  = (const float*)d_in[16];
    const float* bog  = (const float*)d_in[17];
    float* out = (float*)d_out;

    float* aln   = symaddr(g_aln);
    float* sln   = symaddr(g_sln);
    float* tmpb  = symaddr(g_tmpb);
    float* anorm = symaddr(g_anorm);
    float* qb    = symaddr(g_q);
    float* kb    = symaddr(g_k);
    float* vb    = symaddr(g_v);
    float* gateb = symaddr(g_gate);
    float* ogb   = symaddr(g_og);
    float* ob    = symaddr(g_o);
    float* pbb   = symaddr(g_pb);

    cudaFuncSetAttribute(pair_kernel, cudaFuncAttributeMaxDynamicSharedMemorySize, PAIR_SMEM);
    cudaFuncSetAttribute(attn_kernel, cudaFuncAttributeMaxDynamicSharedMemorySize, ATTN_SMEM);

    // fused LayerNorms
    ln2_kernel<<<dim3(ROWS, 2), 256>>>(a, s, aln, sln);

    // batch 1: adaLN gate (sigmoid), adaLN bias-proj, output-gate (sigmoid) — K=384
    {
        GemmBatchArgs p = {};
        p.j[0] = { sln, Wb,  tmpb,  nullptr, nullptr, nullptr, CS, 0 };
        p.j[1] = { sln, Wg,  anorm, bg,      nullptr, nullptr, CS, 1 };   // gsig
        p.j[2] = { s,   Wog, ogb,   bog,     nullptr, nullptr, CS, 1 };
        gemm128_kernel<<<dim3(CT / 128, ROWS / 128, 3), 256>>>(p, ROWS, CT);
    }
    // anorm = gsig * aln + tmpb
    combine_kernel<<<ROWS * CT / 4 / 256, 256>>>(anorm, aln, tmpb);

    // batch 2: Q/K/V/gate — shared A, K=768
    {
        GemmBatchArgs p = {};
        p.j[0] = { anorm, Wq,  qb,    bq,      nullptr, nullptr, CT, 0 };
        p.j[1] = { anorm, Wk,  kb,    nullptr, nullptr, nullptr, CT, 0 };
        p.j[2] = { anorm, Wv,  vb,    nullptr, nullptr, nullptr, CT, 0 };
        p.j[3] = { anorm, Wgt, gateb, nullptr, nullptr, nullptr, CT, 0 };
        gemm128_kernel<<<dim3(CT / 128, ROWS / 128, 4), 256>>>(p, ROWS, CT);
    }

    // pair bias (incl. bias_mask)
    pair_kernel<<<dim3(NN / PJT, ROWS), 256, PAIR_SMEM>>>(z, bm, Wpb, png, pnb, pbb);
    // attention + gating
    attn_kernel<<<dim3(NN / 64, NH, BB), 256, ATTN_SMEM>>>(qb, kb, vb, gateb, pbb, ob);

    // output projection with output-gate multiply — BM=64 for 288 CTAs
    {
        GemmBatchArgs p = {};
        p.j[0] = { ob, Wout, out, nullptr, ogb, nullptr, CT, 0 };
        gemm_batch_kernel<64><<<dim3(CT / 64, ROWS / 64, 1), 256>>>(p, ROWS, CT);
    }
}

// round 12
// speedup vs baseline: 3.1790x; 1.1457x over previous
#include <cuda_runtime.h>
#include <math.h>

#define BB 2
#define NN 768
#define CT 768
#define CS 384
#define CP 128
#define NH 16
#define HD 48
#define ROWS (BB*NN)   /* 1536 */

// ---------------- scratch (device globals; no allocation allowed) ----------------
__device__ float g_aln  [ROWS*CT];
__device__ float g_sln  [ROWS*CS];
__device__ float g_tmpb [ROWS*CT];
__device__ float g_anorm[ROWS*CT];
__device__ float g_q    [ROWS*CT];
__device__ float g_k    [ROWS*CT];
__device__ float g_v    [ROWS*CT];
__device__ float g_gate [ROWS*CT];
__device__ float g_og   [ROWS*CT];
__device__ float g_o    [ROWS*CT];
__device__ float g_pb   [BB*NH*NN*NN];   // 75.5 MB pair bias [b,h,i,j]

// ---------------- tf32 / mma / ldmatrix helpers ----------------
__device__ __forceinline__ unsigned f2tf(float f) {
    unsigned u;
    asm("cvt.rna.tf32.f32 %0, %1;" : "=r"(u) : "f"(f));
    return u;
}
__device__ __forceinline__ void mma_tf32(float* c, const unsigned* a, unsigned b0, unsigned b1) {
    asm volatile(
        "mma.sync.aligned.m16n8k8.row.col.f32.tf32.tf32.f32 "
        "{%0,%1,%2,%3}, {%4,%5,%6,%7}, {%8,%9}, {%0,%1,%2,%3};\n"
        : "+f"(c[0]), "+f"(c[1]), "+f"(c[2]), "+f"(c[3])
        : "r"(a[0]), "r"(a[1]), "r"(a[2]), "r"(a[3]), "r"(b0), "r"(b1));
}
__device__ __forceinline__ unsigned smem_u32(const void* p) {
    return (unsigned)__cvta_generic_to_shared(p);
}
__device__ __forceinline__ void ldsm_x4(unsigned* r, unsigned a) {
    asm volatile("ldmatrix.sync.aligned.m8n8.x4.shared.b16 {%0,%1,%2,%3}, [%4];"
        : "=r"(r[0]), "=r"(r[1]), "=r"(r[2]), "=r"(r[3]) : "r"(a));
}
__device__ __forceinline__ void ldsm_x2(unsigned& r0, unsigned& r1, unsigned a) {
    asm volatile("ldmatrix.sync.aligned.m8n8.x2.shared.b16 {%0,%1}, [%2];"
        : "=r"(r0), "=r"(r1) : "r"(a));
}

// ---------------- fused LayerNorms (no affine) ----------------
__device__ __forceinline__ float2 blockReduce2(float a, float b) {
    #pragma unroll
    for (int o = 16; o; o >>= 1) {
        a += __shfl_xor_sync(0xffffffffu, a, o);
        b += __shfl_xor_sync(0xffffffffu, b, o);
    }
    __shared__ float sa[8], sb[8];
    int w = threadIdx.x >> 5, l = threadIdx.x & 31;
    if (l == 0) { sa[w] = a; sb[w] = b; }
    __syncthreads();
    if (w == 0) {
        a = (l < 8) ? sa[l] : 0.f;
        b = (l < 8) ? sb[l] : 0.f;
        #pragma unroll
        for (int o = 4; o; o >>= 1) {
            a += __shfl_xor_sync(0xffffffffu, a, o);
            b += __shfl_xor_sync(0xffffffffu, b, o);
        }
        if (l == 0) { sa[0] = a; sb[0] = b; }
    }
    __syncthreads();
    return make_float2(sa[0], sb[0]);
}

__global__ void __launch_bounds__(256) ln2_kernel(
    const float* __restrict__ a, const float* __restrict__ s,
    float* __restrict__ aout, float* __restrict__ sout)
{
    int C = (blockIdx.y == 0) ? CT : CS;
    const float* in = (blockIdx.y == 0) ? a : s;
    float* out = (blockIdx.y == 0) ? aout : sout;
    int r = blockIdx.x;
    const float* x = in + (size_t)r * C;
    float sm = 0.f, sq = 0.f;
    for (int c = threadIdx.x; c < C; c += 256) { float v = x[c]; sm += v; sq += v * v; }
    float2 red = blockReduce2(sm, sq);
    float mean = red.x / C;
    float inv = rsqrtf(red.y / C - mean * mean + 1e-5f);
    float* y = out + (size_t)r * C;
    for (int c = threadIdx.x; c < C; c += 256) y[c] = (x[c] - mean) * inv;
}

// ---------------- GEMM jobs ----------------
struct GemmJob {
    const float* A; const float* B; float* C;
    const float* bias; const float* mul; const float* add;
    int K; int sig;
};
struct GemmBatchArgs { GemmJob j[4]; };

// ============ 128x128x16 tf32 GEMM, ldmatrix A-frags, double-buffered smem ============
// 256 threads = 8 warps in 2(m) x 4(n); warp tile 64m x 32n (MT=4, NT=4)
#define AST 20    /* As row stride (words); 5 16B-groups -> conflict-free ldsm */
#define BST 136   /* Bs row stride (words) */
#define ABUF (128*AST)
#define BBUF (16*BST)

__global__ void __launch_bounds__(256, 2) gemm128_kernel(GemmBatchArgs p, int M, int N) {
    const GemmJob jb = p.j[blockIdx.z];
    const float* __restrict__ A = jb.A;
    const float* __restrict__ B = jb.B;
    const int K = jb.K;

    __shared__ unsigned As[2 * ABUF];   // [m][k] tf32, double-buffered
    __shared__ unsigned Bs[2 * BBUF];   // [k][n] tf32, double-buffered

    int t = threadIdx.x, w = t >> 5, lane = t & 31;
    int gid = lane >> 2, tig = lane & 3;
    int wm = w >> 2, wn = w & 3;
    int m0 = blockIdx.y * 128, n0 = blockIdx.x * 128;
    int mw = wm * 64, nw = wn * 32;

    float acc[4][4][4];
    #pragma unroll
    for (int mt = 0; mt < 4; mt++)
        #pragma unroll
        for (int nt = 0; nt < 4; nt++)
            #pragma unroll
            for (int r = 0; r < 4; r++) acc[mt][nt][r] = 0.f;

    int arow[2], akq[2], brow[2], bc4[2];
    #pragma unroll
    for (int i = 0; i < 2; i++) {
        int idx = t + i * 256;
        arow[i] = idx >> 2; akq[i] = idx & 3;     // A: 128 rows x 4 float4 (16 k)
        brow[i] = idx >> 5; bc4[i] = idx & 31;    // B: 16 k-rows x 32 float4 (128 n)
    }

    unsigned aBase = smem_u32(As);
    int lrow = lane & 15, lkq = lane >> 4;
    unsigned a_addr[4];
    #pragma unroll
    for (int mt = 0; mt < 4; mt++)
        a_addr[mt] = aBase + (unsigned)(((mw + mt * 16 + lrow) * AST + lkq * 4) * 4);

    // prologue: load + store chunk 0
    float4 ar[2], br[2];
    #pragma unroll
    for (int i = 0; i < 2; i++) {
        ar[i] = *(const float4*)(A + (size_t)(m0 + arow[i]) * K + akq[i] * 4);
        br[i] = *(const float4*)(B + (size_t)brow[i] * N + n0 + bc4[i] * 4);
    }
    #pragma unroll
    for (int i = 0; i < 2; i++) {
        uint4 av = make_uint4(f2tf(ar[i].x), f2tf(ar[i].y), f2tf(ar[i].z), f2tf(ar[i].w));
        *(uint4*)&As[arow[i] * AST + akq[i] * 4] = av;
        uint4 bv = make_uint4(f2tf(br[i].x), f2tf(br[i].y), f2tf(br[i].z), f2tf(br[i].w));
        *(uint4*)&Bs[brow[i] * BST + bc4[i] * 4] = bv;
    }
    __syncthreads();

    int nchunk = K / 16;
    for (int ch = 0; ch < nchunk; ch++) {
        int buf = ch & 1;
        unsigned aOff = buf * (ABUF * 4);
        const unsigned* BsC = Bs + buf * BBUF;

        // issue global loads for next chunk (overlap with mma below)
        bool more = (ch + 1 < nchunk);
        if (more) {
            int k0 = (ch + 1) * 16;
            #pragma unroll
            for (int i = 0; i < 2; i++) {
                ar[i] = *(const float4*)(A + (size_t)(m0 + arow[i]) * K + k0 + akq[i] * 4);
                br[i] = *(const float4*)(B + (size_t)(k0 + brow[i]) * N + n0 + bc4[i] * 4);
            }
        }

        #pragma unroll
        for (int ks = 0; ks < 2; ks++) {
            int kb = ks * 8;
            unsigned af[4][4];
            #pragma unroll
            for (int mt = 0; mt < 4; mt++) ldsm_x4(af[mt], a_addr[mt] + aOff + kb * 4);
            unsigned bf[4][2];
            #pragma unroll
            for (int nt = 0; nt < 4; nt++) {
                bf[nt][0] = BsC[(kb + tig) * BST + nw + nt * 8 + gid];
                bf[nt][1] = BsC[(kb + tig + 4) * BST + nw + nt * 8 + gid];
            }
            #pragma unroll
            for (int mt = 0; mt < 4; mt++)
                #pragma unroll
                for (int nt = 0; nt < 4; nt++)
                    mma_tf32(acc[mt][nt], af[mt], bf[nt][0], bf[nt][1]);
        }

        // store next chunk into the other buffer
        if (more) {
            unsigned* AsN = As + (buf ^ 1) * ABUF;
            unsigned* BsN = Bs + (buf ^ 1) * BBUF;
            #pragma unroll
            for (int i = 0; i < 2; i++) {
                uint4 av = make_uint4(f2tf(ar[i].x), f2tf(ar[i].y), f2tf(ar[i].z), f2tf(ar[i].w));
                *(uint4*)&AsN[arow[i] * AST + akq[i] * 4] = av;
                uint4 bv = make_uint4(f2tf(br[i].x), f2tf(br[i].y), f2tf(br[i].z), f2tf(br[i].w));
                *(uint4*)&BsN[brow[i] * BST + bc4[i] * 4] = bv;
            }
            __syncthreads();
        }
    }

    // epilogue
    const float* bias = jb.bias;
    const float* mul = jb.mul;
    const float* add = jb.add;
    int do_sig = jb.sig;
    float* C = jb.C;
    #pragma unroll
    for (int mt = 0; mt < 4; mt++) {
        #pragma unroll
        for (int nt = 0; nt < 4; nt++) {
            int r0 = m0 + mw + mt * 16 + gid;
            int c0 = n0 + nw + nt * 8 + 2 * tig;
            #pragma unroll
            for (int rr = 0; rr < 2; rr++) {
                int r = r0 + rr * 8;
                #pragma unroll
                for (int cc = 0; cc < 2; cc++) {
                    float v = acc[mt][nt][rr * 2 + cc];
                    int c = c0 + cc;
                    if (bias) v += bias[c];
                    if (do_sig) v = 1.f / (1.f + __expf(-v));
                    size_t ix = (size_t)r * N + c;
                    if (mul) v *= mul[ix];
                    if (add) v += add[ix];
                    C[ix] = v;
                }
            }
        }
    }
}

// ============ 64x64 kernel kept for Wout (needs 288 CTAs) ============
template <int BM>
__global__ void __launch_bounds__(256, 2) gemm_batch_kernel(GemmBatchArgs p, int M, int N) {
    const GemmJob jb = p.j[blockIdx.z];
    const float* __restrict__ A = jb.A;
    const float* __restrict__ B = jb.B;
    const int K = jb.K;
    constexpr int MT = BM / 64;
    constexpr int NLD = BM / 32;

    __shared__ unsigned As[32][BM + 8];
    __shared__ unsigned Bs[32][72];
    int t = threadIdx.x;
    int w = t >> 5, lane = t & 31;
    int gid = lane >> 2, tig = lane & 3;
    int wm = w >> 1, wn = w & 1;
    int m0 = blockIdx.y * BM, n0 = blockIdx.x * 64;
    int mw = wm * (BM / 4), nw = wn * 32;

    float acc[MT][4][4];
    #pragma unroll
    for (int mt = 0; mt < MT; mt++)
        #pragma unroll
        for (int nt = 0; nt < 4; nt++)
            #pragma unroll
            for (int r = 0; r < 4; r++) acc[mt][nt][r] = 0.f;

    int arow[NLD], akb[NLD], brow[2], bc4[2];
    #pragma unroll
    for (int i = 0; i < NLD; i++) { int idx = t + i * 256; arow[i] = idx & (BM - 1); akb[i] = idx / BM; }
    #pragma unroll
    for (int i = 0; i < 2; i++) { int idx = t + i * 256; brow[i] = idx >> 4; bc4[i] = idx & 15; }

    float4 ar[NLD], br[2];
    #pragma unroll
    for (int i = 0; i < NLD; i++)
        ar[i] = *(const float4*)(A + (size_t)(m0 + arow[i]) * K + akb[i] * 4);
    #pragma unroll
    for (int i = 0; i < 2; i++)
        br[i] = *(const float4*)(B + (size_t)brow[i] * N + n0 + bc4[i] * 4);

    int nchunk = K / 32;
    for (int ch = 0; ch < nchunk; ch++) {
        #pragma unroll
        for (int i = 0; i < NLD; i++) {
            As[akb[i] * 4 + 0][arow[i]] = f2tf(ar[i].x);
            As[akb[i] * 4 + 1][arow[i]] = f2tf(ar[i].y);
            As[akb[i] * 4 + 2][arow[i]] = f2tf(ar[i].z);
            As[akb[i] * 4 + 3][arow[i]] = f2tf(ar[i].w);
        }
        #pragma unroll
        for (int i = 0; i < 2; i++) {
            Bs[brow[i]][bc4[i] * 4 + 0] = f2tf(br[i].x);
            Bs[brow[i]][bc4[i] * 4 + 1] = f2tf(br[i].y);
            Bs[brow[i]][bc4[i] * 4 + 2] = f2tf(br[i].z);
            Bs[brow[i]][bc4[i] * 4 + 3] = f2tf(br[i].w);
        }
        __syncthreads();
        if (ch + 1 < nchunk) {
            int k0 = (ch + 1) * 32;
            #pragma unroll
            for (int i = 0; i < NLD; i++)
                ar[i] = *(const float4*)(A + (size_t)(m0 + arow[i]) * K + k0 + akb[i] * 4);
            #pragma unroll
            for (int i = 0; i < 2; i++)
                br[i] = *(const float4*)(B + (size_t)(k0 + brow[i]) * N + n0 + bc4[i] * 4);
        }
        #pragma unroll
        for (int ks = 0; ks < 4; ks++) {
            int kb = ks * 8;
            unsigned af[MT][4];
            #pragma unroll
            for (int mt = 0; mt < MT; mt++) {
                int mb = mw + mt * 16 + gid;
                af[mt][0] = As[kb + tig][mb];
                af[mt][1] = As[kb + tig][mb + 8];
                af[mt][2] = As[kb + tig + 4][mb];
                af[mt][3] = As[kb + tig + 4][mb + 8];
            }
            unsigned bf[4][2];
            #pragma unroll
            for (int nt = 0; nt < 4; nt++) {
                int nb = nw + nt * 8 + gid;
                bf[nt][0] = Bs[kb + tig][nb];
                bf[nt][1] = Bs[kb + tig + 4][nb];
            }
            #pragma unroll
            for (int mt = 0; mt < MT; mt++)
                #pragma unroll
                for (int nt = 0; nt < 4; nt++)
                    mma_tf32(acc[mt][nt], af[mt], bf[nt][0], bf[nt][1]);
        }
        __syncthreads();
    }

    const float* bias = jb.bias;
    const float* mul = jb.mul;
    const float* add = jb.add;
    int do_sig = jb.sig;
    float* C = jb.C;
    #pragma unroll
    for (int mt = 0; mt < MT; mt++) {
        #pragma unroll
        for (int nt = 0; nt < 4; nt++) {
            int r0 = m0 + mw + mt * 16 + gid;
            int c0 = n0 + nw + nt * 8 + 2 * tig;
            #pragma unroll
            for (int rr = 0; rr < 2; rr++) {
                int r = r0 + rr * 8;
                #pragma unroll
                for (int cc = 0; cc < 2; cc++) {
                    float v = acc[mt][nt][rr * 2 + cc];
                    int c = c0 + cc;
                    if (bias) v += bias[c];
                    if (do_sig) v = 1.f / (1.f + __expf(-v));
                    size_t ix = (size_t)r * N + c;
                    if (mul) v *= mul[ix];
                    if (add) v += add[ix];
                    C[ix] = v;
                }
            }
        }
    }
}

// ---------------- elementwise adaLN combine: anorm = gsig*aln + tmpb ----------------
__global__ void __launch_bounds__(256) combine_kernel(
    float* __restrict__ anorm, const float* __restrict__ aln, const float* __restrict__ tmpb)
{
    int i = blockIdx.x * 256 + threadIdx.x;
    float4 g = ((const float4*)anorm)[i];
    float4 a = ((const float4*)aln)[i];
    float4 tb = ((const float4*)tmpb)[i];
    g.x = g.x * a.x + tb.x;
    g.y = g.y * a.y + tb.y;
    g.z = g.z * a.z + tb.z;
    g.w = g.w * a.w + tb.w;
    ((float4*)anorm)[i] = g;
}

// ---------------- pair bias: LN(z)*gamma+beta @ Wpb + bias_mask -> g_pb[b,h,i,j] ----------------
// Direct global->register LN (1 float4/lane = one 128-ch row per warp), single tf32 smem write.
#define PJT 128
#define ZST 132
#define WST 24
#define PAIR_SMEM ((PJT*ZST + CP*WST + PJT) * 4)

__global__ void __launch_bounds__(256, 2) pair_kernel(
    const float* __restrict__ z, const float* __restrict__ bmask,
    const float* __restrict__ Wpb, const float* __restrict__ gma,
    const float* __restrict__ bta, float* __restrict__ pb)
{
    extern __shared__ float smp[];
    float* zn = smp;                                  // [128][132] tf32 after LN
    unsigned* Wb = (unsigned*)(smp + PJT * ZST);      // [128][24]
    float* bm_s = smp + PJT * ZST + CP * WST;         // [128]

    int t = threadIdx.x;
    int w = t >> 5, lane = t & 31;
    int gid = lane >> 2, tig = lane & 3;
    int bi = blockIdx.y;
    int b = bi / NN, i = bi % NN;
    int j0 = blockIdx.x * PJT;

    for (int idx = t; idx < CP * NH; idx += 256) {
        int c = idx >> 4, hh = idx & 15;
        Wb[c * WST + hh] = f2tf(Wpb[idx]);
    }
    if (t < PJT) bm_s[t] = bmask[(size_t)bi * NN + j0 + t];

    // per-warp gamma/beta for this lane's 4 channels (registers, uniform across rows)
    float4 gv = *(const float4*)(gma + lane * 4);
    float4 bv = *(const float4*)(bta + lane * 4);

    // LN: warp w handles rows w*16..w*16+15; one row per iteration, float4 per lane
    const float* zrow = z + ((size_t)bi * NN + j0) * CP;
    #pragma unroll 4
    for (int rr = 0; rr < 16; rr++) {
        int r = w * 16 + rr;
        float4 v = *(const float4*)(zrow + (size_t)r * CP + lane * 4);
        float s = v.x + v.y + v.z + v.w;
        float sq = v.x * v.x + v.y * v.y + v.z * v.z + v.w * v.w;
        #pragma unroll
        for (int o = 16; o; o >>= 1) {
            s  += __shfl_xor_sync(0xffffffffu, s, o);
            sq += __shfl_xor_sync(0xffffffffu, sq, o);
        }
        float mean = s * (1.f / CP);
        float inv = rsqrtf(sq * (1.f / CP) - mean * mean + 1e-5f);
        uint4 outv;
        outv.x = f2tf((v.x - mean) * inv * gv.x + bv.x);
        outv.y = f2tf((v.y - mean) * inv * gv.y + bv.y);
        outv.z = f2tf((v.z - mean) * inv * gv.z + bv.z);
        outv.w = f2tf((v.w - mean) * inv * gv.w + bv.w);
        *(uint4*)(zn + r * ZST + lane * 4) = outv;
    }
    __syncthreads();

    int mb = w * 16;
    unsigned zBase = smem_u32(zn);
    int lrow = lane & 15, lkq = lane >> 4;
    unsigned z_addr = zBase + (unsigned)(((mb + lrow) * ZST + lkq * 4) * 4);
    float c2[2][4];
    #pragma unroll
    for (int nt = 0; nt < 2; nt++)
        #pragma unroll
        for (int r = 0; r < 4; r++) c2[nt][r] = 0.f;
    #pragma unroll
    for (int ks = 0; ks < 16; ks++) {
        int kb = ks * 8;
        unsigned af[4];
        ldsm_x4(af, z_addr + kb * 4);
        #pragma unroll
        for (int nt = 0; nt < 2; nt++) {
            unsigned b0 = Wb[(kb + tig) * WST + nt * 8 + gid];
            unsigned b1 = Wb[(kb + tig + 4) * WST + nt * 8 + gid];
            mma_tf32(c2[nt], af, b0, b1);
        }
    }
    float bm0 = bm_s[mb + gid], bm1 = bm_s[mb + gid + 8];
    int jg0 = j0 + mb + gid;
    #pragma unroll
    for (int nt = 0; nt < 2; nt++) {
        int h0 = nt * 8 + 2 * tig;
        size_t base0 = ((size_t)(b * NH + h0) * NN + i) * NN;
        size_t base1 = ((size_t)(b * NH + h0 + 1) * NN + i) * NN;
        pb[base0 + jg0]     = c2[nt][0] + bm0;
        pb[base1 + jg0]     = c2[nt][1] + bm0;
        pb[base0 + jg0 + 8] = c2[nt][2] + bm1;
        pb[base1 + jg0 + 8] = c2[nt][3] + bm1;
    }
}

// ---------------- attention: flash-style with tf32 mma + ldmatrix ----------------
#define ATQ 52
#define AVQ 56
#define ATP 68
#define ATTN_SMEM ((2*64*ATQ + 64*AVQ + 64*ATP + 3*64) * 4)

__global__ void __launch_bounds__(256, 3) attn_kernel(
    const float* __restrict__ q, const float* __restrict__ k,
    const float* __restrict__ v, const float* __restrict__ gate,
    const float* __restrict__ pb, float* __restrict__ o)
{
    extern __shared__ float sm[];
    unsigned* Qs = (unsigned*)sm;           // [64][52] tf32
    unsigned* Ks = Qs + 64 * ATQ;           // [64][52] tf32
    unsigned* Vs = Ks + 64 * ATQ;           // [64][56] tf32
    float* Ps = (float*)(Vs + 64 * AVQ);    // [64][68]
    float* Ms = Ps + 64 * ATP;
    float* Ls = Ms + 64;
    float* Ss = Ls + 64;

    int qt = blockIdx.x, hh = blockIdx.y, b = blockIdx.z;
    int t = threadIdx.x;
    int w = t >> 5, lane = t & 31;
    int gid = lane >> 2, tig = lane & 3;
    int q0 = qt * 64;
    const float SC = 0.14433756729740643f;  // 1/sqrt(48)

    for (int idx = t; idx < 64 * HD; idx += 256) {
        int r = idx / HD, d = idx % HD;
        Qs[r * ATQ + d] = f2tf(q[((size_t)(b * NN + q0 + r)) * CT + hh * HD + d] * SC);
    }
    if (t < 64) { Ms[t] = -1e30f; Ls[t] = 0.f; }

    int wmS = w >> 2, wnS = w & 3;
    int mbS = wmS * 32, nbS = wnS * 16;
    int wmP = w >> 1, wnP = w & 1;
    int mbP = wmP * 16, nbP = wnP * 24;

    int lrow = lane & 15, lkq = lane >> 4;
    unsigned qaddr[2];
    #pragma unroll
    for (int mt = 0; mt < 2; mt++)
        qaddr[mt] = smem_u32(Qs) + (unsigned)(((mbS + mt * 16 + lrow) * ATQ + lkq * 4) * 4);
    unsigned kaddr[2];
    #pragma unroll
    for (int nt = 0; nt < 2; nt++)
        kaddr[nt] = smem_u32(Ks) + (unsigned)(((nbS + nt * 8 + (lane & 7)) * ATQ + ((lane >> 3) & 1) * 4) * 4);
    unsigned paddr = smem_u32(Ps) + (unsigned)(((mbP + lrow) * ATP + lkq * 4) * 4);

    float oacc[3][4];
    #pragma unroll
    for (int nt = 0; nt < 3; nt++)
        #pragma unroll
        for (int r = 0; r < 4; r++) oacc[nt][r] = 0.f;

    const float* bp0 = pb + ((size_t)(b * NH + hh) * NN + q0) * NN;

    for (int kt = 0; kt < 12; kt++) {
        int k0 = kt * 64;
        __syncthreads();
        for (int idx = t; idx < 64 * HD; idx += 256) {
            int r = idx / HD, d = idx % HD;
            size_t gi = ((size_t)(b * NN + k0 + r)) * CT + hh * HD + d;
            Ks[r * ATQ + d] = f2tf(k[gi]);
            Vs[r * AVQ + d] = f2tf(v[gi]);
        }
        for (int idx = t; idx < 64 * 16; idx += 256) {
            int r = idx >> 4, c4 = idx & 15;
            float4 bv = *(const float4*)(bp0 + (size_t)r * NN + k0 + c4 * 4);
            *(float4*)(Ps + r * ATP + c4 * 4) = bv;
        }
        __syncthreads();

        float sacc[2][2][4];
        #pragma unroll
        for (int mt = 0; mt < 2; mt++)
            #pragma unroll
            for (int nt = 0; nt < 2; nt++)
                #pragma unroll
                for (int r = 0; r < 4; r++) sacc[mt][nt][r] = 0.f;
        #pragma unroll
        for (int ks = 0; ks < 6; ks++) {
            int kb = ks * 8;
            unsigned af[2][4];
            #pragma unroll
            for (int mt = 0; mt < 2; mt++) ldsm_x4(af[mt], qaddr[mt] + kb * 4);
            #pragma unroll
            for (int nt = 0; nt < 2; nt++) {
                unsigned b0, b1;
                ldsm_x2(b0, b1, kaddr[nt] + kb * 4);
                #pragma unroll
                for (int mt = 0; mt < 2; mt++)
                    mma_tf32(sacc[mt][nt], af[mt], b0, b1);
            }
        }
        #pragma unroll
        for (int mt = 0; mt < 2; mt++) {
            #pragma unroll
            for (int nt = 0; nt < 2; nt++) {
                int r = mbS + mt * 16 + gid;
                int c = nbS + nt * 8 + 2 * tig;
                float* p0 = Ps + r * ATP + c;
                float* p1 = Ps + (r + 8) * ATP + c;
                p0[0] += sacc[mt][nt][0];
                p0[1] += sacc[mt][nt][1];
                p1[0] += sacc[mt][nt][2];
                p1[1] += sacc[mt][nt][3];
            }
        }
        __syncthreads();

        // online softmax: 4 lanes per query row, stride-4 interleave; store P as tf32 bits
        {
            int qq = t >> 2, pp = t & 3;
            float* prow = Ps + qq * ATP + pp;
            float tmax = -1e30f;
            #pragma unroll
            for (int jj = 0; jj < 16; jj++) tmax = fmaxf(tmax, prow[jj * 4]);
            tmax = fmaxf(tmax, __shfl_xor_sync(0xffffffffu, tmax, 1));
            tmax = fmaxf(tmax, __shfl_xor_sync(0xffffffffu, tmax, 2));
            float mold = Ms[qq];
            float mnew = fmaxf(mold, tmax);
            float tsum = 0.f;
            #pragma unroll
            for (int jj = 0; jj < 16; jj++) {
                float p = __expf(prow[jj * 4] - mnew);
                tsum += p;
                prow[jj * 4] = __uint_as_float(f2tf(p));
            }
            tsum += __shfl_xor_sync(0xffffffffu, tsum, 1);
            tsum += __shfl_xor_sync(0xffffffffu, tsum, 2);
            if (pp == 0) {
                float scl = __expf(mold - mnew);
                Ss[qq] = scl;
                Ls[qq] = Ls[qq] * scl + tsum;
                Ms[qq] = mnew;
            }
        }
        __syncthreads();

        // rescale + O += P @ V via mma (P frag via ldmatrix)
        {
            float s0 = Ss[mbP + gid], s1 = Ss[mbP + gid + 8];
            #pragma unroll
            for (int nt = 0; nt < 3; nt++) {
                oacc[nt][0] *= s0; oacc[nt][1] *= s0;
                oacc[nt][2] *= s1; oacc[nt][3] *= s1;
            }
            #pragma unroll
            for (int ks = 0; ks < 8; ks++) {
                int kb = ks * 8;
                unsigned af[4];
                ldsm_x4(af, paddr + kb * 4);
                #pragma unroll
                for (int nt = 0; nt < 3; nt++) {
                    unsigned b0 = Vs[(kb + tig) * AVQ + nbP + nt * 8 + gid];
                    unsigned b1 = Vs[(kb + tig + 4) * AVQ + nbP + nt * 8 + gid];
                    mma_tf32(oacc[nt], af, b0, b1);
                }
            }
        }
    }

    // epilogue: normalize, gate, write
    __syncthreads();
    float inv0 = 1.f / Ls[mbP + gid];
    float inv1 = 1.f / Ls[mbP + gid + 8];
    size_t row0 = (size_t)(b * NN + q0 + mbP + gid);
    size_t row1 = row0 + 8;
    #pragma unroll
    for (int nt = 0; nt < 3; nt++) {
        int c = hh * HD + nbP + nt * 8 + 2 * tig;
        size_t i00 = row0 * CT + c;
        size_t i10 = row1 * CT + c;
        float g00 = 1.f / (1.f + __expf(-gate[i00]));
        float g01 = 1.f / (1.f + __expf(-gate[i00 + 1]));
        float g10 = 1.f / (1.f + __expf(-gate[i10]));
        float g11 = 1.f / (1.f + __expf(-gate[i10 + 1]));
        o[i00]     = g00 * oacc[nt][0] * inv0;
        o[i00 + 1] = g01 * oacc[nt][1] * inv0;
        o[i10]     = g10 * oacc[nt][2] * inv1;
        o[i10 + 1] = g11 * oacc[nt][3] * inv1;
    }
}

// ---------------- launch ----------------
static float* symaddr(const void* sym) {
    void* p = nullptr;
    cudaGetSymbolAddress(&p, sym);
    return (float*)p;
}

extern "C" void kernel_launch(void* const* d_in, const int* in_sizes, int n_in,
                              void* d_out, int out_size) {
    const float* a    = (const float*)d_in[0];
    const float* s    = (const float*)d_in[1];
    const float* z    = (const float*)d_in[2];
    const float* bm   = (const float*)d_in[3];
    const float* Wg   = (const float*)d_in[4];
    const float* bg   = (const float*)d_in[5];
    const float* Wb   = (const float*)d_in[6];
    const float* Wq   = (const float*)d_in[7];
    const float* bq   = (const float*)d_in[8];
    const float* Wk   = (const float*)d_in[9];
    const float* Wv   = (const float*)d_in[10];
    const float* Wpb  = (const float*)d_in[11];
    const float* png  = (const float*)d_in[12];
    const float* pnb  = (const float*)d_in[13];
    const float* Wgt  = (const float*)d_in[14];
    const float* Wout = (const float*)d_in[15];
    const float* Wog  = (const float*)d_in[16];
    const float* bog  = (const float*)d_in[17];
    float* out = (float*)d_out;

    float* aln   = symaddr(g_aln);
    float* sln   = symaddr(g_sln);
    float* tmpb  = symaddr(g_tmpb);
    float* anorm = symaddr(g_anorm);
    float* qb    = symaddr(g_q);
    float* kb    = symaddr(g_k);
    float* vb    = symaddr(g_v);
    float* gateb = symaddr(g_gate);
    float* ogb   = symaddr(g_og);
    float* ob    = symaddr(g_o);
    float* pbb   = symaddr(g_pb);

    cudaFuncSetAttribute(pair_kernel, cudaFuncAttributeMaxDynamicSharedMemorySize, PAIR_SMEM);
    cudaFuncSetAttribute(attn_kernel, cudaFuncAttributeMaxDynamicSharedMemorySize, ATTN_SMEM);

    // fused LayerNorms
    ln2_kernel<<<dim3(ROWS, 2), 256>>>(a, s, aln, sln);

    // batch 1: adaLN gate (sigmoid), adaLN bias-proj, output-gate (sigmoid) — K=384
    {
        GemmBatchArgs p = {};
        p.j[0] = { sln, Wb,  tmpb,  nullptr, nullptr, nullptr, CS, 0 };
        p.j[1] = { sln, Wg,  anorm, bg,      nullptr, nullptr, CS, 1 };   // gsig
        p.j[2] = { s,   Wog, ogb,   bog,     nullptr, nullptr, CS, 1 };
        gemm128_kernel<<<dim3(CT / 128, ROWS / 128, 3), 256>>>(p, ROWS, CT);
    }
    // anorm = gsig * aln + tmpb
    combine_kernel<<<ROWS * CT / 4 / 256, 256>>>(anorm, aln, tmpb);

    // batch 2: Q/K/V/gate — shared A, K=768
    {
        GemmBatchArgs p = {};
        p.j[0] = { anorm, Wq,  qb,    bq,      nullptr, nullptr, CT, 0 };
        p.j[1] = { anorm, Wk,  kb,    nullptr, nullptr, nullptr, CT, 0 };
        p.j[2] = { anorm, Wv,  vb,    nullptr, nullptr, nullptr, CT, 0 };
        p.j[3] = { anorm, Wgt, gateb, nullptr, nullptr, nullptr, CT, 0 };
        gemm128_kernel<<<dim3(CT / 128, ROWS / 128, 4), 256>>>(p, ROWS, CT);
    }

    // pair bias (incl. bias_mask)
    pair_kernel<<<dim3(NN / PJT, ROWS), 256, PAIR_SMEM>>>(z, bm, Wpb, png, pnb, pbb);
    // attention + gating
    attn_kernel<<<dim3(NN / 64, NH, BB), 256, ATTN_SMEM>>>(qb, kb, vb, gateb, pbb, ob);

    // output projection with output-gate multiply — BM=64 for 288 CTAs
    {
        GemmBatchArgs p = {};
        p.j[0] = { ob, Wout, out, nullptr, ogb, nullptr, CT, 0 };
        gemm_batch_kernel<64><<<dim3(CT / 64, ROWS / 64, 1), 256>>>(p, ROWS, CT);
    }
}

// round 13
// speedup vs baseline: 3.3835x; 1.0643x over previous
#include <cuda_runtime.h>
#include <math.h>

#define BB 2
#define NN 768
#define CT 768
#define CS 384
#define CP 128
#define NH 16
#define HD 48
#define ROWS (BB*NN)   /* 1536 */

// ---------------- scratch (device globals; no allocation allowed) ----------------
__device__ float g_aln  [ROWS*CT];
__device__ float g_sln  [ROWS*CS];
__device__ float g_tmpb [ROWS*CT];
__device__ float g_anorm[ROWS*CT];
__device__ float g_q    [ROWS*CT];
__device__ float g_k    [ROWS*CT];
__device__ float g_v    [ROWS*CT];
__device__ float g_gate [ROWS*CT];
__device__ float g_og   [ROWS*CT];
__device__ float g_o    [ROWS*CT];
__device__ float g_pb   [BB*NH*NN*NN];   // 75.5 MB pair bias [b,h,i,j]
// pre-rounded (tf32-valued fp32) operands
__device__ float g_wq [CT*CT];
__device__ float g_wk [CT*CT];
__device__ float g_wv [CT*CT];
__device__ float g_wgt[CT*CT];
__device__ float g_wb [CS*CT];
__device__ float g_wg [CS*CT];
__device__ float g_wog[CS*CT];
__device__ float g_srnd[ROWS*CS];

// ---------------- tf32 / mma / ldmatrix / cp.async helpers ----------------
__device__ __forceinline__ unsigned f2tf(float f) {
    unsigned u;
    asm("cvt.rna.tf32.f32 %0, %1;" : "=r"(u) : "f"(f));
    return u;
}
__device__ __forceinline__ void mma_tf32(float* c, const unsigned* a, unsigned b0, unsigned b1) {
    asm volatile(
        "mma.sync.aligned.m16n8k8.row.col.f32.tf32.tf32.f32 "
        "{%0,%1,%2,%3}, {%4,%5,%6,%7}, {%8,%9}, {%0,%1,%2,%3};\n"
        : "+f"(c[0]), "+f"(c[1]), "+f"(c[2]), "+f"(c[3])
        : "r"(a[0]), "r"(a[1]), "r"(a[2]), "r"(a[3]), "r"(b0), "r"(b1));
}
__device__ __forceinline__ unsigned smem_u32(const void* p) {
    return (unsigned)__cvta_generic_to_shared(p);
}
__device__ __forceinline__ void ldsm_x4(unsigned* r, unsigned a) {
    asm volatile("ldmatrix.sync.aligned.m8n8.x4.shared.b16 {%0,%1,%2,%3}, [%4];"
        : "=r"(r[0]), "=r"(r[1]), "=r"(r[2]), "=r"(r[3]) : "r"(a));
}
__device__ __forceinline__ void ldsm_x2(unsigned& r0, unsigned& r1, unsigned a) {
    asm volatile("ldmatrix.sync.aligned.m8n8.x2.shared.b16 {%0,%1}, [%2];"
        : "=r"(r0), "=r"(r1) : "r"(a));
}
__device__ __forceinline__ void cp16(unsigned saddr, const void* g) {
    asm volatile("cp.async.cg.shared.global [%0], [%1], 16;" :: "r"(saddr), "l"(g));
}
#define CP_COMMIT() asm volatile("cp.async.commit_group;")
#define CP_WAIT1()  asm volatile("cp.async.wait_group 1;")

// ---------------- pre-round weights / s to tf32-valued fp32 ----------------
struct RoundJob { const float* src; float* dst; int n4; };
struct RoundArgs { RoundJob j[8]; };
__global__ void __launch_bounds__(256) round_kernel(RoundArgs ra) {
    RoundJob jb = ra.j[blockIdx.y];
    for (int i = blockIdx.x * 256 + threadIdx.x; i < jb.n4; i += gridDim.x * 256) {
        float4 v = ((const float4*)jb.src)[i];
        uint4 o = make_uint4(f2tf(v.x), f2tf(v.y), f2tf(v.z), f2tf(v.w));
        ((uint4*)jb.dst)[i] = o;
    }
}

// ---------------- fused LayerNorms (no affine); s-branch output rounded to tf32 ----------------
__device__ __forceinline__ float2 blockReduce2(float a, float b) {
    #pragma unroll
    for (int o = 16; o; o >>= 1) {
        a += __shfl_xor_sync(0xffffffffu, a, o);
        b += __shfl_xor_sync(0xffffffffu, b, o);
    }
    __shared__ float sa[8], sb[8];
    int w = threadIdx.x >> 5, l = threadIdx.x & 31;
    if (l == 0) { sa[w] = a; sb[w] = b; }
    __syncthreads();
    if (w == 0) {
        a = (l < 8) ? sa[l] : 0.f;
        b = (l < 8) ? sb[l] : 0.f;
        #pragma unroll
        for (int o = 4; o; o >>= 1) {
            a += __shfl_xor_sync(0xffffffffu, a, o);
            b += __shfl_xor_sync(0xffffffffu, b, o);
        }
        if (l == 0) { sa[0] = a; sb[0] = b; }
    }
    __syncthreads();
    return make_float2(sa[0], sb[0]);
}

__global__ void __launch_bounds__(256) ln2_kernel(
    const float* __restrict__ a, const float* __restrict__ s,
    float* __restrict__ aout, float* __restrict__ sout)
{
    int isS = (blockIdx.y != 0);
    int C = isS ? CS : CT;
    const float* in = isS ? s : a;
    float* out = isS ? sout : aout;
    int r = blockIdx.x;
    const float* x = in + (size_t)r * C;
    float sm = 0.f, sq = 0.f;
    for (int c = threadIdx.x; c < C; c += 256) { float v = x[c]; sm += v; sq += v * v; }
    float2 red = blockReduce2(sm, sq);
    float mean = red.x / C;
    float inv = rsqrtf(red.y / C - mean * mean + 1e-5f);
    float* y = out + (size_t)r * C;
    for (int c = threadIdx.x; c < C; c += 256) {
        float v = (x[c] - mean) * inv;
        y[c] = isS ? __uint_as_float(f2tf(v)) : v;   // sln feeds GEMM A -> pre-round
    }
}

// ---------------- GEMM jobs ----------------
struct GemmJob {
    const float* A; const float* B; float* C;
    const float* bias; const float* mul; const float* add;
    int K; int sig;
};
struct GemmBatchArgs { GemmJob j[4]; };

// ============ 128x128x16 tf32 GEMM, cp.async 3-stage pipeline, ldmatrix A-frags ============
// Operands MUST be pre-rounded to tf32 values (HW truncation then exact).
// 256 threads = 8 warps in 2(m) x 4(n); warp tile 64m x 32n
#define AST 20
#define BST 136
#define ABUF (128*AST)
#define BBUF (16*BST)
#define GEMM_SMEM (3*(ABUF+BBUF)*4)   /* 56832 B */

__global__ void __launch_bounds__(256, 2) gemm128_kernel(GemmBatchArgs p, int M, int N) {
    const GemmJob jb = p.j[blockIdx.z];
    const float* __restrict__ A = jb.A;
    const float* __restrict__ B = jb.B;
    const int K = jb.K;

    extern __shared__ unsigned smg[];
    unsigned* As = smg;               // 3 x [128][AST]
    unsigned* Bs = smg + 3 * ABUF;    // 3 x [16][BST]

    int t = threadIdx.x, w = t >> 5, lane = t & 31;
    int gid = lane >> 2, tig = lane & 3;
    int wm = w >> 2, wn = w & 3;
    int m0 = blockIdx.y * 128, n0 = blockIdx.x * 128;
    int mw = wm * 64, nw = wn * 32;

    float acc[4][4][4];
    #pragma unroll
    for (int mt = 0; mt < 4; mt++)
        #pragma unroll
        for (int nt = 0; nt < 4; nt++)
            #pragma unroll
            for (int r = 0; r < 4; r++) acc[mt][nt][r] = 0.f;

    // staging maps: A 128 rows x 4x16B (16 k), B 16 k-rows x 32x16B (128 n)
    int arow[2], akq[2], brow[2], bc4[2];
    unsigned sa[2], sb[2];
    #pragma unroll
    for (int i = 0; i < 2; i++) {
        int idx = t + i * 256;
        arow[i] = idx >> 2; akq[i] = idx & 3;
        brow[i] = idx >> 5; bc4[i] = idx & 31;
        sa[i] = smem_u32(As) + (unsigned)((arow[i] * AST + akq[i] * 4) * 4);
        sb[i] = smem_u32(As) + (unsigned)((3 * ABUF + brow[i] * BST + bc4[i] * 4) * 4);
    }

    unsigned aBase = smem_u32(As);
    int lrow = lane & 15, lkq = lane >> 4;
    unsigned a_addr[4];
    #pragma unroll
    for (int mt = 0; mt < 4; mt++)
        a_addr[mt] = aBase + (unsigned)(((mw + mt * 16 + lrow) * AST + lkq * 4) * 4);

    int nchunk = K / 16;
    // prologue: issue stages 0,1
    #pragma unroll
    for (int st = 0; st < 2; st++) {
        #pragma unroll
        for (int i = 0; i < 2; i++) {
            cp16(sa[i] + st * (ABUF * 4), A + (size_t)(m0 + arow[i]) * K + st * 16 + akq[i] * 4);
            cp16(sb[i] + st * (BBUF * 4), B + (size_t)(st * 16 + brow[i]) * N + n0 + bc4[i] * 4);
        }
        CP_COMMIT();
    }

    for (int ch = 0; ch < nchunk; ch++) {
        int stage = ch % 3;
        CP_WAIT1();
        __syncthreads();
        // issue chunk ch+2 into stage (ch+2)%3 (that buffer's compute finished last iter)
        if (ch + 2 < nchunk) {
            int k0 = (ch + 2) * 16;
            int st = (ch + 2) % 3;
            #pragma unroll
            for (int i = 0; i < 2; i++) {
                cp16(sa[i] + st * (ABUF * 4), A + (size_t)(m0 + arow[i]) * K + k0 + akq[i] * 4);
                cp16(sb[i] + st * (BBUF * 4), B + (size_t)(k0 + brow[i]) * N + n0 + bc4[i] * 4);
            }
        }
        CP_COMMIT();

        unsigned aOff = stage * (ABUF * 4);
        const unsigned* BsC = Bs + stage * BBUF;
        #pragma unroll
        for (int ks = 0; ks < 2; ks++) {
            int kb = ks * 8;
            unsigned af[4][4];
            #pragma unroll
            for (int mt = 0; mt < 4; mt++) ldsm_x4(af[mt], a_addr[mt] + aOff + kb * 4);
            unsigned bf[4][2];
            #pragma unroll
            for (int nt = 0; nt < 4; nt++) {
                bf[nt][0] = BsC[(kb + tig) * BST + nw + nt * 8 + gid];
                bf[nt][1] = BsC[(kb + tig + 4) * BST + nw + nt * 8 + gid];
            }
            #pragma unroll
            for (int mt = 0; mt < 4; mt++)
                #pragma unroll
                for (int nt = 0; nt < 4; nt++)
                    mma_tf32(acc[mt][nt], af[mt], bf[nt][0], bf[nt][1]);
        }
    }

    // epilogue
    const float* bias = jb.bias;
    const float* mul = jb.mul;
    const float* add = jb.add;
    int do_sig = jb.sig;
    float* C = jb.C;
    #pragma unroll
    for (int mt = 0; mt < 4; mt++) {
        #pragma unroll
        for (int nt = 0; nt < 4; nt++) {
            int r0 = m0 + mw + mt * 16 + gid;
            int c0 = n0 + nw + nt * 8 + 2 * tig;
            #pragma unroll
            for (int rr = 0; rr < 2; rr++) {
                int r = r0 + rr * 8;
                #pragma unroll
                for (int cc = 0; cc < 2; cc++) {
                    float v = acc[mt][nt][rr * 2 + cc];
                    int c = c0 + cc;
                    if (bias) v += bias[c];
                    if (do_sig) v = 1.f / (1.f + __expf(-v));
                    size_t ix = (size_t)r * N + c;
                    if (mul) v *= mul[ix];
                    if (add) v += add[ix];
                    C[ix] = v;
                }
            }
        }
    }
}

// ============ 64x64 kernel kept for Wout (needs 288 CTAs) ============
template <int BM>
__global__ void __launch_bounds__(256, 2) gemm_batch_kernel(GemmBatchArgs p, int M, int N) {
    const GemmJob jb = p.j[blockIdx.z];
    const float* __restrict__ A = jb.A;
    const float* __restrict__ B = jb.B;
    const int K = jb.K;
    constexpr int MT = BM / 64;
    constexpr int NLD = BM / 32;

    __shared__ unsigned As[32][BM + 8];
    __shared__ unsigned Bs[32][72];
    int t = threadIdx.x;
    int w = t >> 5, lane = t & 31;
    int gid = lane >> 2, tig = lane & 3;
    int wm = w >> 1, wn = w & 1;
    int m0 = blockIdx.y * BM, n0 = blockIdx.x * 64;
    int mw = wm * (BM / 4), nw = wn * 32;

    float acc[MT][4][4];
    #pragma unroll
    for (int mt = 0; mt < MT; mt++)
        #pragma unroll
        for (int nt = 0; nt < 4; nt++)
            #pragma unroll
            for (int r = 0; r < 4; r++) acc[mt][nt][r] = 0.f;

    int arow[NLD], akb[NLD], brow[2], bc4[2];
    #pragma unroll
    for (int i = 0; i < NLD; i++) { int idx = t + i * 256; arow[i] = idx & (BM - 1); akb[i] = idx / BM; }
    #pragma unroll
    for (int i = 0; i < 2; i++) { int idx = t + i * 256; brow[i] = idx >> 4; bc4[i] = idx & 15; }

    float4 ar[NLD], br[2];
    #pragma unroll
    for (int i = 0; i < NLD; i++)
        ar[i] = *(const float4*)(A + (size_t)(m0 + arow[i]) * K + akb[i] * 4);
    #pragma unroll
    for (int i = 0; i < 2; i++)
        br[i] = *(const float4*)(B + (size_t)brow[i] * N + n0 + bc4[i] * 4);

    int nchunk = K / 32;
    for (int ch = 0; ch < nchunk; ch++) {
        #pragma unroll
        for (int i = 0; i < NLD; i++) {
            As[akb[i] * 4 + 0][arow[i]] = f2tf(ar[i].x);
            As[akb[i] * 4 + 1][arow[i]] = f2tf(ar[i].y);
            As[akb[i] * 4 + 2][arow[i]] = f2tf(ar[i].z);
            As[akb[i] * 4 + 3][arow[i]] = f2tf(ar[i].w);
        }
        #pragma unroll
        for (int i = 0; i < 2; i++) {
            Bs[brow[i]][bc4[i] * 4 + 0] = f2tf(br[i].x);
            Bs[brow[i]][bc4[i] * 4 + 1] = f2tf(br[i].y);
            Bs[brow[i]][bc4[i] * 4 + 2] = f2tf(br[i].z);
            Bs[brow[i]][bc4[i] * 4 + 3] = f2tf(br[i].w);
        }
        __syncthreads();
        if (ch + 1 < nchunk) {
            int k0 = (ch + 1) * 32;
            #pragma unroll
            for (int i = 0; i < NLD; i++)
                ar[i] = *(const float4*)(A + (size_t)(m0 + arow[i]) * K + k0 + akb[i] * 4);
            #pragma unroll
            for (int i = 0; i < 2; i++)
                br[i] = *(const float4*)(B + (size_t)(k0 + brow[i]) * N + n0 + bc4[i] * 4);
        }
        #pragma unroll
        for (int ks = 0; ks < 4; ks++) {
            int kb = ks * 8;
            unsigned af[MT][4];
            #pragma unroll
            for (int mt = 0; mt < MT; mt++) {
                int mb = mw + mt * 16 + gid;
                af[mt][0] = As[kb + tig][mb];
                af[mt][1] = As[kb + tig][mb + 8];
                af[mt][2] = As[kb + tig + 4][mb];
                af[mt][3] = As[kb + tig + 4][mb + 8];
            }
            unsigned bf[4][2];
            #pragma unroll
            for (int nt = 0; nt < 4; nt++) {
                int nb = nw + nt * 8 + gid;
                bf[nt][0] = Bs[kb + tig][nb];
                bf[nt][1] = Bs[kb + tig + 4][nb];
            }
            #pragma unroll
            for (int mt = 0; mt < MT; mt++)
                #pragma unroll
                for (int nt = 0; nt < 4; nt++)
                    mma_tf32(acc[mt][nt], af[mt], bf[nt][0], bf[nt][1]);
        }
        __syncthreads();
    }

    const float* bias = jb.bias;
    const float* mul = jb.mul;
    const float* add = jb.add;
    int do_sig = jb.sig;
    float* C = jb.C;
    #pragma unroll
    for (int mt = 0; mt < MT; mt++) {
        #pragma unroll
        for (int nt = 0; nt < 4; nt++) {
            int r0 = m0 + mw + mt * 16 + gid;
            int c0 = n0 + nw + nt * 8 + 2 * tig;
            #pragma unroll
            for (int rr = 0; rr < 2; rr++) {
                int r = r0 + rr * 8;
                #pragma unroll
                for (int cc = 0; cc < 2; cc++) {
                    float v = acc[mt][nt][rr * 2 + cc];
                    int c = c0 + cc;
                    if (bias) v += bias[c];
                    if (do_sig) v = 1.f / (1.f + __expf(-v));
                    size_t ix = (size_t)r * N + c;
                    if (mul) v *= mul[ix];
                    if (add) v += add[ix];
                    C[ix] = v;
                }
            }
        }
    }
}

// ---------------- elementwise adaLN combine: anorm = round_tf32(gsig*aln + tmpb) ----------------
__global__ void __launch_bounds__(256) combine_kernel(
    float* __restrict__ anorm, const float* __restrict__ aln, const float* __restrict__ tmpb)
{
    int i = blockIdx.x * 256 + threadIdx.x;
    float4 g = ((const float4*)anorm)[i];
    float4 a = ((const float4*)aln)[i];
    float4 tb = ((const float4*)tmpb)[i];
    uint4 o;
    o.x = f2tf(g.x * a.x + tb.x);
    o.y = f2tf(g.y * a.y + tb.y);
    o.z = f2tf(g.z * a.z + tb.z);
    o.w = f2tf(g.w * a.w + tb.w);
    ((uint4*)anorm)[i] = o;
}

// ---------------- pair bias: LN(z)*gamma+beta @ Wpb + bias_mask -> g_pb[b,h,i,j] ----------------
#define PJT 128
#define ZST 132
#define WST 24
#define PAIR_SMEM ((PJT*ZST + CP*WST + PJT) * 4)

__global__ void __launch_bounds__(256, 2) pair_kernel(
    const float* __restrict__ z, const float* __restrict__ bmask,
    const float* __restrict__ Wpb, const float* __restrict__ gma,
    const float* __restrict__ bta, float* __restrict__ pb)
{
    extern __shared__ float smp[];
    float* zn = smp;                                  // [128][132] tf32 after LN
    unsigned* Wb = (unsigned*)(smp + PJT * ZST);      // [128][24]
    float* bm_s = smp + PJT * ZST + CP * WST;         // [128]

    int t = threadIdx.x;
    int w = t >> 5, lane = t & 31;
    int gid = lane >> 2, tig = lane & 3;
    int bi = blockIdx.y;
    int b = bi / NN, i = bi % NN;
    int j0 = blockIdx.x * PJT;

    for (int idx = t; idx < CP * NH; idx += 256) {
        int c = idx >> 4, hh = idx & 15;
        Wb[c * WST + hh] = f2tf(Wpb[idx]);
    }
    if (t < PJT) bm_s[t] = bmask[(size_t)bi * NN + j0 + t];

    float4 gv = *(const float4*)(gma + lane * 4);
    float4 bv = *(const float4*)(bta + lane * 4);

    const float* zrow = z + ((size_t)bi * NN + j0) * CP;
    #pragma unroll 4
    for (int rr = 0; rr < 16; rr++) {
        int r = w * 16 + rr;
        float4 v = *(const float4*)(zrow + (size_t)r * CP + lane * 4);
        float s = v.x + v.y + v.z + v.w;
        float sq = v.x * v.x + v.y * v.y + v.z * v.z + v.w * v.w;
        #pragma unroll
        for (int o = 16; o; o >>= 1) {
            s  += __shfl_xor_sync(0xffffffffu, s, o);
            sq += __shfl_xor_sync(0xffffffffu, sq, o);
        }
        float mean = s * (1.f / CP);
        float inv = rsqrtf(sq * (1.f / CP) - mean * mean + 1e-5f);
        uint4 outv;
        outv.x = f2tf((v.x - mean) * inv * gv.x + bv.x);
        outv.y = f2tf((v.y - mean) * inv * gv.y + bv.y);
        outv.z = f2tf((v.z - mean) * inv * gv.z + bv.z);
        outv.w = f2tf((v.w - mean) * inv * gv.w + bv.w);
        *(uint4*)(zn + r * ZST + lane * 4) = outv;
    }
    __syncthreads();

    int mb = w * 16;
    unsigned zBase = smem_u32(zn);
    int lrow = lane & 15, lkq = lane >> 4;
    unsigned z_addr = zBase + (unsigned)(((mb + lrow) * ZST + lkq * 4) * 4);
    float c2[2][4];
    #pragma unroll
    for (int nt = 0; nt < 2; nt++)
        #pragma unroll
        for (int r = 0; r < 4; r++) c2[nt][r] = 0.f;
    #pragma unroll
    for (int ks = 0; ks < 16; ks++) {
        int kb = ks * 8;
        unsigned af[4];
        ldsm_x4(af, z_addr + kb * 4);
        #pragma unroll
        for (int nt = 0; nt < 2; nt++) {
            unsigned b0 = Wb[(kb + tig) * WST + nt * 8 + gid];
            unsigned b1 = Wb[(kb + tig + 4) * WST + nt * 8 + gid];
            mma_tf32(c2[nt], af, b0, b1);
        }
    }
    float bm0 = bm_s[mb + gid], bm1 = bm_s[mb + gid + 8];
    int jg0 = j0 + mb + gid;
    #pragma unroll
    for (int nt = 0; nt < 2; nt++) {
        int h0 = nt * 8 + 2 * tig;
        size_t base0 = ((size_t)(b * NH + h0) * NN + i) * NN;
        size_t base1 = ((size_t)(b * NH + h0 + 1) * NN + i) * NN;
        pb[base0 + jg0]     = c2[nt][0] + bm0;
        pb[base1 + jg0]     = c2[nt][1] + bm0;
        pb[base0 + jg0 + 8] = c2[nt][2] + bm1;
        pb[base1 + jg0 + 8] = c2[nt][3] + bm1;
    }
}

// ---------------- attention: flash-style with tf32 mma + ldmatrix, float4 staging ----------------
#define ATQ 52
#define AVQ 56
#define ATP 68
#define ATTN_SMEM ((2*64*ATQ + 64*AVQ + 64*ATP + 3*64) * 4)

__global__ void __launch_bounds__(256, 3) attn_kernel(
    const float* __restrict__ q, const float* __restrict__ k,
    const float* __restrict__ v, const float* __restrict__ gate,
    const float* __restrict__ pb, float* __restrict__ o)
{
    extern __shared__ float sm[];
    unsigned* Qs = (unsigned*)sm;           // [64][52] tf32
    unsigned* Ks = Qs + 64 * ATQ;           // [64][52] tf32
    unsigned* Vs = Ks + 64 * ATQ;           // [64][56] tf32
    float* Ps = (float*)(Vs + 64 * AVQ);    // [64][68]
    float* Ms = Ps + 64 * ATP;
    float* Ls = Ms + 64;
    float* Ss = Ls + 64;

    int qt = blockIdx.x, hh = blockIdx.y, b = blockIdx.z;
    int t = threadIdx.x;
    int w = t >> 5, lane = t & 31;
    int gid = lane >> 2, tig = lane & 3;
    int q0 = qt * 64;
    const float SC = 0.14433756729740643f;  // 1/sqrt(48)

    #pragma unroll
    for (int it = 0; it < 3; it++) {        // 64 rows x 12 float4
        int idx = t + it * 256;
        int r = idx / 12, d4 = idx % 12;
        float4 vq = *(const float4*)(q + ((size_t)(b * NN + q0 + r)) * CT + hh * HD + d4 * 4);
        *(uint4*)(Qs + r * ATQ + d4 * 4) =
            make_uint4(f2tf(vq.x * SC), f2tf(vq.y * SC), f2tf(vq.z * SC), f2tf(vq.w * SC));
    }
    if (t < 64) { Ms[t] = -1e30f; Ls[t] = 0.f; }

    int wmS = w >> 2, wnS = w & 3;
    int mbS = wmS * 32, nbS = wnS * 16;
    int wmP = w >> 1, wnP = w & 1;
    int mbP = wmP * 16, nbP = wnP * 24;

    int lrow = lane & 15, lkq = lane >> 4;
    unsigned qaddr[2];
    #pragma unroll
    for (int mt = 0; mt < 2; mt++)
        qaddr[mt] = smem_u32(Qs) + (unsigned)(((mbS + mt * 16 + lrow) * ATQ + lkq * 4) * 4);
    unsigned kaddr[2];
    #pragma unroll
    for (int nt = 0; nt < 2; nt++)
        kaddr[nt] = smem_u32(Ks) + (unsigned)(((nbS + nt * 8 + (lane & 7)) * ATQ + ((lane >> 3) & 1) * 4) * 4);
    unsigned paddr = smem_u32(Ps) + (unsigned)(((mbP + lrow) * ATP + lkq * 4) * 4);

    float oacc[3][4];
    #pragma unroll
    for (int nt = 0; nt < 3; nt++)
        #pragma unroll
        for (int r = 0; r < 4; r++) oacc[nt][r] = 0.f;

    const float* bp0 = pb + ((size_t)(b * NH + hh) * NN + q0) * NN;

    for (int kt = 0; kt < 12; kt++) {
        int k0 = kt * 64;
        __syncthreads();
        #pragma unroll
        for (int it = 0; it < 3; it++) {
            int idx = t + it * 256;
            int r = idx / 12, d4 = idx % 12;
            size_t gi = ((size_t)(b * NN + k0 + r)) * CT + hh * HD + d4 * 4;
            float4 kv = *(const float4*)(k + gi);
            *(uint4*)(Ks + r * ATQ + d4 * 4) = make_uint4(f2tf(kv.x), f2tf(kv.y), f2tf(kv.z), f2tf(kv.w));
            float4 vv = *(const float4*)(v + gi);
            *(uint4*)(Vs + r * AVQ + d4 * 4) = make_uint4(f2tf(vv.x), f2tf(vv.y), f2tf(vv.z), f2tf(vv.w));
        }
        for (int idx = t; idx < 64 * 16; idx += 256) {
            int r = idx >> 4, c4 = idx & 15;
            float4 bv = *(const float4*)(bp0 + (size_t)r * NN + k0 + c4 * 4);
            *(float4*)(Ps + r * ATP + c4 * 4) = bv;
        }
        __syncthreads();

        float sacc[2][2][4];
        #pragma unroll
        for (int mt = 0; mt < 2; mt++)
            #pragma unroll
            for (int nt = 0; nt < 2; nt++)
                #pragma unroll
                for (int r = 0; r < 4; r++) sacc[mt][nt][r] = 0.f;
        #pragma unroll
        for (int ks = 0; ks < 6; ks++) {
            int kb = ks * 8;
            unsigned af[2][4];
            #pragma unroll
            for (int mt = 0; mt < 2; mt++) ldsm_x4(af[mt], qaddr[mt] + kb * 4);
            #pragma unroll
            for (int nt = 0; nt < 2; nt++) {
                unsigned b0, b1;
                ldsm_x2(b0, b1, kaddr[nt] + kb * 4);
                #pragma unroll
                for (int mt = 0; mt < 2; mt++)
                    mma_tf32(sacc[mt][nt], af[mt], b0, b1);
            }
        }
        #pragma unroll
        for (int mt = 0; mt < 2; mt++) {
            #pragma unroll
            for (int nt = 0; nt < 2; nt++) {
                int r = mbS + mt * 16 + gid;
                int c = nbS + nt * 8 + 2 * tig;
                float* p0 = Ps + r * ATP + c;
                float* p1 = Ps + (r + 8) * ATP + c;
                p0[0] += sacc[mt][nt][0];
                p0[1] += sacc[mt][nt][1];
                p1[0] += sacc[mt][nt][2];
                p1[1] += sacc[mt][nt][3];
            }
        }
        __syncthreads();

        // online softmax: 4 lanes per query row, stride-4 interleave; store P as tf32 bits
        {
            int qq = t >> 2, pp = t & 3;
            float* prow = Ps + qq * ATP + pp;
            float tmax = -1e30f;
            #pragma unroll
            for (int jj = 0; jj < 16; jj++) tmax = fmaxf(tmax, prow[jj * 4]);
            tmax = fmaxf(tmax, __shfl_xor_sync(0xffffffffu, tmax, 1));
            tmax = fmaxf(tmax, __shfl_xor_sync(0xffffffffu, tmax, 2));
            float mold = Ms[qq];
            float mnew = fmaxf(mold, tmax);
            float tsum = 0.f;
            #pragma unroll
            for (int jj = 0; jj < 16; jj++) {
                float p = __expf(prow[jj * 4] - mnew);
                tsum += p;
                prow[jj * 4] = __uint_as_float(f2tf(p));
            }
            tsum += __shfl_xor_sync(0xffffffffu, tsum, 1);
            tsum += __shfl_xor_sync(0xffffffffu, tsum, 2);
            if (pp == 0) {
                float scl = __expf(mold - mnew);
                Ss[qq] = scl;
                Ls[qq] = Ls[qq] * scl + tsum;
                Ms[qq] = mnew;
            }
        }
        __syncthreads();

        // rescale + O += P @ V via mma (P frag via ldmatrix)
        {
            float s0 = Ss[mbP + gid], s1 = Ss[mbP + gid + 8];
            #pragma unroll
            for (int nt = 0; nt < 3; nt++) {
                oacc[nt][0] *= s0; oacc[nt][1] *= s0;
                oacc[nt][2] *= s1; oacc[nt][3] *= s1;
            }
            #pragma unroll
            for (int ks = 0; ks < 8; ks++) {
                int kb = ks * 8;
                unsigned af[4];
                ldsm_x4(af, paddr + kb * 4);
                #pragma unroll
                for (int nt = 0; nt < 3; nt++) {
                    unsigned b0 = Vs[(kb + tig) * AVQ + nbP + nt * 8 + gid];
                    unsigned b1 = Vs[(kb + tig + 4) * AVQ + nbP + nt * 8 + gid];
                    mma_tf32(oacc[nt], af, b0, b1);
                }
            }
        }
    }

    // epilogue: normalize, gate, write
    __syncthreads();
    float inv0 = 1.f / Ls[mbP + gid];
    float inv1 = 1.f / Ls[mbP + gid + 8];
    size_t row0 = (size_t)(b * NN + q0 + mbP + gid);
    size_t row1 = row0 + 8;
    #pragma unroll
    for (int nt = 0; nt < 3; nt++) {
        int c = hh * HD + nbP + nt * 8 + 2 * tig;
        size_t i00 = row0 * CT + c;
        size_t i10 = row1 * CT + c;
        float g00 = 1.f / (1.f + __expf(-gate[i00]));
        float g01 = 1.f / (1.f + __expf(-gate[i00 + 1]));
        float g10 = 1.f / (1.f + __expf(-gate[i10]));
        float g11 = 1.f / (1.f + __expf(-gate[i10 + 1]));
        o[i00]     = g00 * oacc[nt][0] * inv0;
        o[i00 + 1] = g01 * oacc[nt][1] * inv0;
        o[i10]     = g10 * oacc[nt][2] * inv1;
        o[i10 + 1] = g11 * oacc[nt][3] * inv1;
    }
}

// ---------------- launch ----------------
static float* symaddr(const void* sym) {
    void* p = nullptr;
    cudaGetSymbolAddress(&p, sym);
    return (float*)p;
}

extern "C" void kernel_launch(void* const* d_in, const int* in_sizes, int n_in,
                              void* d_out, int out_size) {
    const float* a    = (const float*)d_in[0];
    const float* s    = (const float*)d_in[1];
    const float* z    = (const float*)d_in[2];
    const float* bm   = (const float*)d_in[3];
    const float* Wg   = (const float*)d_in[4];
    const float* bg   = (const float*)d_in[5];
    const float* Wb   = (const float*)d_in[6];
    const float* Wq   = (const float*)d_in[7];
    const float* bq   = (const float*)d_in[8];
    const float* Wk   = (const float*)d_in[9];
    const float* Wv   = (const float*)d_in[10];
    const float* Wpb  = (const float*)d_in[11];
    const float* png  = (const float*)d_in[12];
    const float* pnb  = (const float*)d_in[13];
    const float* Wgt  = (const float*)d_in[14];
    const float* Wout = (const float*)d_in[15];
    const float* Wog  = (const float*)d_in[16];
    const float* bog  = (const float*)d_in[17];
    float* out = (float*)d_out;

    float* aln   = symaddr(g_aln);
    float* sln   = symaddr(g_sln);
    float* tmpb  = symaddr(g_tmpb);
    float* anorm = symaddr(g_anorm);
    float* qb    = symaddr(g_q);
    float* kb    = symaddr(g_k);
    float* vb    = symaddr(g_v);
    float* gateb = symaddr(g_gate);
    float* ogb   = symaddr(g_og);
    float* ob    = symaddr(g_o);
    float* pbb   = symaddr(g_pb);
    float* wq    = symaddr(g_wq);
    float* wk    = symaddr(g_wk);
    float* wv    = symaddr(g_wv);
    float* wgt   = symaddr(g_wgt);
    float* wb    = symaddr(g_wb);
    float* wg    = symaddr(g_wg);
    float* wog   = symaddr(g_wog);
    float* srnd  = symaddr(g_srnd);

    cudaFuncSetAttribute(gemm128_kernel, cudaFuncAttributeMaxDynamicSharedMemorySize, GEMM_SMEM);
    cudaFuncSetAttribute(pair_kernel, cudaFuncAttributeMaxDynamicSharedMemorySize, PAIR_SMEM);
    cudaFuncSetAttribute(attn_kernel, cudaFuncAttributeMaxDynamicSharedMemorySize, ATTN_SMEM);

    // pre-round GEMM operands to tf32 values (once)
    {
        RoundArgs ra = {};
        ra.j[0] = { Wq,  wq,  CT * CT / 4 };
        ra.j[1] = { Wk,  wk,  CT * CT / 4 };
        ra.j[2] = { Wv,  wv,  CT * CT / 4 };
        ra.j[3] = { Wgt, wgt, CT * CT / 4 };
        ra.j[4] = { Wb,  wb,  CS * CT / 4 };
        ra.j[5] = { Wg,  wg,  CS * CT / 4 };
        ra.j[6] = { Wog, wog, CS * CT / 4 };
        ra.j[7] = { s,   srnd, ROWS * CS / 4 };
        round_kernel<<<dim3(144, 8), 256>>>(ra);
    }

    // fused LayerNorms (sln rounded to tf32)
    ln2_kernel<<<dim3(ROWS, 2), 256>>>(a, s, aln, sln);

    // batch 1: adaLN gate (sigmoid), adaLN bias-proj, output-gate (sigmoid) — K=384
    {
        GemmBatchArgs p = {};
        p.j[0] = { sln,  wb,  tmpb,  nullptr, nullptr, nullptr, CS, 0 };
        p.j[1] = { sln,  wg,  anorm, bg,      nullptr, nullptr, CS, 1 };   // gsig
        p.j[2] = { srnd, wog, ogb,   bog,     nullptr, nullptr, CS, 1 };
        gemm128_kernel<<<dim3(CT / 128, ROWS / 128, 3), 256, GEMM_SMEM>>>(p, ROWS, CT);
    }
    // anorm = round_tf32(gsig * aln + tmpb)
    combine_kernel<<<ROWS * CT / 4 / 256, 256>>>(anorm, aln, tmpb);

    // batch 2: Q/K/V/gate — shared A, K=768
    {
        GemmBatchArgs p = {};
        p.j[0] = { anorm, wq,  qb,    bq,      nullptr, nullptr, CT, 0 };
        p.j[1] = { anorm, wk,  kb,    nullptr, nullptr, nullptr, CT, 0 };
        p.j[2] = { anorm, wv,  vb,    nullptr, nullptr, nullptr, CT, 0 };
        p.j[3] = { anorm, wgt, gateb, nullptr, nullptr, nullptr, CT, 0 };
        gemm128_kernel<<<dim3(CT / 128, ROWS / 128, 4), 256, GEMM_SMEM>>>(p, ROWS, CT);
    }

    // pair bias (incl. bias_mask)
    pair_kernel<<<dim3(NN / PJT, ROWS), 256, PAIR_SMEM>>>(z, bm, Wpb, png, pnb, pbb);
    // attention + gating
    attn_kernel<<<dim3(NN / 64, NH, BB), 256, ATTN_SMEM>>>(qb, kb, vb, gateb, pbb, ob);

    // output projection with output-gate multiply — BM=64 for 288 CTAs
    {
        GemmBatchArgs p = {};
        p.j[0] = { ob, Wout, out, nullptr, ogb, nullptr, CT, 0 };
        gemm_batch_kernel<64><<<dim3(CT / 64, ROWS / 64, 1), 256>>>(p, ROWS, CT);
    }
}

// round 14
// speedup vs baseline: 3.6705x; 1.0848x over previous
#include <cuda_runtime.h>
#include <math.h>

#define BB 2
#define NN 768
#define CT 768
#define CS 384
#define CP 128
#define NH 16
#define HD 48
#define ROWS (BB*NN)   /* 1536 */

// ---------------- scratch (device globals; no allocation allowed) ----------------
__device__ float g_aln  [ROWS*CT];
__device__ float g_sln  [ROWS*CS];
__device__ float g_tmpb [ROWS*CT];
__device__ float g_anorm[ROWS*CT];
__device__ float g_q    [ROWS*CT];
__device__ float g_k    [ROWS*CT];
__device__ float g_v    [ROWS*CT];
__device__ float g_gate [ROWS*CT];
__device__ float g_og   [ROWS*CT];
__device__ float g_o    [ROWS*CT];
__device__ float g_pb   [BB*NH*NN*NN];   // 75.5 MB pair bias [b,h,i,j]
// pre-rounded (tf32-valued fp32) operands
__device__ float g_wq [CT*CT];
__device__ float g_wk [CT*CT];
__device__ float g_wv [CT*CT];
__device__ float g_wgt[CT*CT];
__device__ float g_wb [CS*CT];
__device__ float g_wg [CS*CT];
__device__ float g_wog[CS*CT];
__device__ float g_srnd[ROWS*CS];

// ---------------- tf32 / mma / ldmatrix / cp.async helpers ----------------
__device__ __forceinline__ unsigned f2tf(float f) {
    unsigned u;
    asm("cvt.rna.tf32.f32 %0, %1;" : "=r"(u) : "f"(f));
    return u;
}
__device__ __forceinline__ void mma_tf32(float* c, const unsigned* a, unsigned b0, unsigned b1) {
    asm volatile(
        "mma.sync.aligned.m16n8k8.row.col.f32.tf32.tf32.f32 "
        "{%0,%1,%2,%3}, {%4,%5,%6,%7}, {%8,%9}, {%0,%1,%2,%3};\n"
        : "+f"(c[0]), "+f"(c[1]), "+f"(c[2]), "+f"(c[3])
        : "r"(a[0]), "r"(a[1]), "r"(a[2]), "r"(a[3]), "r"(b0), "r"(b1));
}
__device__ __forceinline__ unsigned smem_u32(const void* p) {
    return (unsigned)__cvta_generic_to_shared(p);
}
__device__ __forceinline__ void ldsm_x4(unsigned* r, unsigned a) {
    asm volatile("ldmatrix.sync.aligned.m8n8.x4.shared.b16 {%0,%1,%2,%3}, [%4];"
        : "=r"(r[0]), "=r"(r[1]), "=r"(r[2]), "=r"(r[3]) : "r"(a));
}
__device__ __forceinline__ void ldsm_x2(unsigned& r0, unsigned& r1, unsigned a) {
    asm volatile("ldmatrix.sync.aligned.m8n8.x2.shared.b16 {%0,%1}, [%2];"
        : "=r"(r0), "=r"(r1) : "r"(a));
}
__device__ __forceinline__ void cp16(unsigned saddr, const void* g) {
    asm volatile("cp.async.cg.shared.global [%0], [%1], 16;" :: "r"(saddr), "l"(g));
}
#define CP_COMMIT() asm volatile("cp.async.commit_group;")
#define CP_WAIT1()  asm volatile("cp.async.wait_group 1;")
#define CP_WAIT0()  asm volatile("cp.async.wait_group 0;")

// ---------------- pre-round weights / s to tf32-valued fp32 ----------------
struct RoundJob { const float* src; float* dst; int n4; };
struct RoundArgs { RoundJob j[8]; };
__global__ void __launch_bounds__(256) round_kernel(RoundArgs ra) {
    RoundJob jb = ra.j[blockIdx.y];
    for (int i = blockIdx.x * 256 + threadIdx.x; i < jb.n4; i += gridDim.x * 256) {
        float4 v = ((const float4*)jb.src)[i];
        uint4 o = make_uint4(f2tf(v.x), f2tf(v.y), f2tf(v.z), f2tf(v.w));
        ((uint4*)jb.dst)[i] = o;
    }
}

// ---------------- fused LayerNorms (no affine); s-branch output rounded to tf32 ----------------
__device__ __forceinline__ float2 blockReduce2(float a, float b) {
    #pragma unroll
    for (int o = 16; o; o >>= 1) {
        a += __shfl_xor_sync(0xffffffffu, a, o);
        b += __shfl_xor_sync(0xffffffffu, b, o);
    }
    __shared__ float sa[8], sb[8];
    int w = threadIdx.x >> 5, l = threadIdx.x & 31;
    if (l == 0) { sa[w] = a; sb[w] = b; }
    __syncthreads();
    if (w == 0) {
        a = (l < 8) ? sa[l] : 0.f;
        b = (l < 8) ? sb[l] : 0.f;
        #pragma unroll
        for (int o = 4; o; o >>= 1) {
            a += __shfl_xor_sync(0xffffffffu, a, o);
            b += __shfl_xor_sync(0xffffffffu, b, o);
        }
        if (l == 0) { sa[0] = a; sb[0] = b; }
    }
    __syncthreads();
    return make_float2(sa[0], sb[0]);
}

__global__ void __launch_bounds__(256) ln2_kernel(
    const float* __restrict__ a, const float* __restrict__ s,
    float* __restrict__ aout, float* __restrict__ sout)
{
    int isS = (blockIdx.y != 0);
    int C = isS ? CS : CT;
    const float* in = isS ? s : a;
    float* out = isS ? sout : aout;
    int r = blockIdx.x;
    const float* x = in + (size_t)r * C;
    float sm = 0.f, sq = 0.f;
    for (int c = threadIdx.x; c < C; c += 256) { float v = x[c]; sm += v; sq += v * v; }
    float2 red = blockReduce2(sm, sq);
    float mean = red.x / C;
    float inv = rsqrtf(red.y / C - mean * mean + 1e-5f);
    float* y = out + (size_t)r * C;
    for (int c = threadIdx.x; c < C; c += 256) {
        float v = (x[c] - mean) * inv;
        y[c] = isS ? __uint_as_float(f2tf(v)) : v;   // sln feeds GEMM A -> pre-round
    }
}

// ---------------- GEMM jobs ----------------
struct GemmJob {
    const float* A; const float* B; float* C;
    const float* bias; const float* mul; const float* add;
    int K; int sig; int rnd; float scale;
};
struct GemmBatchArgs { GemmJob j[4]; };

// ============ 128x128x16 tf32 GEMM, cp.async 3-stage pipeline, ldmatrix A-frags ============
#define AST 20
#define BST 136
#define ABUF (128*AST)
#define BBUF (16*BST)
#define GEMM_SMEM (3*(ABUF+BBUF)*4)   /* 56832 B */

__global__ void __launch_bounds__(256, 2) gemm128_kernel(GemmBatchArgs p, int M, int N) {
    const GemmJob jb = p.j[blockIdx.z];
    const float* __restrict__ A = jb.A;
    const float* __restrict__ B = jb.B;
    const int K = jb.K;

    extern __shared__ unsigned smg[];
    unsigned* As = smg;               // 3 x [128][AST]
    unsigned* Bs = smg + 3 * ABUF;    // 3 x [16][BST]

    int t = threadIdx.x, w = t >> 5, lane = t & 31;
    int gid = lane >> 2, tig = lane & 3;
    int wm = w >> 2, wn = w & 3;
    int m0 = blockIdx.y * 128, n0 = blockIdx.x * 128;
    int mw = wm * 64, nw = wn * 32;

    float acc[4][4][4];
    #pragma unroll
    for (int mt = 0; mt < 4; mt++)
        #pragma unroll
        for (int nt = 0; nt < 4; nt++)
            #pragma unroll
            for (int r = 0; r < 4; r++) acc[mt][nt][r] = 0.f;

    int arow[2], akq[2], brow[2], bc4[2];
    unsigned sa[2], sb[2];
    #pragma unroll
    for (int i = 0; i < 2; i++) {
        int idx = t + i * 256;
        arow[i] = idx >> 2; akq[i] = idx & 3;
        brow[i] = idx >> 5; bc4[i] = idx & 31;
        sa[i] = smem_u32(As) + (unsigned)((arow[i] * AST + akq[i] * 4) * 4);
        sb[i] = smem_u32(As) + (unsigned)((3 * ABUF + brow[i] * BST + bc4[i] * 4) * 4);
    }

    unsigned aBase = smem_u32(As);
    int lrow = lane & 15, lkq = lane >> 4;
    unsigned a_addr[4];
    #pragma unroll
    for (int mt = 0; mt < 4; mt++)
        a_addr[mt] = aBase + (unsigned)(((mw + mt * 16 + lrow) * AST + lkq * 4) * 4);

    int nchunk = K / 16;
    #pragma unroll
    for (int st = 0; st < 2; st++) {
        #pragma unroll
        for (int i = 0; i < 2; i++) {
            cp16(sa[i] + st * (ABUF * 4), A + (size_t)(m0 + arow[i]) * K + st * 16 + akq[i] * 4);
            cp16(sb[i] + st * (BBUF * 4), B + (size_t)(st * 16 + brow[i]) * N + n0 + bc4[i] * 4);
        }
        CP_COMMIT();
    }

    for (int ch = 0; ch < nchunk; ch++) {
        int stage = ch % 3;
        CP_WAIT1();
        __syncthreads();
        if (ch + 2 < nchunk) {
            int k0 = (ch + 2) * 16;
            int st = (ch + 2) % 3;
            #pragma unroll
            for (int i = 0; i < 2; i++) {
                cp16(sa[i] + st * (ABUF * 4), A + (size_t)(m0 + arow[i]) * K + k0 + akq[i] * 4);
                cp16(sb[i] + st * (BBUF * 4), B + (size_t)(k0 + brow[i]) * N + n0 + bc4[i] * 4);
            }
        }
        CP_COMMIT();

        unsigned aOff = stage * (ABUF * 4);
        const unsigned* BsC = Bs + stage * BBUF;
        #pragma unroll
        for (int ks = 0; ks < 2; ks++) {
            int kb = ks * 8;
            unsigned af[4][4];
            #pragma unroll
            for (int mt = 0; mt < 4; mt++) ldsm_x4(af[mt], a_addr[mt] + aOff + kb * 4);
            unsigned bf[4][2];
            #pragma unroll
            for (int nt = 0; nt < 4; nt++) {
                bf[nt][0] = BsC[(kb + tig) * BST + nw + nt * 8 + gid];
                bf[nt][1] = BsC[(kb + tig + 4) * BST + nw + nt * 8 + gid];
            }
            #pragma unroll
            for (int mt = 0; mt < 4; mt++)
                #pragma unroll
                for (int nt = 0; nt < 4; nt++)
                    mma_tf32(acc[mt][nt], af[mt], bf[nt][0], bf[nt][1]);
        }
    }

    // epilogue
    const float* bias = jb.bias;
    const float* mul = jb.mul;
    const float* add = jb.add;
    int do_sig = jb.sig;
    int do_rnd = jb.rnd;
    float scl = jb.scale;
    float* C = jb.C;
    #pragma unroll
    for (int mt = 0; mt < 4; mt++) {
        #pragma unroll
        for (int nt = 0; nt < 4; nt++) {
            int r0 = m0 + mw + mt * 16 + gid;
            int c0 = n0 + nw + nt * 8 + 2 * tig;
            #pragma unroll
            for (int rr = 0; rr < 2; rr++) {
                int r = r0 + rr * 8;
                #pragma unroll
                for (int cc = 0; cc < 2; cc++) {
                    float v = acc[mt][nt][rr * 2 + cc];
                    int c = c0 + cc;
                    if (bias) v += bias[c];
                    if (do_sig) v = 1.f / (1.f + __expf(-v));
                    size_t ix = (size_t)r * N + c;
                    if (mul) v *= mul[ix];
                    if (add) v += add[ix];
                    v *= scl;
                    C[ix] = do_rnd ? __uint_as_float(f2tf(v)) : v;
                }
            }
        }
    }
}

// ============ 64x64 kernel kept for Wout (needs 288 CTAs) ============
template <int BM>
__global__ void __launch_bounds__(256, 2) gemm_batch_kernel(GemmBatchArgs p, int M, int N) {
    const GemmJob jb = p.j[blockIdx.z];
    const float* __restrict__ A = jb.A;
    const float* __restrict__ B = jb.B;
    const int K = jb.K;
    constexpr int MT = BM / 64;
    constexpr int NLD = BM / 32;

    __shared__ unsigned As[32][BM + 8];
    __shared__ unsigned Bs[32][72];
    int t = threadIdx.x;
    int w = t >> 5, lane = t & 31;
    int gid = lane >> 2, tig = lane & 3;
    int wm = w >> 1, wn = w & 1;
    int m0 = blockIdx.y * BM, n0 = blockIdx.x * 64;
    int mw = wm * (BM / 4), nw = wn * 32;

    float acc[MT][4][4];
    #pragma unroll
    for (int mt = 0; mt < MT; mt++)
        #pragma unroll
        for (int nt = 0; nt < 4; nt++)
            #pragma unroll
            for (int r = 0; r < 4; r++) acc[mt][nt][r] = 0.f;

    int arow[NLD], akb[NLD], brow[2], bc4[2];
    #pragma unroll
    for (int i = 0; i < NLD; i++) { int idx = t + i * 256; arow[i] = idx & (BM - 1); akb[i] = idx / BM; }
    #pragma unroll
    for (int i = 0; i < 2; i++) { int idx = t + i * 256; brow[i] = idx >> 4; bc4[i] = idx & 15; }

    float4 ar[NLD], br[2];
    #pragma unroll
    for (int i = 0; i < NLD; i++)
        ar[i] = *(const float4*)(A + (size_t)(m0 + arow[i]) * K + akb[i] * 4);
    #pragma unroll
    for (int i = 0; i < 2; i++)
        br[i] = *(const float4*)(B + (size_t)brow[i] * N + n0 + bc4[i] * 4);

    int nchunk = K / 32;
    for (int ch = 0; ch < nchunk; ch++) {
        #pragma unroll
        for (int i = 0; i < NLD; i++) {
            As[akb[i] * 4 + 0][arow[i]] = f2tf(ar[i].x);
            As[akb[i] * 4 + 1][arow[i]] = f2tf(ar[i].y);
            As[akb[i] * 4 + 2][arow[i]] = f2tf(ar[i].z);
            As[akb[i] * 4 + 3][arow[i]] = f2tf(ar[i].w);
        }
        #pragma unroll
        for (int i = 0; i < 2; i++) {
            Bs[brow[i]][bc4[i] * 4 + 0] = f2tf(br[i].x);
            Bs[brow[i]][bc4[i] * 4 + 1] = f2tf(br[i].y);
            Bs[brow[i]][bc4[i] * 4 + 2] = f2tf(br[i].z);
            Bs[brow[i]][bc4[i] * 4 + 3] = f2tf(br[i].w);
        }
        __syncthreads();
        if (ch + 1 < nchunk) {
            int k0 = (ch + 1) * 32;
            #pragma unroll
            for (int i = 0; i < NLD; i++)
                ar[i] = *(const float4*)(A + (size_t)(m0 + arow[i]) * K + k0 + akb[i] * 4);
            #pragma unroll
            for (int i = 0; i < 2; i++)
                br[i] = *(const float4*)(B + (size_t)(k0 + brow[i]) * N + n0 + bc4[i] * 4);
        }
        #pragma unroll
        for (int ks = 0; ks < 4; ks++) {
            int kb = ks * 8;
            unsigned af[MT][4];
            #pragma unroll
            for (int mt = 0; mt < MT; mt++) {
                int mb = mw + mt * 16 + gid;
                af[mt][0] = As[kb + tig][mb];
                af[mt][1] = As[kb + tig][mb + 8];
                af[mt][2] = As[kb + tig + 4][mb];
                af[mt][3] = As[kb + tig + 4][mb + 8];
            }
            unsigned bf[4][2];
            #pragma unroll
            for (int nt = 0; nt < 4; nt++) {
                int nb = nw + nt * 8 + gid;
                bf[nt][0] = Bs[kb + tig][nb];
                bf[nt][1] = Bs[kb + tig + 4][nb];
            }
            #pragma unroll
            for (int mt = 0; mt < MT; mt++)
                #pragma unroll
                for (int nt = 0; nt < 4; nt++)
                    mma_tf32(acc[mt][nt], af[mt], bf[nt][0], bf[nt][1]);
        }
        __syncthreads();
    }

    const float* bias = jb.bias;
    const float* mul = jb.mul;
    const float* add = jb.add;
    int do_sig = jb.sig;
    float* C = jb.C;
    #pragma unroll
    for (int mt = 0; mt < MT; mt++) {
        #pragma unroll
        for (int nt = 0; nt < 4; nt++) {
            int r0 = m0 + mw + mt * 16 + gid;
            int c0 = n0 + nw + nt * 8 + 2 * tig;
            #pragma unroll
            for (int rr = 0; rr < 2; rr++) {
                int r = r0 + rr * 8;
                #pragma unroll
                for (int cc = 0; cc < 2; cc++) {
                    float v = acc[mt][nt][rr * 2 + cc];
                    int c = c0 + cc;
                    if (bias) v += bias[c];
                    if (do_sig) v = 1.f / (1.f + __expf(-v));
                    size_t ix = (size_t)r * N + c;
                    if (mul) v *= mul[ix];
                    if (add) v += add[ix];
                    C[ix] = v;
                }
            }
        }
    }
}

// ---------------- elementwise adaLN combine: anorm = round_tf32(gsig*aln + tmpb) ----------------
__global__ void __launch_bounds__(256) combine_kernel(
    float* __restrict__ anorm, const float* __restrict__ aln, const float* __restrict__ tmpb)
{
    int i = blockIdx.x * 256 + threadIdx.x;
    float4 g = ((const float4*)anorm)[i];
    float4 a = ((const float4*)aln)[i];
    float4 tb = ((const float4*)tmpb)[i];
    uint4 o;
    o.x = f2tf(g.x * a.x + tb.x);
    o.y = f2tf(g.y * a.y + tb.y);
    o.z = f2tf(g.z * a.z + tb.z);
    o.w = f2tf(g.w * a.w + tb.w);
    ((uint4*)anorm)[i] = o;
}

// ---------------- pair bias: 512 threads, batched z loads, warp-pair mma split ----------------
#define PJT 128
#define ZST 132
#define WST 24
#define PAIR_SMEM ((PJT*ZST + CP*WST + PJT) * 4)

__global__ void __launch_bounds__(512, 2) pair_kernel(
    const float* __restrict__ z, const float* __restrict__ bmask,
    const float* __restrict__ Wpb, const float* __restrict__ gma,
    const float* __restrict__ bta, float* __restrict__ pb)
{
    extern __shared__ float smp[];
    float* zn = smp;                                  // [128][132] tf32 after LN
    unsigned* Wb = (unsigned*)(smp + PJT * ZST);      // [128][24]
    float* bm_s = smp + PJT * ZST + CP * WST;         // [128]

    int t = threadIdx.x;
    int w = t >> 5, lane = t & 31;
    int gid = lane >> 2, tig = lane & 3;
    int bi = blockIdx.y;
    int b = bi / NN, i = bi % NN;
    int j0 = blockIdx.x * PJT;

    for (int idx = t; idx < CP * NH; idx += 512) {
        int c = idx >> 4, hh = idx & 15;
        Wb[c * WST + hh] = f2tf(Wpb[idx]);
    }
    if (t < PJT) bm_s[t] = bmask[(size_t)bi * NN + j0 + t];

    float4 gv = *(const float4*)(gma + lane * 4);
    float4 bv = *(const float4*)(bta + lane * 4);

    // LN: warp w (0..15) handles rows w*8..w*8+7, in 2 batches of 4 (MLP=4)
    const float* zrow = z + ((size_t)bi * NN + j0) * CP;
    #pragma unroll
    for (int rb = 0; rb < 2; rb++) {
        float4 vz[4];
        #pragma unroll
        for (int u = 0; u < 4; u++) {
            int r = w * 8 + rb * 4 + u;
            vz[u] = *(const float4*)(zrow + (size_t)r * CP + lane * 4);
        }
        #pragma unroll
        for (int u = 0; u < 4; u++) {
            int r = w * 8 + rb * 4 + u;
            float4 v = vz[u];
            float s = v.x + v.y + v.z + v.w;
            float sq = v.x * v.x + v.y * v.y + v.z * v.z + v.w * v.w;
            #pragma unroll
            for (int o = 16; o; o >>= 1) {
                s  += __shfl_xor_sync(0xffffffffu, s, o);
                sq += __shfl_xor_sync(0xffffffffu, sq, o);
            }
            float mean = s * (1.f / CP);
            float inv = rsqrtf(sq * (1.f / CP) - mean * mean + 1e-5f);
            uint4 outv;
            outv.x = f2tf((v.x - mean) * inv * gv.x + bv.x);
            outv.y = f2tf((v.y - mean) * inv * gv.y + bv.y);
            outv.z = f2tf((v.z - mean) * inv * gv.z + bv.z);
            outv.w = f2tf((v.w - mean) * inv * gv.w + bv.w);
            *(uint4*)(zn + r * ZST + lane * 4) = outv;
        }
    }
    __syncthreads();

    // mma: warp pair (w&7) shares 16 rows; w>>3 selects 8-head group
    int mb = (w & 7) * 16;
    int nth = w >> 3;
    unsigned zBase = smem_u32(zn);
    int lrow = lane & 15, lkq = lane >> 4;
    unsigned z_addr = zBase + (unsigned)(((mb + lrow) * ZST + lkq * 4) * 4);
    float c2[4] = {0.f, 0.f, 0.f, 0.f};
    #pragma unroll
    for (int ks = 0; ks < 16; ks++) {
        int kb = ks * 8;
        unsigned af[4];
        ldsm_x4(af, z_addr + kb * 4);
        unsigned b0 = Wb[(kb + tig) * WST + nth * 8 + gid];
        unsigned b1 = Wb[(kb + tig + 4) * WST + nth * 8 + gid];
        mma_tf32(c2, af, b0, b1);
    }
    float bm0 = bm_s[mb + gid], bm1 = bm_s[mb + gid + 8];
    int jg0 = j0 + mb + gid;
    {
        int h0 = nth * 8 + 2 * tig;
        size_t base0 = ((size_t)(b * NH + h0) * NN + i) * NN;
        size_t base1 = ((size_t)(b * NH + h0 + 1) * NN + i) * NN;
        pb[base0 + jg0]     = c2[0] + bm0;
        pb[base1 + jg0]     = c2[1] + bm0;
        pb[base0 + jg0 + 8] = c2[2] + bm1;
        pb[base1 + jg0 + 8] = c2[3] + bm1;
    }
}

// ---------------- attention: flash-style, cp.async raw staging (q/k/v pre-rounded) ----------------
#define ATQ 52
#define AVQ 56
#define ATP 68
#define ATTN_SMEM ((2*64*ATQ + 64*AVQ + 64*ATP + 3*64) * 4)

__global__ void __launch_bounds__(256, 3) attn_kernel(
    const float* __restrict__ q, const float* __restrict__ k,
    const float* __restrict__ v, const float* __restrict__ gate,
    const float* __restrict__ pb, float* __restrict__ o)
{
    extern __shared__ float sm[];
    unsigned* Qs = (unsigned*)sm;           // [64][52] tf32 (pre-scaled by 1/sqrt(d))
    unsigned* Ks = Qs + 64 * ATQ;           // [64][52] tf32
    unsigned* Vs = Ks + 64 * ATQ;           // [64][56] tf32
    float* Ps = (float*)(Vs + 64 * AVQ);    // [64][68]
    float* Ms = Ps + 64 * ATP;
    float* Ls = Ms + 64;
    float* Ss = Ls + 64;

    int qt = blockIdx.x, hh = blockIdx.y, b = blockIdx.z;
    int t = threadIdx.x;
    int w = t >> 5, lane = t & 31;
    int gid = lane >> 2, tig = lane & 3;
    int q0 = qt * 64;

    unsigned qsm = smem_u32(Qs), ksm = smem_u32(Ks), vsm = smem_u32(Vs), psm = smem_u32(Ps);

    // Q staging: raw cp.async (q already tf32-rounded and scaled in GEMM epilogue)
    #pragma unroll
    for (int it = 0; it < 3; it++) {
        int idx = t + it * 256;
        int r = idx / 12, d4 = idx % 12;
        cp16(qsm + (unsigned)((r * ATQ + d4 * 4) * 4),
             q + ((size_t)(b * NN + q0 + r)) * CT + hh * HD + d4 * 4);
    }
    if (t < 64) { Ms[t] = -1e30f; Ls[t] = 0.f; }

    int wmS = w >> 2, wnS = w & 3;
    int mbS = wmS * 32, nbS = wnS * 16;
    int wmP = w >> 1, wnP = w & 1;
    int mbP = wmP * 16, nbP = wnP * 24;

    int lrow = lane & 15, lkq = lane >> 4;
    unsigned qaddr[2];
    #pragma unroll
    for (int mt = 0; mt < 2; mt++)
        qaddr[mt] = qsm + (unsigned)(((mbS + mt * 16 + lrow) * ATQ + lkq * 4) * 4);
    unsigned kaddr[2];
    #pragma unroll
    for (int nt = 0; nt < 2; nt++)
        kaddr[nt] = ksm + (unsigned)(((nbS + nt * 8 + (lane & 7)) * ATQ + ((lane >> 3) & 1) * 4) * 4);
    unsigned paddr = psm + (unsigned)(((mbP + lrow) * ATP + lkq * 4) * 4);

    float oacc[3][4];
    #pragma unroll
    for (int nt = 0; nt < 3; nt++)
        #pragma unroll
        for (int r = 0; r < 4; r++) oacc[nt][r] = 0.f;

    const float* bp0 = pb + ((size_t)(b * NH + hh) * NN + q0) * NN;

    for (int kt = 0; kt < 12; kt++) {
        int k0 = kt * 64;
        __syncthreads();
        // raw cp.async staging: K, V (pre-rounded tf32), bias tile (fp32)
        #pragma unroll
        for (int it = 0; it < 3; it++) {
            int idx = t + it * 256;
            int r = idx / 12, d4 = idx % 12;
            size_t gi = ((size_t)(b * NN + k0 + r)) * CT + hh * HD + d4 * 4;
            cp16(ksm + (unsigned)((r * ATQ + d4 * 4) * 4), k + gi);
            cp16(vsm + (unsigned)((r * AVQ + d4 * 4) * 4), v + gi);
        }
        #pragma unroll
        for (int it = 0; it < 4; it++) {
            int idx = t + it * 256;
            int r = idx >> 4, c4 = idx & 15;
            cp16(psm + (unsigned)((r * ATP + c4 * 4) * 4), bp0 + (size_t)r * NN + k0 + c4 * 4);
        }
        CP_COMMIT();
        CP_WAIT0();
        __syncthreads();

        float sacc[2][2][4];
        #pragma unroll
        for (int mt = 0; mt < 2; mt++)
            #pragma unroll
            for (int nt = 0; nt < 2; nt++)
                #pragma unroll
                for (int r = 0; r < 4; r++) sacc[mt][nt][r] = 0.f;
        #pragma unroll
        for (int ks = 0; ks < 6; ks++) {
            int kb = ks * 8;
            unsigned af[2][4];
            #pragma unroll
            for (int mt = 0; mt < 2; mt++) ldsm_x4(af[mt], qaddr[mt] + kb * 4);
            #pragma unroll
            for (int nt = 0; nt < 2; nt++) {
                unsigned b0, b1;
                ldsm_x2(b0, b1, kaddr[nt] + kb * 4);
                #pragma unroll
                for (int mt = 0; mt < 2; mt++)
                    mma_tf32(sacc[mt][nt], af[mt], b0, b1);
            }
        }
        #pragma unroll
        for (int mt = 0; mt < 2; mt++) {
            #pragma unroll
            for (int nt = 0; nt < 2; nt++) {
                int r = mbS + mt * 16 + gid;
                int c = nbS + nt * 8 + 2 * tig;
                float* p0 = Ps + r * ATP + c;
                float* p1 = Ps + (r + 8) * ATP + c;
                p0[0] += sacc[mt][nt][0];
                p0[1] += sacc[mt][nt][1];
                p1[0] += sacc[mt][nt][2];
                p1[1] += sacc[mt][nt][3];
            }
        }
        __syncthreads();

        // online softmax: 4 lanes per query row, stride-4 interleave; store P as tf32 bits
        {
            int qq = t >> 2, pp = t & 3;
            float* prow = Ps + qq * ATP + pp;
            float tmax = -1e30f;
            #pragma unroll
            for (int jj = 0; jj < 16; jj++) tmax = fmaxf(tmax, prow[jj * 4]);
            tmax = fmaxf(tmax, __shfl_xor_sync(0xffffffffu, tmax, 1));
            tmax = fmaxf(tmax, __shfl_xor_sync(0xffffffffu, tmax, 2));
            float mold = Ms[qq];
            float mnew = fmaxf(mold, tmax);
            float tsum = 0.f;
            #pragma unroll
            for (int jj = 0; jj < 16; jj++) {
                float p = __expf(prow[jj * 4] - mnew);
                tsum += p;
                prow[jj * 4] = __uint_as_float(f2tf(p));
            }
            tsum += __shfl_xor_sync(0xffffffffu, tsum, 1);
            tsum += __shfl_xor_sync(0xffffffffu, tsum, 2);
            if (pp == 0) {
                float scl = __expf(mold - mnew);
                Ss[qq] = scl;
                Ls[qq] = Ls[qq] * scl + tsum;
                Ms[qq] = mnew;
            }
        }
        __syncthreads();

        // rescale + O += P @ V via mma (P frag via ldmatrix)
        {
            float s0 = Ss[mbP + gid], s1 = Ss[mbP + gid + 8];
            #pragma unroll
            for (int nt = 0; nt < 3; nt++) {
                oacc[nt][0] *= s0; oacc[nt][1] *= s0;
                oacc[nt][2] *= s1; oacc[nt][3] *= s1;
            }
            #pragma unroll
            for (int ks = 0; ks < 8; ks++) {
                int kb = ks * 8;
                unsigned af[4];
                ldsm_x4(af, paddr + kb * 4);
                #pragma unroll
                for (int nt = 0; nt < 3; nt++) {
                    unsigned b0 = Vs[(kb + tig) * AVQ + nbP + nt * 8 + gid];
                    unsigned b1 = Vs[(kb + tig + 4) * AVQ + nbP + nt * 8 + gid];
                    mma_tf32(oacc[nt], af, b0, b1);
                }
            }
        }
    }

    // epilogue: normalize, gate, write
    __syncthreads();
    float inv0 = 1.f / Ls[mbP + gid];
    float inv1 = 1.f / Ls[mbP + gid + 8];
    size_t row0 = (size_t)(b * NN + q0 + mbP + gid);
    size_t row1 = row0 + 8;
    #pragma unroll
    for (int nt = 0; nt < 3; nt++) {
        int c = hh * HD + nbP + nt * 8 + 2 * tig;
        size_t i00 = row0 * CT + c;
        size_t i10 = row1 * CT + c;
        float g00 = 1.f / (1.f + __expf(-gate[i00]));
        float g01 = 1.f / (1.f + __expf(-gate[i00 + 1]));
        float g10 = 1.f / (1.f + __expf(-gate[i10]));
        float g11 = 1.f / (1.f + __expf(-gate[i10 + 1]));
        o[i00]     = g00 * oacc[nt][0] * inv0;
        o[i00 + 1] = g01 * oacc[nt][1] * inv0;
        o[i10]     = g10 * oacc[nt][2] * inv1;
        o[i10 + 1] = g11 * oacc[nt][3] * inv1;
    }
}

// ---------------- launch ----------------
static float* symaddr(const void* sym) {
    void* p = nullptr;
    cudaGetSymbolAddress(&p, sym);
    return (float*)p;
}

extern "C" void kernel_launch(void* const* d_in, const int* in_sizes, int n_in,
                              void* d_out, int out_size) {
    const float* a    = (const float*)d_in[0];
    const float* s    = (const float*)d_in[1];
    const float* z    = (const float*)d_in[2];
    const float* bm   = (const float*)d_in[3];
    const float* Wg   = (const float*)d_in[4];
    const float* bg   = (const float*)d_in[5];
    const float* Wb   = (const float*)d_in[6];
    const float* Wq   = (const float*)d_in[7];
    const float* bq   = (const float*)d_in[8];
    const float* Wk   = (const float*)d_in[9];
    const float* Wv   = (const float*)d_in[10];
    const float* Wpb  = (const float*)d_in[11];
    const float* png  = (const float*)d_in[12];
    const float* pnb  = (const float*)d_in[13];
    const float* Wgt  = (const float*)d_in[14];
    const float* Wout = (const float*)d_in[15];
    const float* Wog  = (const float*)d_in[16];
    const float* bog  = (const float*)d_in[17];
    float* out = (float*)d_out;

    float* aln   = symaddr(g_aln);
    float* sln   = symaddr(g_sln);
    float* tmpb  = symaddr(g_tmpb);
    float* anorm = symaddr(g_anorm);
    float* qb    = symaddr(g_q);
    float* kb    = symaddr(g_k);
    float* vb    = symaddr(g_v);
    float* gateb = symaddr(g_gate);
    float* ogb   = symaddr(g_og);
    float* ob    = symaddr(g_o);
    float* pbb   = symaddr(g_pb);
    float* wq    = symaddr(g_wq);
    float* wk    = symaddr(g_wk);
    float* wv    = symaddr(g_wv);
    float* wgt   = symaddr(g_wgt);
    float* wb    = symaddr(g_wb);
    float* wg    = symaddr(g_wg);
    float* wog   = symaddr(g_wog);
    float* srnd  = symaddr(g_srnd);

    const float SC = 0.14433756729740643f;  // 1/sqrt(48)

    cudaFuncSetAttribute(gemm128_kernel, cudaFuncAttributeMaxDynamicSharedMemorySize, GEMM_SMEM);
    cudaFuncSetAttribute(pair_kernel, cudaFuncAttributeMaxDynamicSharedMemorySize, PAIR_SMEM);
    cudaFuncSetAttribute(attn_kernel, cudaFuncAttributeMaxDynamicSharedMemorySize, ATTN_SMEM);

    // pre-round GEMM operands to tf32 values (once)
    {
        RoundArgs ra = {};
        ra.j[0] = { Wq,  wq,  CT * CT / 4 };
        ra.j[1] = { Wk,  wk,  CT * CT / 4 };
        ra.j[2] = { Wv,  wv,  CT * CT / 4 };
        ra.j[3] = { Wgt, wgt, CT * CT / 4 };
        ra.j[4] = { Wb,  wb,  CS * CT / 4 };
        ra.j[5] = { Wg,  wg,  CS * CT / 4 };
        ra.j[6] = { Wog, wog, CS * CT / 4 };
        ra.j[7] = { s,   srnd, ROWS * CS / 4 };
        round_kernel<<<dim3(144, 8), 256>>>(ra);
    }

    // fused LayerNorms (sln rounded to tf32)
    ln2_kernel<<<dim3(ROWS, 2), 256>>>(a, s, aln, sln);

    // batch 1: adaLN gate (sigmoid), adaLN bias-proj, output-gate (sigmoid) — K=384
    {
        GemmBatchArgs p = {};
        p.j[0] = { sln,  wb,  tmpb,  nullptr, nullptr, nullptr, CS, 0, 0, 1.f };
        p.j[1] = { sln,  wg,  anorm, bg,      nullptr, nullptr, CS, 1, 0, 1.f };   // gsig
        p.j[2] = { srnd, wog, ogb,   bog,     nullptr, nullptr, CS, 1, 0, 1.f };
        gemm128_kernel<<<dim3(CT / 128, ROWS / 128, 3), 256, GEMM_SMEM>>>(p, ROWS, CT);
    }
    // anorm = round_tf32(gsig * aln + tmpb)
    combine_kernel<<<ROWS * CT / 4 / 256, 256>>>(anorm, aln, tmpb);

    // batch 2: Q/K/V/gate — shared A, K=768; q scaled+rounded, k/v rounded in epilogue
    {
        GemmBatchArgs p = {};
        p.j[0] = { anorm, wq,  qb,    bq,      nullptr, nullptr, CT, 0, 1, SC  };
        p.j[1] = { anorm, wk,  kb,    nullptr, nullptr, nullptr, CT, 0, 1, 1.f };
        p.j[2] = { anorm, wv,  vb,    nullptr, nullptr, nullptr, CT, 0, 1, 1.f };
        p.j[3] = { anorm, wgt, gateb, nullptr, nullptr, nullptr, CT, 0, 0, 1.f };
        gemm128_kernel<<<dim3(CT / 128, ROWS / 128, 4), 256, GEMM_SMEM>>>(p, ROWS, CT);
    }

    // pair bias (incl. bias_mask)
    pair_kernel<<<dim3(NN / PJT, ROWS), 512, PAIR_SMEM>>>(z, bm, Wpb, png, pnb, pbb);
    // attention + gating
    attn_kernel<<<dim3(NN / 64, NH, BB), 256, ATTN_SMEM>>>(qb, kb, vb, gateb, pbb, ob);

    // output projection with output-gate multiply — BM=64 for 288 CTAs
    {
        GemmBatchArgs p = {};
        p.j[0] = { ob, Wout, out, nullptr, ogb, nullptr, CT, 0, 0, 1.f };
        gemm_batch_kernel<64><<<dim3(CT / 64, ROWS / 64, 1), 256>>>(p, ROWS, CT);
    }
}

// round 15
// speedup vs baseline: 3.6764x; 1.0016x over previous
#include <cuda_runtime.h>
#include <math.h>

#define BB 2
#define NN 768
#define CT 768
#define CS 384
#define CP 128
#define NH 16
#define HD 48
#define ROWS (BB*NN)   /* 1536 */

// ---------------- scratch (device globals; no allocation allowed) ----------------
__device__ float g_aln  [ROWS*CT];
__device__ float g_sln  [ROWS*CS];
__device__ float g_tmpb [ROWS*CT];
__device__ float g_anorm[ROWS*CT];
__device__ float g_q    [ROWS*CT];
__device__ float g_k    [ROWS*CT];
__device__ float g_v    [ROWS*CT];
__device__ float g_gate [ROWS*CT];
__device__ float g_og   [ROWS*CT];
__device__ float g_o    [ROWS*CT];
__device__ float g_pb   [BB*NH*NN*NN];   // 75.5 MB pair bias [b,h,i,j]
// pre-rounded (tf32-valued fp32) operands
__device__ float g_wq [CT*CT];
__device__ float g_wk [CT*CT];
__device__ float g_wv [CT*CT];
__device__ float g_wgt[CT*CT];
__device__ float g_wb [CS*CT];
__device__ float g_wg [CS*CT];
__device__ float g_wog[CS*CT];
__device__ float g_srnd[ROWS*CS];

// ---------------- tf32 / mma / ldmatrix / cp.async helpers ----------------
__device__ __forceinline__ unsigned f2tf(float f) {
    unsigned u;
    asm("cvt.rna.tf32.f32 %0, %1;" : "=r"(u) : "f"(f));
    return u;
}
__device__ __forceinline__ void mma_tf32(float* c, const unsigned* a, unsigned b0, unsigned b1) {
    asm volatile(
        "mma.sync.aligned.m16n8k8.row.col.f32.tf32.tf32.f32 "
        "{%0,%1,%2,%3}, {%4,%5,%6,%7}, {%8,%9}, {%0,%1,%2,%3};\n"
        : "+f"(c[0]), "+f"(c[1]), "+f"(c[2]), "+f"(c[3])
        : "r"(a[0]), "r"(a[1]), "r"(a[2]), "r"(a[3]), "r"(b0), "r"(b1));
}
__device__ __forceinline__ unsigned smem_u32(const void* p) {
    return (unsigned)__cvta_generic_to_shared(p);
}
__device__ __forceinline__ void ldsm_x4(unsigned* r, unsigned a) {
    asm volatile("ldmatrix.sync.aligned.m8n8.x4.shared.b16 {%0,%1,%2,%3}, [%4];"
        : "=r"(r[0]), "=r"(r[1]), "=r"(r[2]), "=r"(r[3]) : "r"(a));
}
__device__ __forceinline__ void ldsm_x2(unsigned& r0, unsigned& r1, unsigned a) {
    asm volatile("ldmatrix.sync.aligned.m8n8.x2.shared.b16 {%0,%1}, [%2];"
        : "=r"(r0), "=r"(r1) : "r"(a));
}
__device__ __forceinline__ void cp16(unsigned saddr, const void* g) {
    asm volatile("cp.async.cg.shared.global [%0], [%1], 16;" :: "r"(saddr), "l"(g));
}
#define CP_COMMIT() asm volatile("cp.async.commit_group;")
#define CP_WAIT1()  asm volatile("cp.async.wait_group 1;")
#define CP_WAIT0()  asm volatile("cp.async.wait_group 0;")

// ---------------- pre-round weights / s to tf32-valued fp32 ----------------
struct RoundJob { const float* src; float* dst; int n4; };
struct RoundArgs { RoundJob j[8]; };
__global__ void __launch_bounds__(256) round_kernel(RoundArgs ra) {
    RoundJob jb = ra.j[blockIdx.y];
    for (int i = blockIdx.x * 256 + threadIdx.x; i < jb.n4; i += gridDim.x * 256) {
        float4 v = ((const float4*)jb.src)[i];
        uint4 o = make_uint4(f2tf(v.x), f2tf(v.y), f2tf(v.z), f2tf(v.w));
        ((uint4*)jb.dst)[i] = o;
    }
}

// ---------------- fused LayerNorms (no affine); s-branch output rounded to tf32 ----------------
__device__ __forceinline__ float2 blockReduce2(float a, float b) {
    #pragma unroll
    for (int o = 16; o; o >>= 1) {
        a += __shfl_xor_sync(0xffffffffu, a, o);
        b += __shfl_xor_sync(0xffffffffu, b, o);
    }
    __shared__ float sa[8], sb[8];
    int w = threadIdx.x >> 5, l = threadIdx.x & 31;
    if (l == 0) { sa[w] = a; sb[w] = b; }
    __syncthreads();
    if (w == 0) {
        a = (l < 8) ? sa[l] : 0.f;
        b = (l < 8) ? sb[l] : 0.f;
        #pragma unroll
        for (int o = 4; o; o >>= 1) {
            a += __shfl_xor_sync(0xffffffffu, a, o);
            b += __shfl_xor_sync(0xffffffffu, b, o);
        }
        if (l == 0) { sa[0] = a; sb[0] = b; }
    }
    __syncthreads();
    return make_float2(sa[0], sb[0]);
}

__global__ void __launch_bounds__(256) ln2_kernel(
    const float* __restrict__ a, const float* __restrict__ s,
    float* __restrict__ aout, float* __restrict__ sout)
{
    int isS = (blockIdx.y != 0);
    int C = isS ? CS : CT;
    const float* in = isS ? s : a;
    float* out = isS ? sout : aout;
    int r = blockIdx.x;
    const float* x = in + (size_t)r * C;
    float sm = 0.f, sq = 0.f;
    for (int c = threadIdx.x; c < C; c += 256) { float v = x[c]; sm += v; sq += v * v; }
    float2 red = blockReduce2(sm, sq);
    float mean = red.x / C;
    float inv = rsqrtf(red.y / C - mean * mean + 1e-5f);
    float* y = out + (size_t)r * C;
    for (int c = threadIdx.x; c < C; c += 256) {
        float v = (x[c] - mean) * inv;
        y[c] = isS ? __uint_as_float(f2tf(v)) : v;   // sln feeds GEMM A -> pre-round
    }
}

// ---------------- GEMM jobs ----------------
struct GemmJob {
    const float* A; const float* B; float* C;
    const float* bias; const float* mul; const float* add;
    int K; int sig; int rnd; float scale;
};
struct GemmBatchArgs { GemmJob j[4]; };

// ============ 128x128x16 tf32 GEMM, cp.async 3-stage pipeline, ldmatrix A-frags ============
#define AST 20
#define BST 136
#define ABUF (128*AST)
#define BBUF (16*BST)
#define GEMM_SMEM (3*(ABUF+BBUF)*4)   /* 56832 B */

__global__ void __launch_bounds__(256, 2) gemm128_kernel(GemmBatchArgs p, int M, int N) {
    const GemmJob jb = p.j[blockIdx.z];
    const float* __restrict__ A = jb.A;
    const float* __restrict__ B = jb.B;
    const int K = jb.K;

    extern __shared__ unsigned smg[];
    unsigned* As = smg;               // 3 x [128][AST]
    unsigned* Bs = smg + 3 * ABUF;    // 3 x [16][BST]

    int t = threadIdx.x, w = t >> 5, lane = t & 31;
    int gid = lane >> 2, tig = lane & 3;
    int wm = w >> 2, wn = w & 3;
    int m0 = blockIdx.y * 128, n0 = blockIdx.x * 128;
    int mw = wm * 64, nw = wn * 32;

    float acc[4][4][4];
    #pragma unroll
    for (int mt = 0; mt < 4; mt++)
        #pragma unroll
        for (int nt = 0; nt < 4; nt++)
            #pragma unroll
            for (int r = 0; r < 4; r++) acc[mt][nt][r] = 0.f;

    int arow[2], akq[2], brow[2], bc4[2];
    unsigned sa[2], sb[2];
    #pragma unroll
    for (int i = 0; i < 2; i++) {
        int idx = t + i * 256;
        arow[i] = idx >> 2; akq[i] = idx & 3;
        brow[i] = idx >> 5; bc4[i] = idx & 31;
        sa[i] = smem_u32(As) + (unsigned)((arow[i] * AST + akq[i] * 4) * 4);
        sb[i] = smem_u32(As) + (unsigned)((3 * ABUF + brow[i] * BST + bc4[i] * 4) * 4);
    }

    unsigned aBase = smem_u32(As);
    int lrow = lane & 15, lkq = lane >> 4;
    unsigned a_addr[4];
    #pragma unroll
    for (int mt = 0; mt < 4; mt++)
        a_addr[mt] = aBase + (unsigned)(((mw + mt * 16 + lrow) * AST + lkq * 4) * 4);

    int nchunk = K / 16;
    #pragma unroll
    for (int st = 0; st < 2; st++) {
        #pragma unroll
        for (int i = 0; i < 2; i++) {
            cp16(sa[i] + st * (ABUF * 4), A + (size_t)(m0 + arow[i]) * K + st * 16 + akq[i] * 4);
            cp16(sb[i] + st * (BBUF * 4), B + (size_t)(st * 16 + brow[i]) * N + n0 + bc4[i] * 4);
        }
        CP_COMMIT();
    }

    for (int ch = 0; ch < nchunk; ch++) {
        int stage = ch % 3;
        CP_WAIT1();
        __syncthreads();
        if (ch + 2 < nchunk) {
            int k0 = (ch + 2) * 16;
            int st = (ch + 2) % 3;
            #pragma unroll
            for (int i = 0; i < 2; i++) {
                cp16(sa[i] + st * (ABUF * 4), A + (size_t)(m0 + arow[i]) * K + k0 + akq[i] * 4);
                cp16(sb[i] + st * (BBUF * 4), B + (size_t)(k0 + brow[i]) * N + n0 + bc4[i] * 4);
            }
        }
        CP_COMMIT();

        unsigned aOff = stage * (ABUF * 4);
        const unsigned* BsC = Bs + stage * BBUF;
        #pragma unroll
        for (int ks = 0; ks < 2; ks++) {
            int kb = ks * 8;
            unsigned af[4][4];
            #pragma unroll
            for (int mt = 0; mt < 4; mt++) ldsm_x4(af[mt], a_addr[mt] + aOff + kb * 4);
            unsigned bf[4][2];
            #pragma unroll
            for (int nt = 0; nt < 4; nt++) {
                bf[nt][0] = BsC[(kb + tig) * BST + nw + nt * 8 + gid];
                bf[nt][1] = BsC[(kb + tig + 4) * BST + nw + nt * 8 + gid];
            }
            #pragma unroll
            for (int mt = 0; mt < 4; mt++)
                #pragma unroll
                for (int nt = 0; nt < 4; nt++)
                    mma_tf32(acc[mt][nt], af[mt], bf[nt][0], bf[nt][1]);
        }
    }

    // epilogue
    const float* bias = jb.bias;
    const float* mul = jb.mul;
    const float* add = jb.add;
    int do_sig = jb.sig;
    int do_rnd = jb.rnd;
    float scl = jb.scale;
    float* C = jb.C;
    #pragma unroll
    for (int mt = 0; mt < 4; mt++) {
        #pragma unroll
        for (int nt = 0; nt < 4; nt++) {
            int r0 = m0 + mw + mt * 16 + gid;
            int c0 = n0 + nw + nt * 8 + 2 * tig;
            #pragma unroll
            for (int rr = 0; rr < 2; rr++) {
                int r = r0 + rr * 8;
                #pragma unroll
                for (int cc = 0; cc < 2; cc++) {
                    float v = acc[mt][nt][rr * 2 + cc];
                    int c = c0 + cc;
                    if (bias) v += bias[c];
                    if (do_sig) v = 1.f / (1.f + __expf(-v));
                    size_t ix = (size_t)r * N + c;
                    if (mul) v *= mul[ix];
                    if (add) v += add[ix];
                    v *= scl;
                    C[ix] = do_rnd ? __uint_as_float(f2tf(v)) : v;
                }
            }
        }
    }
}

// ============ 64x64 kernel kept for Wout (needs 288 CTAs) ============
template <int BM>
__global__ void __launch_bounds__(256, 2) gemm_batch_kernel(GemmBatchArgs p, int M, int N) {
    const GemmJob jb = p.j[blockIdx.z];
    const float* __restrict__ A = jb.A;
    const float* __restrict__ B = jb.B;
    const int K = jb.K;
    constexpr int MT = BM / 64;
    constexpr int NLD = BM / 32;

    __shared__ unsigned As[32][BM + 8];
    __shared__ unsigned Bs[32][72];
    int t = threadIdx.x;
    int w = t >> 5, lane = t & 31;
    int gid = lane >> 2, tig = lane & 3;
    int wm = w >> 1, wn = w & 1;
    int m0 = blockIdx.y * BM, n0 = blockIdx.x * 64;
    int mw = wm * (BM / 4), nw = wn * 32;

    float acc[MT][4][4];
    #pragma unroll
    for (int mt = 0; mt < MT; mt++)
        #pragma unroll
        for (int nt = 0; nt < 4; nt++)
            #pragma unroll
            for (int r = 0; r < 4; r++) acc[mt][nt][r] = 0.f;

    int arow[NLD], akb[NLD], brow[2], bc4[2];
    #pragma unroll
    for (int i = 0; i < NLD; i++) { int idx = t + i * 256; arow[i] = idx & (BM - 1); akb[i] = idx / BM; }
    #pragma unroll
    for (int i = 0; i < 2; i++) { int idx = t + i * 256; brow[i] = idx >> 4; bc4[i] = idx & 15; }

    float4 ar[NLD], br[2];
    #pragma unroll
    for (int i = 0; i < NLD; i++)
        ar[i] = *(const float4*)(A + (size_t)(m0 + arow[i]) * K + akb[i] * 4);
    #pragma unroll
    for (int i = 0; i < 2; i++)
        br[i] = *(const float4*)(B + (size_t)brow[i] * N + n0 + bc4[i] * 4);

    int nchunk = K / 32;
    for (int ch = 0; ch < nchunk; ch++) {
        #pragma unroll
        for (int i = 0; i < NLD; i++) {
            As[akb[i] * 4 + 0][arow[i]] = f2tf(ar[i].x);
            As[akb[i] * 4 + 1][arow[i]] = f2tf(ar[i].y);
            As[akb[i] * 4 + 2][arow[i]] = f2tf(ar[i].z);
            As[akb[i] * 4 + 3][arow[i]] = f2tf(ar[i].w);
        }
        #pragma unroll
        for (int i = 0; i < 2; i++) {
            Bs[brow[i]][bc4[i] * 4 + 0] = f2tf(br[i].x);
            Bs[brow[i]][bc4[i] * 4 + 1] = f2tf(br[i].y);
            Bs[brow[i]][bc4[i] * 4 + 2] = f2tf(br[i].z);
            Bs[brow[i]][bc4[i] * 4 + 3] = f2tf(br[i].w);
        }
        __syncthreads();
        if (ch + 1 < nchunk) {
            int k0 = (ch + 1) * 32;
            #pragma unroll
            for (int i = 0; i < NLD; i++)
                ar[i] = *(const float4*)(A + (size_t)(m0 + arow[i]) * K + k0 + akb[i] * 4);
            #pragma unroll
            for (int i = 0; i < 2; i++)
                br[i] = *(const float4*)(B + (size_t)(k0 + brow[i]) * N + n0 + bc4[i] * 4);
        }
        #pragma unroll
        for (int ks = 0; ks < 4; ks++) {
            int kb = ks * 8;
            unsigned af[MT][4];
            #pragma unroll
            for (int mt = 0; mt < MT; mt++) {
                int mb = mw + mt * 16 + gid;
                af[mt][0] = As[kb + tig][mb];
                af[mt][1] = As[kb + tig][mb + 8];
                af[mt][2] = As[kb + tig + 4][mb];
                af[mt][3] = As[kb + tig + 4][mb + 8];
            }
            unsigned bf[4][2];
            #pragma unroll
            for (int nt = 0; nt < 4; nt++) {
                int nb = nw + nt * 8 + gid;
                bf[nt][0] = Bs[kb + tig][nb];
                bf[nt][1] = Bs[kb + tig + 4][nb];
            }
            #pragma unroll
            for (int mt = 0; mt < MT; mt++)
                #pragma unroll
                for (int nt = 0; nt < 4; nt++)
                    mma_tf32(acc[mt][nt], af[mt], bf[nt][0], bf[nt][1]);
        }
        __syncthreads();
    }

    const float* bias = jb.bias;
    const float* mul = jb.mul;
    const float* add = jb.add;
    int do_sig = jb.sig;
    float* C = jb.C;
    #pragma unroll
    for (int mt = 0; mt < MT; mt++) {
        #pragma unroll
        for (int nt = 0; nt < 4; nt++) {
            int r0 = m0 + mw + mt * 16 + gid;
            int c0 = n0 + nw + nt * 8 + 2 * tig;
            #pragma unroll
            for (int rr = 0; rr < 2; rr++) {
                int r = r0 + rr * 8;
                #pragma unroll
                for (int cc = 0; cc < 2; cc++) {
                    float v = acc[mt][nt][rr * 2 + cc];
                    int c = c0 + cc;
                    if (bias) v += bias[c];
                    if (do_sig) v = 1.f / (1.f + __expf(-v));
                    size_t ix = (size_t)r * N + c;
                    if (mul) v *= mul[ix];
                    if (add) v += add[ix];
                    C[ix] = v;
                }
            }
        }
    }
}

// ---------------- elementwise adaLN combine: anorm = round_tf32(gsig*aln + tmpb) ----------------
__global__ void __launch_bounds__(256) combine_kernel(
    float* __restrict__ anorm, const float* __restrict__ aln, const float* __restrict__ tmpb)
{
    int i0 = blockIdx.x * 512 + threadIdx.x;
    float4 g0 = ((const float4*)anorm)[i0];
    float4 g1 = ((const float4*)anorm)[i0 + 256];
    float4 a0 = ((const float4*)aln)[i0];
    float4 a1 = ((const float4*)aln)[i0 + 256];
    float4 t0 = ((const float4*)tmpb)[i0];
    float4 t1 = ((const float4*)tmpb)[i0 + 256];
    uint4 o0, o1;
    o0.x = f2tf(g0.x * a0.x + t0.x);
    o0.y = f2tf(g0.y * a0.y + t0.y);
    o0.z = f2tf(g0.z * a0.z + t0.z);
    o0.w = f2tf(g0.w * a0.w + t0.w);
    o1.x = f2tf(g1.x * a1.x + t1.x);
    o1.y = f2tf(g1.y * a1.y + t1.y);
    o1.z = f2tf(g1.z * a1.z + t1.z);
    o1.w = f2tf(g1.w * a1.w + t1.w);
    ((uint4*)anorm)[i0] = o0;
    ((uint4*)anorm)[i0 + 256] = o1;
}

// ---------------- pair bias: cp.async z staging, 512 threads ----------------
#define PJT 128
#define ZST 132
#define WST 24
#define PAIR_SMEM ((PJT*ZST + CP*WST + PJT) * 4)

__global__ void __launch_bounds__(512, 2) pair_kernel(
    const float* __restrict__ z, const float* __restrict__ bmask,
    const float* __restrict__ Wpb, const float* __restrict__ gma,
    const float* __restrict__ bta, float* __restrict__ pb)
{
    extern __shared__ float smp[];
    float* zn = smp;                                  // [128][132]: raw z, then tf32 LN in place
    unsigned* Wb = (unsigned*)(smp + PJT * ZST);      // [128][24]
    float* bm_s = smp + PJT * ZST + CP * WST;         // [128]

    int t = threadIdx.x;
    int w = t >> 5, lane = t & 31;
    int gid = lane >> 2, tig = lane & 3;
    int bi = blockIdx.y;
    int b = bi / NN, i = bi % NN;
    int j0 = blockIdx.x * PJT;

    unsigned zBase = smem_u32(zn);

    // stage z via cp.async: warp w owns rows w*8..w*8+7; each lane copies its own float4 slice.
    // Per-lane self-consistency: the lane reads back exactly the words it copied -> wait0 suffices.
    const float* zrow = z + ((size_t)bi * NN + j0) * CP;
    #pragma unroll
    for (int u = 0; u < 8; u++) {
        int r = w * 8 + u;
        cp16(zBase + (unsigned)((r * ZST + lane * 4) * 4), zrow + (size_t)r * CP + lane * 4);
    }
    CP_COMMIT();

    // overlap: Wpb + bias_mask staging with the async z copies
    for (int idx = t; idx < CP * NH; idx += 512) {
        int c = idx >> 4, hh = idx & 15;
        Wb[c * WST + hh] = f2tf(Wpb[idx]);
    }
    if (t < PJT) bm_s[t] = bmask[(size_t)bi * NN + j0 + t];

    float4 gv = *(const float4*)(gma + lane * 4);
    float4 bv = *(const float4*)(bta + lane * 4);

    CP_WAIT0();

    // LN from smem, rewrite in place as tf32
    #pragma unroll
    for (int u = 0; u < 8; u++) {
        int r = w * 8 + u;
        float4 v = *(const float4*)(zn + r * ZST + lane * 4);
        float s = v.x + v.y + v.z + v.w;
        float sq = v.x * v.x + v.y * v.y + v.z * v.z + v.w * v.w;
        #pragma unroll
        for (int o = 16; o; o >>= 1) {
            s  += __shfl_xor_sync(0xffffffffu, s, o);
            sq += __shfl_xor_sync(0xffffffffu, sq, o);
        }
        float mean = s * (1.f / CP);
        float inv = rsqrtf(sq * (1.f / CP) - mean * mean + 1e-5f);
        uint4 outv;
        outv.x = f2tf((v.x - mean) * inv * gv.x + bv.x);
        outv.y = f2tf((v.y - mean) * inv * gv.y + bv.y);
        outv.z = f2tf((v.z - mean) * inv * gv.z + bv.z);
        outv.w = f2tf((v.w - mean) * inv * gv.w + bv.w);
        *(uint4*)(zn + r * ZST + lane * 4) = outv;
    }
    __syncthreads();

    // mma: warp pair (w&7) shares 16 rows; w>>3 selects 8-head group
    int mb = (w & 7) * 16;
    int nth = w >> 3;
    int lrow = lane & 15, lkq = lane >> 4;
    unsigned z_addr = zBase + (unsigned)(((mb + lrow) * ZST + lkq * 4) * 4);
    float c2[4] = {0.f, 0.f, 0.f, 0.f};
    #pragma unroll
    for (int ks = 0; ks < 16; ks++) {
        int kb = ks * 8;
        unsigned af[4];
        ldsm_x4(af, z_addr + kb * 4);
        unsigned b0 = Wb[(kb + tig) * WST + nth * 8 + gid];
        unsigned b1 = Wb[(kb + tig + 4) * WST + nth * 8 + gid];
        mma_tf32(c2, af, b0, b1);
    }
    float bm0 = bm_s[mb + gid], bm1 = bm_s[mb + gid + 8];
    int jg0 = j0 + mb + gid;
    {
        int h0 = nth * 8 + 2 * tig;
        size_t base0 = ((size_t)(b * NH + h0) * NN + i) * NN;
        size_t base1 = ((size_t)(b * NH + h0 + 1) * NN + i) * NN;
        pb[base0 + jg0]     = c2[0] + bm0;
        pb[base1 + jg0]     = c2[1] + bm0;
        pb[base0 + jg0 + 8] = c2[2] + bm1;
        pb[base1 + jg0 + 8] = c2[3] + bm1;
    }
}

// ---------------- attention: flash-style, cp.async raw staging (q/k/v pre-rounded) ----------------
#define ATQ 52
#define AVQ 56
#define ATP 68
#define ATTN_SMEM ((2*64*ATQ + 64*AVQ + 64*ATP + 3*64) * 4)

__global__ void __launch_bounds__(256, 3) attn_kernel(
    const float* __restrict__ q, const float* __restrict__ k,
    const float* __restrict__ v, const float* __restrict__ gate,
    const float* __restrict__ pb, float* __restrict__ o)
{
    extern __shared__ float sm[];
    unsigned* Qs = (unsigned*)sm;           // [64][52] tf32 (pre-scaled by 1/sqrt(d))
    unsigned* Ks = Qs + 64 * ATQ;           // [64][52] tf32
    unsigned* Vs = Ks + 64 * ATQ;           // [64][56] tf32
    float* Ps = (float*)(Vs + 64 * AVQ);    // [64][68]
    float* Ms = Ps + 64 * ATP;
    float* Ls = Ms + 64;
    float* Ss = Ls + 64;

    int qt = blockIdx.x, hh = blockIdx.y, b = blockIdx.z;
    int t = threadIdx.x;
    int w = t >> 5, lane = t & 31;
    int gid = lane >> 2, tig = lane & 3;
    int q0 = qt * 64;

    unsigned qsm = smem_u32(Qs), ksm = smem_u32(Ks), vsm = smem_u32(Vs), psm = smem_u32(Ps);

    // Q staging: raw cp.async (q already tf32-rounded and scaled in GEMM epilogue)
    #pragma unroll
    for (int it = 0; it < 3; it++) {
        int idx = t + it * 256;
        int r = idx / 12, d4 = idx % 12;
        cp16(qsm + (unsigned)((r * ATQ + d4 * 4) * 4),
             q + ((size_t)(b * NN + q0 + r)) * CT + hh * HD + d4 * 4);
    }
    if (t < 64) { Ms[t] = -1e30f; Ls[t] = 0.f; }

    int wmS = w >> 2, wnS = w & 3;
    int mbS = wmS * 32, nbS = wnS * 16;
    int wmP = w >> 1, wnP = w & 1;
    int mbP = wmP * 16, nbP = wnP * 24;

    int lrow = lane & 15, lkq = lane >> 4;
    unsigned qaddr[2];
    #pragma unroll
    for (int mt = 0; mt < 2; mt++)
        qaddr[mt] = qsm + (unsigned)(((mbS + mt * 16 + lrow) * ATQ + lkq * 4) * 4);
    unsigned kaddr[2];
    #pragma unroll
    for (int nt = 0; nt < 2; nt++)
        kaddr[nt] = ksm + (unsigned)(((nbS + nt * 8 + (lane & 7)) * ATQ + ((lane >> 3) & 1) * 4) * 4);
    unsigned paddr = psm + (unsigned)(((mbP + lrow) * ATP + lkq * 4) * 4);

    float oacc[3][4];
    #pragma unroll
    for (int nt = 0; nt < 3; nt++)
        #pragma unroll
        for (int r = 0; r < 4; r++) oacc[nt][r] = 0.f;

    const float* bp0 = pb + ((size_t)(b * NH + hh) * NN + q0) * NN;

    for (int kt = 0; kt < 12; kt++) {
        int k0 = kt * 64;
        __syncthreads();
        // raw cp.async staging: K, V (pre-rounded tf32), bias tile (fp32)
        #pragma unroll
        for (int it = 0; it < 3; it++) {
            int idx = t + it * 256;
            int r = idx / 12, d4 = idx % 12;
            size_t gi = ((size_t)(b * NN + k0 + r)) * CT + hh * HD + d4 * 4;
            cp16(ksm + (unsigned)((r * ATQ + d4 * 4) * 4), k + gi);
            cp16(vsm + (unsigned)((r * AVQ + d4 * 4) * 4), v + gi);
        }
        #pragma unroll
        for (int it = 0; it < 4; it++) {
            int idx = t + it * 256;
            int r = idx >> 4, c4 = idx & 15;
            cp16(psm + (unsigned)((r * ATP + c4 * 4) * 4), bp0 + (size_t)r * NN + k0 + c4 * 4);
        }
        CP_COMMIT();
        CP_WAIT0();
        __syncthreads();

        float sacc[2][2][4];
        #pragma unroll
        for (int mt = 0; mt < 2; mt++)
            #pragma unroll
            for (int nt = 0; nt < 2; nt++)
                #pragma unroll
                for (int r = 0; r < 4; r++) sacc[mt][nt][r] = 0.f;
        #pragma unroll
        for (int ks = 0; ks < 6; ks++) {
            int kb = ks * 8;
            unsigned af[2][4];
            #pragma unroll
            for (int mt = 0; mt < 2; mt++) ldsm_x4(af[mt], qaddr[mt] + kb * 4);
            #pragma unroll
            for (int nt = 0; nt < 2; nt++) {
                unsigned b0, b1;
                ldsm_x2(b0, b1, kaddr[nt] + kb * 4);
                #pragma unroll
                for (int mt = 0; mt < 2; mt++)
                    mma_tf32(sacc[mt][nt], af[mt], b0, b1);
            }
        }
        #pragma unroll
        for (int mt = 0; mt < 2; mt++) {
            #pragma unroll
            for (int nt = 0; nt < 2; nt++) {
                int r = mbS + mt * 16 + gid;
                int c = nbS + nt * 8 + 2 * tig;
                float* p0 = Ps + r * ATP + c;
                float* p1 = Ps + (r + 8) * ATP + c;
                p0[0] += sacc[mt][nt][0];
                p0[1] += sacc[mt][nt][1];
                p1[0] += sacc[mt][nt][2];
                p1[1] += sacc[mt][nt][3];
            }
        }
        __syncthreads();

        // online softmax: 4 lanes per query row, stride-4 interleave; store P as tf32 bits
        {
            int qq = t >> 2, pp = t & 3;
            float* prow = Ps + qq * ATP + pp;
            float tmax = -1e30f;
            #pragma unroll
            for (int jj = 0; jj < 16; jj++) tmax = fmaxf(tmax, prow[jj * 4]);
            tmax = fmaxf(tmax, __shfl_xor_sync(0xffffffffu, tmax, 1));
            tmax = fmaxf(tmax, __shfl_xor_sync(0xffffffffu, tmax, 2));
            float mold = Ms[qq];
            float mnew = fmaxf(mold, tmax);
            float tsum = 0.f;
            #pragma unroll
            for (int jj = 0; jj < 16; jj++) {
                float p = __expf(prow[jj * 4] - mnew);
                tsum += p;
                prow[jj * 4] = __uint_as_float(f2tf(p));
            }
            tsum += __shfl_xor_sync(0xffffffffu, tsum, 1);
            tsum += __shfl_xor_sync(0xffffffffu, tsum, 2);
            if (pp == 0) {
                float scl = __expf(mold - mnew);
                Ss[qq] = scl;
                Ls[qq] = Ls[qq] * scl + tsum;
                Ms[qq] = mnew;
            }
        }
        __syncthreads();

        // rescale + O += P @ V via mma (P frag via ldmatrix)
        {
            float s0 = Ss[mbP + gid], s1 = Ss[mbP + gid + 8];
            #pragma unroll
            for (int nt = 0; nt < 3; nt++) {
                oacc[nt][0] *= s0; oacc[nt][1] *= s0;
                oacc[nt][2] *= s1; oacc[nt][3] *= s1;
            }
            #pragma unroll
            for (int ks = 0; ks < 8; ks++) {
                int kb = ks * 8;
                unsigned af[4];
                ldsm_x4(af, paddr + kb * 4);
                #pragma unroll
                for (int nt = 0; nt < 3; nt++) {
                    unsigned b0 = Vs[(kb + tig) * AVQ + nbP + nt * 8 + gid];
                    unsigned b1 = Vs[(kb + tig + 4) * AVQ + nbP + nt * 8 + gid];
                    mma_tf32(oacc[nt], af, b0, b1);
                }
            }
        }
    }

    // epilogue: normalize, gate, write
    __syncthreads();
    float inv0 = 1.f / Ls[mbP + gid];
    float inv1 = 1.f / Ls[mbP + gid + 8];
    size_t row0 = (size_t)(b * NN + q0 + mbP + gid);
    size_t row1 = row0 + 8;
    #pragma unroll
    for (int nt = 0; nt < 3; nt++) {
        int c = hh * HD + nbP + nt * 8 + 2 * tig;
        size_t i00 = row0 * CT + c;
        size_t i10 = row1 * CT + c;
        float g00 = 1.f / (1.f + __expf(-gate[i00]));
        float g01 = 1.f / (1.f + __expf(-gate[i00 + 1]));
        float g10 = 1.f / (1.f + __expf(-gate[i10]));
        float g11 = 1.f / (1.f + __expf(-gate[i10 + 1]));
        o[i00]     = g00 * oacc[nt][0] * inv0;
        o[i00 + 1] = g01 * oacc[nt][1] * inv0;
        o[i10]     = g10 * oacc[nt][2] * inv1;
        o[i10 + 1] = g11 * oacc[nt][3] * inv1;
    }
}

// ---------------- launch ----------------
static float* symaddr(const void* sym) {
    void* p = nullptr;
    cudaGetSymbolAddress(&p, sym);
    return (float*)p;
}

extern "C" void kernel_launch(void* const* d_in, const int* in_sizes, int n_in,
                              void* d_out, int out_size) {
    const float* a    = (const float*)d_in[0];
    const float* s    = (const float*)d_in[1];
    const float* z    = (const float*)d_in[2];
    const float* bm   = (const float*)d_in[3];
    const float* Wg   = (const float*)d_in[4];
    const float* bg   = (const float*)d_in[5];
    const float* Wb   = (const float*)d_in[6];
    const float* Wq   = (const float*)d_in[7];
    const float* bq   = (const float*)d_in[8];
    const float* Wk   = (const float*)d_in[9];
    const float* Wv   = (const float*)d_in[10];
    const float* Wpb  = (const float*)d_in[11];
    const float* png  = (const float*)d_in[12];
    const float* pnb  = (const float*)d_in[13];
    const float* Wgt  = (const float*)d_in[14];
    const float* Wout = (const float*)d_in[15];
    const float* Wog  = (const float*)d_in[16];
    const float* bog  = (const float*)d_in[17];
    float* out = (float*)d_out;

    float* aln   = symaddr(g_aln);
    float* sln   = symaddr(g_sln);
    float* tmpb  = symaddr(g_tmpb);
    float* anorm = symaddr(g_anorm);
    float* qb    = symaddr(g_q);
    float* kb    = symaddr(g_k);
    float* vb    = symaddr(g_v);
    float* gateb = symaddr(g_gate);
    float* ogb   = symaddr(g_og);
    float* ob    = symaddr(g_o);
    float* pbb   = symaddr(g_pb);
    float* wq    = symaddr(g_wq);
    float* wk    = symaddr(g_wk);
    float* wv    = symaddr(g_wv);
    float* wgt   = symaddr(g_wgt);
    float* wb    = symaddr(g_wb);
    float* wg    = symaddr(g_wg);
    float* wog   = symaddr(g_wog);
    float* srnd  = symaddr(g_srnd);

    const float SC = 0.14433756729740643f;  // 1/sqrt(48)

    cudaFuncSetAttribute(gemm128_kernel, cudaFuncAttributeMaxDynamicSharedMemorySize, GEMM_SMEM);
    cudaFuncSetAttribute(pair_kernel, cudaFuncAttributeMaxDynamicSharedMemorySize, PAIR_SMEM);
    cudaFuncSetAttribute(attn_kernel, cudaFuncAttributeMaxDynamicSharedMemorySize, ATTN_SMEM);

    // pre-round GEMM operands to tf32 values (once)
    {
        RoundArgs ra = {};
        ra.j[0] = { Wq,  wq,  CT * CT / 4 };
        ra.j[1] = { Wk,  wk,  CT * CT / 4 };
        ra.j[2] = { Wv,  wv,  CT * CT / 4 };
        ra.j[3] = { Wgt, wgt, CT * CT / 4 };
        ra.j[4] = { Wb,  wb,  CS * CT / 4 };
        ra.j[5] = { Wg,  wg,  CS * CT / 4 };
        ra.j[6] = { Wog, wog, CS * CT / 4 };
        ra.j[7] = { s,   srnd, ROWS * CS / 4 };
        round_kernel<<<dim3(144, 8), 256>>>(ra);
    }

    // fused LayerNorms (sln rounded to tf32)
    ln2_kernel<<<dim3(ROWS, 2), 256>>>(a, s, aln, sln);

    // batch 1: adaLN gate (sigmoid), adaLN bias-proj, output-gate (sigmoid) — K=384
    {
        GemmBatchArgs p = {};
        p.j[0] = { sln,  wb,  tmpb,  nullptr, nullptr, nullptr, CS, 0, 0, 1.f };
        p.j[1] = { sln,  wg,  anorm, bg,      nullptr, nullptr, CS, 1, 0, 1.f };   // gsig
        p.j[2] = { srnd, wog, ogb,   bog,     nullptr, nullptr, CS, 1, 0, 1.f };
        gemm128_kernel<<<dim3(CT / 128, ROWS / 128, 3), 256, GEMM_SMEM>>>(p, ROWS, CT);
    }
    // anorm = round_tf32(gsig * aln + tmpb)
    combine_kernel<<<ROWS * CT / 8 / 256, 256>>>(anorm, aln, tmpb);

    // batch 2: Q/K/V/gate — shared A, K=768; q scaled+rounded, k/v rounded in epilogue
    {
        GemmBatchArgs p = {};
        p.j[0] = { anorm, wq,  qb,    bq,      nullptr, nullptr, CT, 0, 1, SC  };
        p.j[1] = { anorm, wk,  kb,    nullptr, nullptr, nullptr, CT, 0, 1, 1.f };
        p.j[2] = { anorm, wv,  vb,    nullptr, nullptr, nullptr, CT, 0, 1, 1.f };
        p.j[3] = { anorm, wgt, gateb, nullptr, nullptr, nullptr, CT, 0, 0, 1.f };
        gemm128_kernel<<<dim3(CT / 128, ROWS / 128, 4), 256, GEMM_SMEM>>>(p, ROWS, CT);
    }

    // pair bias (incl. bias_mask)
    pair_kernel<<<dim3(NN / PJT, ROWS), 512, PAIR_SMEM>>>(z, bm, Wpb, png, pnb, pbb);
    // attention + gating
    attn_kernel<<<dim3(NN / 64, NH, BB), 256, ATTN_SMEM>>>(qb, kb, vb, gateb, pbb, ob);

    // output projection with output-gate multiply — BM=64 for 288 CTAs
    {
        GemmBatchArgs p = {};
        p.j[0] = { ob, Wout, out, nullptr, ogb, nullptr, CT, 0, 0, 1.f };
        gemm_batch_kernel<64><<<dim3(CT / 64, ROWS / 64, 1), 256>>>(p, ROWS, CT);
    }
}

// round 17
// speedup vs baseline: 3.8316x; 1.0422x over previous
#include <cuda_runtime.h>
#include <math.h>

#define BB 2
#define NN 768
#define CT 768
#define CS 384
#define CP 128
#define NH 16
#define HD 48
#define ROWS (BB*NN)   /* 1536 */

// ---------------- scratch (device globals; no allocation allowed) ----------------
__device__ float g_aln  [ROWS*CT];
__device__ float g_sln  [ROWS*CS];
__device__ float g_tmpb [ROWS*CT];
__device__ float g_anorm[ROWS*CT];
__device__ float g_q    [ROWS*CT];
__device__ float g_k    [ROWS*CT];
__device__ float g_v    [ROWS*CT];
__device__ float g_gate [ROWS*CT];
__device__ float g_og   [ROWS*CT];
__device__ float g_o    [ROWS*CT];
__device__ float g_pb   [BB*NH*NN*NN];   // 75.5 MB pair bias [b,h,i,j]
// pre-rounded (tf32-valued fp32) operands
__device__ float g_wq  [CT*CT];
__device__ float g_wk  [CT*CT];
__device__ float g_wv  [CT*CT];
__device__ float g_wgt [CT*CT];
__device__ float g_wout[CT*CT];
__device__ float g_wb  [CS*CT];
__device__ float g_wg  [CS*CT];
__device__ float g_wog [CS*CT];
__device__ float g_srnd[ROWS*CS];

// ---------------- tf32 / mma / ldmatrix / cp.async helpers ----------------
__device__ __forceinline__ unsigned f2tf(float f) {
    unsigned u;
    asm("cvt.rna.tf32.f32 %0, %1;" : "=r"(u) : "f"(f));
    return u;
}
__device__ __forceinline__ void mma_tf32(float* c, const unsigned* a, unsigned b0, unsigned b1) {
    asm volatile(
        "mma.sync.aligned.m16n8k8.row.col.f32.tf32.tf32.f32 "
        "{%0,%1,%2,%3}, {%4,%5,%6,%7}, {%8,%9}, {%0,%1,%2,%3};\n"
        : "+f"(c[0]), "+f"(c[1]), "+f"(c[2]), "+f"(c[3])
        : "r"(a[0]), "r"(a[1]), "r"(a[2]), "r"(a[3]), "r"(b0), "r"(b1));
}
__device__ __forceinline__ unsigned smem_u32(const void* p) {
    return (unsigned)__cvta_generic_to_shared(p);
}
__device__ __forceinline__ void ldsm_x4(unsigned* r, unsigned a) {
    asm volatile("ldmatrix.sync.aligned.m8n8.x4.shared.b16 {%0,%1,%2,%3}, [%4];"
        : "=r"(r[0]), "=r"(r[1]), "=r"(r[2]), "=r"(r[3]) : "r"(a));
}
__device__ __forceinline__ void ldsm_x2(unsigned& r0, unsigned& r1, unsigned a) {
    asm volatile("ldmatrix.sync.aligned.m8n8.x2.shared.b16 {%0,%1}, [%2];"
        : "=r"(r0), "=r"(r1) : "r"(a));
}
__device__ __forceinline__ void cp16(unsigned saddr, const void* g) {
    asm volatile("cp.async.cg.shared.global [%0], [%1], 16;" :: "r"(saddr), "l"(g));
}
#define CP_COMMIT() asm volatile("cp.async.commit_group;")
#define CP_WAIT1()  asm volatile("cp.async.wait_group 1;")
#define CP_WAIT0()  asm volatile("cp.async.wait_group 0;")

// ---------------- pre-round weights / s to tf32-valued fp32 ----------------
struct RoundJob { const float* src; float* dst; int n4; };
struct RoundArgs { RoundJob j[9]; };
__global__ void __launch_bounds__(256) round_kernel(RoundArgs ra) {
    RoundJob jb = ra.j[blockIdx.y];
    for (int i = blockIdx.x * 256 + threadIdx.x; i < jb.n4; i += gridDim.x * 256) {
        float4 v = ((const float4*)jb.src)[i];
        uint4 o = make_uint4(f2tf(v.x), f2tf(v.y), f2tf(v.z), f2tf(v.w));
        ((uint4*)jb.dst)[i] = o;
    }
}

// ---------------- fused LayerNorms (no affine); s-branch output rounded to tf32 ----------------
__device__ __forceinline__ float2 blockReduce2(float a, float b) {
    #pragma unroll
    for (int o = 16; o; o >>= 1) {
        a += __shfl_xor_sync(0xffffffffu, a, o);
        b += __shfl_xor_sync(0xffffffffu, b, o);
    }
    __shared__ float sa[8], sb[8];
    int w = threadIdx.x >> 5, l = threadIdx.x & 31;
    if (l == 0) { sa[w] = a; sb[w] = b; }
    __syncthreads();
    if (w == 0) {
        a = (l < 8) ? sa[l] : 0.f;
        b = (l < 8) ? sb[l] : 0.f;
        #pragma unroll
        for (int o = 4; o; o >>= 1) {
            a += __shfl_xor_sync(0xffffffffu, a, o);
            b += __shfl_xor_sync(0xffffffffu, b, o);
        }
        if (l == 0) { sa[0] = a; sb[0] = b; }
    }
    __syncthreads();
    return make_float2(sa[0], sb[0]);
}

__global__ void __launch_bounds__(256) ln2_kernel(
    const float* __restrict__ a, const float* __restrict__ s,
    float* __restrict__ aout, float* __restrict__ sout)
{
    int isS = (blockIdx.y != 0);
    int C = isS ? CS : CT;
    const float* in = isS ? s : a;
    float* out = isS ? sout : aout;
    int r = blockIdx.x;
    const float* x = in + (size_t)r * C;
    float sm = 0.f, sq = 0.f;
    for (int c = threadIdx.x; c < C; c += 256) { float v = x[c]; sm += v; sq += v * v; }
    float2 red = blockReduce2(sm, sq);
    float mean = red.x / C;
    float inv = rsqrtf(red.y / C - mean * mean + 1e-5f);
    float* y = out + (size_t)r * C;
    for (int c = threadIdx.x; c < C; c += 256) {
        float v = (x[c] - mean) * inv;
        y[c] = isS ? __uint_as_float(f2tf(v)) : v;   // sln feeds GEMM A -> pre-round
    }
}

// ---------------- GEMM jobs ----------------
struct GemmJob {
    const float* A; const float* B; float* C;
    const float* bias; const float* mul; const float* add;
    int K; int sig; int rnd; float scale;
};
struct GemmBatchArgs { GemmJob j[4]; };

// ============ 128x128x16 tf32 GEMM, cp.async 3-stage pipeline, ldmatrix A-frags ============
#define AST 20
#define BST 136
#define ABUF (128*AST)
#define BBUF (16*BST)
#define GEMM_SMEM (3*(ABUF+BBUF)*4)   /* 56832 B */

__global__ void __launch_bounds__(256, 2) gemm128_kernel(GemmBatchArgs p, int M, int N) {
    const GemmJob jb = p.j[blockIdx.z];
    const float* __restrict__ A = jb.A;
    const float* __restrict__ B = jb.B;
    const int K = jb.K;

    extern __shared__ unsigned smg[];
    unsigned* As = smg;               // 3 x [128][AST]
    unsigned* Bs = smg + 3 * ABUF;    // 3 x [16][BST]

    int t = threadIdx.x, w = t >> 5, lane = t & 31;
    int gid = lane >> 2, tig = lane & 3;
    int wm = w >> 2, wn = w & 3;
    int m0 = blockIdx.y * 128, n0 = blockIdx.x * 128;
    int mw = wm * 64, nw = wn * 32;

    float acc[4][4][4];
    #pragma unroll
    for (int mt = 0; mt < 4; mt++)
        #pragma unroll
        for (int nt = 0; nt < 4; nt++)
            #pragma unroll
            for (int r = 0; r < 4; r++) acc[mt][nt][r] = 0.f;

    int arow[2], akq[2], brow[2], bc4[2];
    unsigned sa[2], sb[2];
    #pragma unroll
    for (int i = 0; i < 2; i++) {
        int idx = t + i * 256;
        arow[i] = idx >> 2; akq[i] = idx & 3;
        brow[i] = idx >> 5; bc4[i] = idx & 31;
        sa[i] = smem_u32(As) + (unsigned)((arow[i] * AST + akq[i] * 4) * 4);
        sb[i] = smem_u32(As) + (unsigned)((3 * ABUF + brow[i] * BST + bc4[i] * 4) * 4);
    }

    unsigned aBase = smem_u32(As);
    int lrow = lane & 15, lkq = lane >> 4;
    unsigned a_addr[4];
    #pragma unroll
    for (int mt = 0; mt < 4; mt++)
        a_addr[mt] = aBase + (unsigned)(((mw + mt * 16 + lrow) * AST + lkq * 4) * 4);

    int nchunk = K / 16;
    #pragma unroll
    for (int st = 0; st < 2; st++) {
        #pragma unroll
        for (int i = 0; i < 2; i++) {
            cp16(sa[i] + st * (ABUF * 4), A + (size_t)(m0 + arow[i]) * K + st * 16 + akq[i] * 4);
            cp16(sb[i] + st * (BBUF * 4), B + (size_t)(st * 16 + brow[i]) * N + n0 + bc4[i] * 4);
        }
        CP_COMMIT();
    }

    for (int ch = 0; ch < nchunk; ch++) {
        int stage = ch % 3;
        CP_WAIT1();
        __syncthreads();
        if (ch + 2 < nchunk) {
            int k0 = (ch + 2) * 16;
            int st = (ch + 2) % 3;
            #pragma unroll
            for (int i = 0; i < 2; i++) {
                cp16(sa[i] + st * (ABUF * 4), A + (size_t)(m0 + arow[i]) * K + k0 + akq[i] * 4);
                cp16(sb[i] + st * (BBUF * 4), B + (size_t)(k0 + brow[i]) * N + n0 + bc4[i] * 4);
            }
        }
        CP_COMMIT();

        unsigned aOff = stage * (ABUF * 4);
        const unsigned* BsC = Bs + stage * BBUF;
        #pragma unroll
        for (int ks = 0; ks < 2; ks++) {
            int kb = ks * 8;
            unsigned af[4][4];
            #pragma unroll
            for (int mt = 0; mt < 4; mt++) ldsm_x4(af[mt], a_addr[mt] + aOff + kb * 4);
            unsigned bf[4][2];
            #pragma unroll
            for (int nt = 0; nt < 4; nt++) {
                bf[nt][0] = BsC[(kb + tig) * BST + nw + nt * 8 + gid];
                bf[nt][1] = BsC[(kb + tig + 4) * BST + nw + nt * 8 + gid];
            }
            #pragma unroll
            for (int mt = 0; mt < 4; mt++)
                #pragma unroll
                for (int nt = 0; nt < 4; nt++)
                    mma_tf32(acc[mt][nt], af[mt], bf[nt][0], bf[nt][1]);
        }
    }

    // epilogue
    const float* bias = jb.bias;
    const float* mul = jb.mul;
    const float* add = jb.add;
    int do_sig = jb.sig;
    int do_rnd = jb.rnd;
    float scl = jb.scale;
    float* C = jb.C;
    #pragma unroll
    for (int mt = 0; mt < 4; mt++) {
        #pragma unroll
        for (int nt = 0; nt < 4; nt++) {
            int r0 = m0 + mw + mt * 16 + gid;
            int c0 = n0 + nw + nt * 8 + 2 * tig;
            #pragma unroll
            for (int rr = 0; rr < 2; rr++) {
                int r = r0 + rr * 8;
                #pragma unroll
                for (int cc = 0; cc < 2; cc++) {
                    float v = acc[mt][nt][rr * 2 + cc];
                    int c = c0 + cc;
                    if (bias) v += bias[c];
                    if (do_sig) v = 1.f / (1.f + __expf(-v));
                    size_t ix = (size_t)r * N + c;
                    if (mul) v *= mul[ix];
                    if (add) v += add[ix];
                    v *= scl;
                    C[ix] = do_rnd ? __uint_as_float(f2tf(v)) : v;
                }
            }
        }
    }
}

// ============ 64x64x16 tf32 GEMM (Wout): cp.async 3-stage pipeline, 288 CTAs ============
#define BST64 72
#define ABUF64 (64*AST)
#define BBUF64 (16*BST64)

__global__ void __launch_bounds__(256, 3) gemm64_kernel(
    const float* __restrict__ A, const float* __restrict__ B, float* __restrict__ C,
    const float* __restrict__ mul, int M, int N, int K)
{
    __shared__ unsigned As[3 * ABUF64];   // [m][k] tf32
    __shared__ unsigned Bs[3 * BBUF64];   // [k][n] tf32

    int t = threadIdx.x, w = t >> 5, lane = t & 31;
    int gid = lane >> 2, tig = lane & 3;
    int wm = w >> 2, wn = w & 3;
    int m0 = blockIdx.y * 64, n0 = blockIdx.x * 64;
    int mw = wm * 32, nw = wn * 16;

    float acc[2][2][4];
    #pragma unroll
    for (int mt = 0; mt < 2; mt++)
        #pragma unroll
        for (int nt = 0; nt < 2; nt++)
            #pragma unroll
            for (int r = 0; r < 4; r++) acc[mt][nt][r] = 0.f;

    // staging: A 64 rows x 4x16B; B 16 rows x 16x16B — 1 cp16/thread each
    int arow = t >> 2, akq = t & 3;
    int brow = t >> 4, bc4 = t & 15;
    unsigned sa = smem_u32(As) + (unsigned)((arow * AST + akq * 4) * 4);
    unsigned sb = smem_u32(Bs) + (unsigned)((brow * BST64 + bc4 * 4) * 4);

    unsigned aBase = smem_u32(As);
    int lrow = lane & 15, lkq = lane >> 4;
    unsigned a_addr[2];
    #pragma unroll
    for (int mt = 0; mt < 2; mt++)
        a_addr[mt] = aBase + (unsigned)(((mw + mt * 16 + lrow) * AST + lkq * 4) * 4);

    int nchunk = K / 16;
    #pragma unroll
    for (int st = 0; st < 2; st++) {
        cp16(sa + st * (ABUF64 * 4), A + (size_t)(m0 + arow) * K + st * 16 + akq * 4);
        cp16(sb + st * (BBUF64 * 4), B + (size_t)(st * 16 + brow) * N + n0 + bc4 * 4);
        CP_COMMIT();
    }

    for (int ch = 0; ch < nchunk; ch++) {
        int stage = ch % 3;
        CP_WAIT1();
        __syncthreads();
        if (ch + 2 < nchunk) {
            int k0 = (ch + 2) * 16;
            int st = (ch + 2) % 3;
            cp16(sa + st * (ABUF64 * 4), A + (size_t)(m0 + arow) * K + k0 + akq * 4);
            cp16(sb + st * (BBUF64 * 4), B + (size_t)(k0 + brow) * N + n0 + bc4 * 4);
        }
        CP_COMMIT();

        unsigned aOff = stage * (ABUF64 * 4);
        const unsigned* BsC = Bs + stage * BBUF64;
        #pragma unroll
        for (int ks = 0; ks < 2; ks++) {
            int kb = ks * 8;
            unsigned af[2][4];
            #pragma unroll
            for (int mt = 0; mt < 2; mt++) ldsm_x4(af[mt], a_addr[mt] + aOff + kb * 4);
            unsigned bf[2][2];
            #pragma unroll
            for (int nt = 0; nt < 2; nt++) {
                bf[nt][0] = BsC[(kb + tig) * BST64 + nw + nt * 8 + gid];
                bf[nt][1] = BsC[(kb + tig + 4) * BST64 + nw + nt * 8 + gid];
            }
            #pragma unroll
            for (int mt = 0; mt < 2; mt++)
                #pragma unroll
                for (int nt = 0; nt < 2; nt++)
                    mma_tf32(acc[mt][nt], af[mt], bf[nt][0], bf[nt][1]);
        }
    }

    // epilogue: out = acc * mul (output gate)
    #pragma unroll
    for (int mt = 0; mt < 2; mt++) {
        #pragma unroll
        for (int nt = 0; nt < 2; nt++) {
            int r0 = m0 + mw + mt * 16 + gid;
            int c0 = n0 + nw + nt * 8 + 2 * tig;
            #pragma unroll
            for (int rr = 0; rr < 2; rr++) {
                int r = r0 + rr * 8;
                #pragma unroll
                for (int cc = 0; cc < 2; cc++) {
                    size_t ix = (size_t)r * N + c0 + cc;
                    C[ix] = acc[mt][nt][rr * 2 + cc] * mul[ix];
                }
            }
        }
    }
}

// ---------------- elementwise adaLN combine: anorm = round_tf32(gsig*aln + tmpb) ----------------
__global__ void __launch_bounds__(256) combine_kernel(
    float* __restrict__ anorm, const float* __restrict__ aln, const float* __restrict__ tmpb)
{
    int i0 = blockIdx.x * 512 + threadIdx.x;
    float4 g0 = ((const float4*)anorm)[i0];
    float4 g1 = ((const float4*)anorm)[i0 + 256];
    float4 a0 = ((const float4*)aln)[i0];
    float4 a1 = ((const float4*)aln)[i0 + 256];
    float4 t0 = ((const float4*)tmpb)[i0];
    float4 t1 = ((const float4*)tmpb)[i0 + 256];
    uint4 o0, o1;
    o0.x = f2tf(g0.x * a0.x + t0.x);
    o0.y = f2tf(g0.y * a0.y + t0.y);
    o0.z = f2tf(g0.z * a0.z + t0.z);
    o0.w = f2tf(g0.w * a0.w + t0.w);
    o1.x = f2tf(g1.x * a1.x + t1.x);
    o1.y = f2tf(g1.y * a1.y + t1.y);
    o1.z = f2tf(g1.z * a1.z + t1.z);
    o1.w = f2tf(g1.w * a1.w + t1.w);
    ((uint4*)anorm)[i0] = o0;
    ((uint4*)anorm)[i0 + 256] = o1;
}

// ---------------- pair bias: cp.async z staging, 512 threads ----------------
#define PJT 128
#define ZST 132
#define WST 24
#define PAIR_SMEM ((PJT*ZST + CP*WST + PJT) * 4)

__global__ void __launch_bounds__(512, 2) pair_kernel(
    const float* __restrict__ z, const float* __restrict__ bmask,
    const float* __restrict__ Wpb, const float* __restrict__ gma,
    const float* __restrict__ bta, float* __restrict__ pb)
{
    extern __shared__ float smp[];
    float* zn = smp;                                  // [128][132]: raw z, then tf32 LN in place
    unsigned* Wb = (unsigned*)(smp + PJT * ZST);      // [128][24]
    float* bm_s = smp + PJT * ZST + CP * WST;         // [128]

    int t = threadIdx.x;
    int w = t >> 5, lane = t & 31;
    int gid = lane >> 2, tig = lane & 3;
    int bi = blockIdx.y;
    int b = bi / NN, i = bi % NN;
    int j0 = blockIdx.x * PJT;

    unsigned zBase = smem_u32(zn);

    // stage z via cp.async: warp w owns rows w*8..w*8+7; each lane copies its own float4 slice.
    const float* zrow = z + ((size_t)bi * NN + j0) * CP;
    #pragma unroll
    for (int u = 0; u < 8; u++) {
        int r = w * 8 + u;
        cp16(zBase + (unsigned)((r * ZST + lane * 4) * 4), zrow + (size_t)r * CP + lane * 4);
    }
    CP_COMMIT();

    // overlap: Wpb + bias_mask staging with the async z copies
    for (int idx = t; idx < CP * NH; idx += 512) {
        int c = idx >> 4, hh = idx & 15;
        Wb[c * WST + hh] = f2tf(Wpb[idx]);
    }
    if (t < PJT) bm_s[t] = bmask[(size_t)bi * NN + j0 + t];

    float4 gv = *(const float4*)(gma + lane * 4);
    float4 bv = *(const float4*)(bta + lane * 4);

    CP_WAIT0();

    // LN from smem, rewrite in place as tf32
    #pragma unroll
    for (int u = 0; u < 8; u++) {
        int r = w * 8 + u;
        float4 v = *(const float4*)(zn + r * ZST + lane * 4);
        float s = v.x + v.y + v.z + v.w;
        float sq = v.x * v.x + v.y * v.y + v.z * v.z + v.w * v.w;
        #pragma unroll
        for (int o = 16; o; o >>= 1) {
            s  += __shfl_xor_sync(0xffffffffu, s, o);
            sq += __shfl_xor_sync(0xffffffffu, sq, o);
        }
        float mean = s * (1.f / CP);
        float inv = rsqrtf(sq * (1.f / CP) - mean * mean + 1e-5f);
        uint4 outv;
        outv.x = f2tf((v.x - mean) * inv * gv.x + bv.x);
        outv.y = f2tf((v.y - mean) * inv * gv.y + bv.y);
        outv.z = f2tf((v.z - mean) * inv * gv.z + bv.z);
        outv.w = f2tf((v.w - mean) * inv * gv.w + bv.w);
        *(uint4*)(zn + r * ZST + lane * 4) = outv;
    }
    __syncthreads();

    // mma: warp pair (w&7) shares 16 rows; w>>3 selects 8-head group
    int mb = (w & 7) * 16;
    int nth = w >> 3;
    int lrow = lane & 15, lkq = lane >> 4;
    unsigned z_addr = zBase + (unsigned)(((mb + lrow) * ZST + lkq * 4) * 4);
    float c2[4] = {0.f, 0.f, 0.f, 0.f};
    #pragma unroll
    for (int ks = 0; ks < 16; ks++) {
        int kb = ks * 8;
        unsigned af[4];
        ldsm_x4(af, z_addr + kb * 4);
        unsigned b0 = Wb[(kb + tig) * WST + nth * 8 + gid];
        unsigned b1 = Wb[(kb + tig + 4) * WST + nth * 8 + gid];
        mma_tf32(c2, af, b0, b1);
    }
    float bm0 = bm_s[mb + gid], bm1 = bm_s[mb + gid + 8];
    int jg0 = j0 + mb + gid;
    {
        int h0 = nth * 8 + 2 * tig;
        size_t base0 = ((size_t)(b * NH + h0) * NN + i) * NN;
        size_t base1 = ((size_t)(b * NH + h0 + 1) * NN + i) * NN;
        pb[base0 + jg0]     = c2[0] + bm0;
        pb[base1 + jg0]     = c2[1] + bm0;
        pb[base0 + jg0 + 8] = c2[2] + bm1;
        pb[base1 + jg0 + 8] = c2[3] + bm1;
    }
}

// ---------------- attention: flash-style, cp.async raw staging (q/k/v pre-rounded) ----------------
#define ATQ 52
#define AVQ 56
#define ATP 68
#define ATTN_SMEM ((2*64*ATQ + 64*AVQ + 64*ATP + 3*64) * 4)

__global__ void __launch_bounds__(256, 3) attn_kernel(
    const float* __restrict__ q, const float* __restrict__ k,
    const float* __restrict__ v, const float* __restrict__ gate,
    const float* __restrict__ pb, float* __restrict__ o)
{
    extern __shared__ float sm[];
    unsigned* Qs = (unsigned*)sm;           // [64][52] tf32 (pre-scaled by 1/sqrt(d))
    unsigned* Ks = Qs + 64 * ATQ;           // [64][52] tf32
    unsigned* Vs = Ks + 64 * ATQ;           // [64][56] tf32
    float* Ps = (float*)(Vs + 64 * AVQ);    // [64][68]
    float* Ms = Ps + 64 * ATP;
    float* Ls = Ms + 64;
    float* Ss = Ls + 64;

    int qt = blockIdx.x, hh = blockIdx.y, b = blockIdx.z;
    int t = threadIdx.x;
    int w = t >> 5, lane = t & 31;
    int gid = lane >> 2, tig = lane & 3;
    int q0 = qt * 64;

    unsigned qsm = smem_u32(Qs), ksm = smem_u32(Ks), vsm = smem_u32(Vs), psm = smem_u32(Ps);

    // Q staging: raw cp.async (q already tf32-rounded and scaled in GEMM epilogue)
    #pragma unroll
    for (int it = 0; it < 3; it++) {
        int idx = t + it * 256;
        int r = idx / 12, d4 = idx % 12;
        cp16(qsm + (unsigned)((r * ATQ + d4 * 4) * 4),
             q + ((size_t)(b * NN + q0 + r)) * CT + hh * HD + d4 * 4);
    }
    if (t < 64) { Ms[t] = -1e30f; Ls[t] = 0.f; }

    int wmS = w >> 2, wnS = w & 3;
    int mbS = wmS * 32, nbS = wnS * 16;
    int wmP = w >> 1, wnP = w & 1;
    int mbP = wmP * 16, nbP = wnP * 24;

    int lrow = lane & 15, lkq = lane >> 4;
    unsigned qaddr[2];
    #pragma unroll
    for (int mt = 0; mt < 2; mt++)
        qaddr[mt] = qsm + (unsigned)(((mbS + mt * 16 + lrow) * ATQ + lkq * 4) * 4);
    unsigned kaddr[2];
    #pragma unroll
    for (int nt = 0; nt < 2; nt++)
        kaddr[nt] = ksm + (unsigned)(((nbS + nt * 8 + (lane & 7)) * ATQ + ((lane >> 3) & 1) * 4) * 4);
    unsigned paddr = psm + (unsigned)(((mbP + lrow) * ATP + lkq * 4) * 4);

    float oacc[3][4];
    #pragma unroll
    for (int nt = 0; nt < 3; nt++)
        #pragma unroll
        for (int r = 0; r < 4; r++) oacc[nt][r] = 0.f;

    const float* bp0 = pb + ((size_t)(b * NH + hh) * NN + q0) * NN;

    for (int kt = 0; kt < 12; kt++) {
        int k0 = kt * 64;
        __syncthreads();
        // raw cp.async staging: K, V (pre-rounded tf32), bias tile (fp32)
        #pragma unroll
        for (int it = 0; it < 3; it++) {
            int idx = t + it * 256;
            int r = idx / 12, d4 = idx % 12;
            size_t gi = ((size_t)(b * NN + k0 + r)) * CT + hh * HD + d4 * 4;
            cp16(ksm + (unsigned)((r * ATQ + d4 * 4) * 4), k + gi);
            cp16(vsm + (unsigned)((r * AVQ + d4 * 4) * 4), v + gi);
        }
        #pragma unroll
        for (int it = 0; it < 4; it++) {
            int idx = t + it * 256;
            int r = idx >> 4, c4 = idx & 15;
            cp16(psm + (unsigned)((r * ATP + c4 * 4) * 4), bp0 + (size_t)r * NN + k0 + c4 * 4);
        }
        CP_COMMIT();
        CP_WAIT0();
        __syncthreads();

        float sacc[2][2][4];
        #pragma unroll
        for (int mt = 0; mt < 2; mt++)
            #pragma unroll
            for (int nt = 0; nt < 2; nt++)
                #pragma unroll
                for (int r = 0; r < 4; r++) sacc[mt][nt][r] = 0.f;
        #pragma unroll
        for (int ks = 0; ks < 6; ks++) {
            int kb = ks * 8;
            unsigned af[2][4];
            #pragma unroll
            for (int mt = 0; mt < 2; mt++) ldsm_x4(af[mt], qaddr[mt] + kb * 4);
            #pragma unroll
            for (int nt = 0; nt < 2; nt++) {
                unsigned b0, b1;
                ldsm_x2(b0, b1, kaddr[nt] + kb * 4);
                #pragma unroll
                for (int mt = 0; mt < 2; mt++)
                    mma_tf32(sacc[mt][nt], af[mt], b0, b1);
            }
        }
        #pragma unroll
        for (int mt = 0; mt < 2; mt++) {
            #pragma unroll
            for (int nt = 0; nt < 2; nt++) {
                int r = mbS + mt * 16 + gid;
                int c = nbS + nt * 8 + 2 * tig;
                float* p0 = Ps + r * ATP + c;
                float* p1 = Ps + (r + 8) * ATP + c;
                p0[0] += sacc[mt][nt][0];
                p0[1] += sacc[mt][nt][1];
                p1[0] += sacc[mt][nt][2];
                p1[1] += sacc[mt][nt][3];
            }
        }
        __syncthreads();

        // online softmax: 4 lanes per query row, stride-4 interleave; store P as tf32 bits
        {
            int qq = t >> 2, pp = t & 3;
            float* prow = Ps + qq * ATP + pp;
            float tmax = -1e30f;
            #pragma unroll
            for (int jj = 0; jj < 16; jj++) tmax = fmaxf(tmax, prow[jj * 4]);
            tmax = fmaxf(tmax, __shfl_xor_sync(0xffffffffu, tmax, 1));
            tmax = fmaxf(tmax, __shfl_xor_sync(0xffffffffu, tmax, 2));
            float mold = Ms[qq];
            float mnew = fmaxf(mold, tmax);
            float tsum = 0.f;
            #pragma unroll
            for (int jj = 0; jj < 16; jj++) {
                float p = __expf(prow[jj * 4] - mnew);
                tsum += p;
                prow[jj * 4] = __uint_as_float(f2tf(p));
            }
            tsum += __shfl_xor_sync(0xffffffffu, tsum, 1);
            tsum += __shfl_xor_sync(0xffffffffu, tsum, 2);
            if (pp == 0) {
                float scl = __expf(mold - mnew);
                Ss[qq] = scl;
                Ls[qq] = Ls[qq] * scl + tsum;
                Ms[qq] = mnew;
            }
        }
        __syncthreads();

        // rescale + O += P @ V via mma (P frag via ldmatrix)
        {
            float s0 = Ss[mbP + gid], s1 = Ss[mbP + gid + 8];
            #pragma unroll
            for (int nt = 0; nt < 3; nt++) {
                oacc[nt][0] *= s0; oacc[nt][1] *= s0;
                oacc[nt][2] *= s1; oacc[nt][3] *= s1;
            }
            #pragma unroll
            for (int ks = 0; ks < 8; ks++) {
                int kb = ks * 8;
                unsigned af[4];
                ldsm_x4(af, paddr + kb * 4);
                #pragma unroll
                for (int nt = 0; nt < 3; nt++) {
                    unsigned b0 = Vs[(kb + tig) * AVQ + nbP + nt * 8 + gid];
                    unsigned b1 = Vs[(kb + tig + 4) * AVQ + nbP + nt * 8 + gid];
                    mma_tf32(oacc[nt], af, b0, b1);
                }
            }
        }
    }

    // epilogue: normalize, gate, write (tf32-rounded: feeds Wout GEMM raw copies)
    __syncthreads();
    float inv0 = 1.f / Ls[mbP + gid];
    float inv1 = 1.f / Ls[mbP + gid + 8];
    size_t row0 = (size_t)(b * NN + q0 + mbP + gid);
    size_t row1 = row0 + 8;
    #pragma unroll
    for (int nt = 0; nt < 3; nt++) {
        int c = hh * HD + nbP + nt * 8 + 2 * tig;
        size_t i00 = row0 * CT + c;
        size_t i10 = row1 * CT + c;
        float g00 = 1.f / (1.f + __expf(-gate[i00]));
        float g01 = 1.f / (1.f + __expf(-gate[i00 + 1]));
        float g10 = 1.f / (1.f + __expf(-gate[i10]));
        float g11 = 1.f / (1.f + __expf(-gate[i10 + 1]));
        o[i00]     = __uint_as_float(f2tf(g00 * oacc[nt][0] * inv0));
        o[i00 + 1] = __uint_as_float(f2tf(g01 * oacc[nt][1] * inv0));
        o[i10]     = __uint_as_float(f2tf(g10 * oacc[nt][2] * inv1));
        o[i10 + 1] = __uint_as_float(f2tf(g11 * oacc[nt][3] * inv1));
    }
}

// ---------------- launch ----------------
static float* symaddr(const void* sym) {
    void* p = nullptr;
    cudaGetSymbolAddress(&p, sym);
    return (float*)p;
}

extern "C" void kernel_launch(void* const* d_in, const int* in_sizes, int n_in,
                              void* d_out, int out_size) {
    const float* a    = (const float*)d_in[0];
    const float* s    = (const float*)d_in[1];
    const float* z    = (const float*)d_in[2];
    const float* bm   = (const float*)d_in[3];
    const float* Wg   = (const float*)d_in[4];
    const float* bg   = (const float*)d_in[5];
    const float* Wb   = (const float*)d_in[6];
    const float* Wq   = (const float*)d_in[7];
    const float* bq   = (const float*)d_in[8];
    const float* Wk   = (const float*)d_in[9];
    const float* Wv   = (const float*)d_in[10];
    const float* Wpb  = (const float*)d_in[11];
    const float* png  = (const float*)d_in[12];
    const float* pnb  = (const float*)d_in[13];
    const float* Wgt  = (const float*)d_in[14];
    const float* Wout = (const float*)d_in[15];
    const float* Wog  = (const float*)d_in[16];
    const float* bog  = (const float*)d_in[17];
    float* out = (float*)d_out;

    float* aln   = symaddr(g_aln);
    float* sln   = symaddr(g_sln);
    float* tmpb  = symaddr(g_tmpb);
    float* anorm = symaddr(g_anorm);
    float* qb    = symaddr(g_q);
    float* kb    = symaddr(g_k);
    float* vb    = symaddr(g_v);
    float* gateb = symaddr(g_gate);
    float* ogb   = symaddr(g_og);
    float* ob    = symaddr(g_o);
    float* pbb   = symaddr(g_pb);
    float* wq    = symaddr(g_wq);
    float* wk    = symaddr(g_wk);
    float* wv    = symaddr(g_wv);
    float* wgt   = symaddr(g_wgt);
    float* wout  = symaddr(g_wout);
    float* wb    = symaddr(g_wb);
    float* wg    = symaddr(g_wg);
    float* wog   = symaddr(g_wog);
    float* srnd  = symaddr(g_srnd);

    const float SC = 0.14433756729740643f;  // 1/sqrt(48)

    cudaFuncSetAttribute(gemm128_kernel, cudaFuncAttributeMaxDynamicSharedMemorySize, GEMM_SMEM);
    cudaFuncSetAttribute(pair_kernel, cudaFuncAttributeMaxDynamicSharedMemorySize, PAIR_SMEM);
    cudaFuncSetAttribute(attn_kernel, cudaFuncAttributeMaxDynamicSharedMemorySize, ATTN_SMEM);

    // pre-round GEMM operands to tf32 values (once)
    {
        RoundArgs ra = {};
        ra.j[0] = { Wq,   wq,   CT * CT / 4 };
        ra.j[1] = { Wk,   wk,   CT * CT / 4 };
        ra.j[2] = { Wv,   wv,   CT * CT / 4 };
        ra.j[3] = { Wgt,  wgt,  CT * CT / 4 };
        ra.j[4] = { Wout, wout, CT * CT / 4 };
        ra.j[5] = { Wb,   wb,   CS * CT / 4 };
        ra.j[6] = { Wg,   wg,   CS * CT / 4 };
        ra.j[7] = { Wog,  wog,  CS * CT / 4 };
        ra.j[8] = { s,    srnd, ROWS * CS / 4 };
        round_kernel<<<dim3(144, 9), 256>>>(ra);
    }

    // fused LayerNorms (sln rounded to tf32)
    ln2_kernel<<<dim3(ROWS, 2), 256>>>(a, s, aln, sln);

    // batch 1: adaLN gate (sigmoid), adaLN bias-proj, output-gate (sigmoid) — K=384
    {
        GemmBatchArgs p = {};
        p.j[0] = { sln,  wb,  tmpb,  nullptr, nullptr, nullptr, CS, 0, 0, 1.f };
        p.j[1] = { sln,  wg,  anorm, bg,      nullptr, nullptr, CS, 1, 0, 1.f };   // gsig
        p.j[2] = { srnd, wog, ogb,   bog,     nullptr, nullptr, CS, 1, 0, 1.f };
        gemm128_kernel<<<dim3(CT / 128, ROWS / 128, 3), 256, GEMM_SMEM>>>(p, ROWS, CT);
    }
    // anorm = round_tf32(gsig * aln + tmpb)
    combine_kernel<<<ROWS * CT / 8 / 256, 256>>>(anorm, aln, tmpb);

    // batch 2: Q/K/V/gate — shared A, K=768; q scaled+rounded, k/v rounded in epilogue
    {
        GemmBatchArgs p = {};
        p.j[0] = { anorm, wq,  qb,    bq,      nullptr, nullptr, CT, 0, 1, SC  };
        p.j[1] = { anorm, wk,  kb,    nullptr, nullptr, nullptr, CT, 0, 1, 1.f };
        p.j[2] = { anorm, wv,  vb,    nullptr, nullptr, nullptr, CT, 0, 1, 1.f };
        p.j[3] = { anorm, wgt, gateb, nullptr, nullptr, nullptr, CT, 0, 0, 1.f };
        gemm128_kernel<<<dim3(CT / 128, ROWS / 128, 4), 256, GEMM_SMEM>>>(p, ROWS, CT);
    }

    // pair bias (incl. bias_mask)
    pair_kernel<<<dim3(NN / PJT, ROWS), 512, PAIR_SMEM>>>(z, bm, Wpb, png, pnb, pbb);
    // attention + gating (output tf32-rounded for raw-copy Wout GEMM)
    attn_kernel<<<dim3(NN / 64, NH, BB), 256, ATTN_SMEM>>>(qb, kb, vb, gateb, pbb, ob);

    // output projection with output-gate multiply — pipelined 64x64, 288 CTAs
    gemm64_kernel<<<dim3(CT / 64, ROWS / 64), 256>>>(ob, wout, out, ogb, ROWS, CT, CT);
}